// round 10
// baseline (speedup 1.0000x reference)
#include <cuda_runtime.h>
#include <cuda_fp16.h>
#include <math.h>
#include <stdint.h>

// ---------------------------------------------------------------------------
// Problem constants
// ---------------------------------------------------------------------------
#define BATCH   2
#define SEQ     2048
#define DMODEL  1024
#define NHEADS  16
#define HEADDIM 64
#define DFF     4096
#define BS      (BATCH * SEQ)          // 4096 rows
#define LN_EPS  1e-5f
#define ATTN_SCALE 0.08838834764831845f   // 1/sqrt(128)
#define QKVN    (3 * DMODEL)           // fused QKV width

// ---------------------------------------------------------------------------
// Scratch buffers
// ---------------------------------------------------------------------------
__device__ float  g_bufA   [BS * DMODEL];            // Wo out (fp32)
__device__ float  g_bufB   [BS * DMODEL];            // FFN2 out (fp32)
__device__ float  g_bufX1  [BS * DMODEL];            // LN1 out fp32
__device__ __half g_xh     [BS * DMODEL];            // x in fp16
__device__ __half g_QKVh   [BS * QKVN];              // fused QKV output fp16
__device__ __half g_QPh    [BATCH * NHEADS * SEQ * 2 * HEADDIM];
__device__ __half g_KPh    [BATCH * NHEADS * SEQ * 2 * HEADDIM];
__device__ __half g_AttnH  [BS * DMODEL];            // attention out fp16
__device__ __half g_X1h    [BS * DMODEL];            // LN1 out fp16
__device__ __half g_FFh    [BS * DFF];               // FFN hidden fp16

// Pre-transposed fp16 weights: [N][K]
__device__ __half g_WqkvT[QKVN * DMODEL];            // rows: Wq | Wk | Wv
__device__ float  g_bqkv [QKVN];
__device__ __half g_WoT[DMODEL * DMODEL];
__device__ __half g_W1T[DMODEL * DFF];
__device__ __half g_W2T[DFF * DMODEL];

// ---------------------------------------------------------------------------
// Helpers
// ---------------------------------------------------------------------------
__device__ __forceinline__ uint32_t smem_u32(const void* p) {
    uint32_t a;
    asm("{ .reg .u64 t; cvta.to.shared.u64 t, %1; cvt.u32.u64 %0, t; }"
        : "=r"(a) : "l"(p));
    return a;
}

__device__ __forceinline__ void cp_async16(uint32_t saddr, const void* gptr) {
    asm volatile("cp.async.cg.shared.global [%0], [%1], 16;"
                 :: "r"(saddr), "l"(gptr) : "memory");
}

// fp16 mma m16n8k16, fp32 accumulate
__device__ __forceinline__ void mma_f16(float (&d)[4],
                                        const uint32_t (&a)[4],
                                        uint32_t b0, uint32_t b1)
{
    asm volatile(
        "mma.sync.aligned.m16n8k16.row.col.f32.f16.f16.f32 "
        "{%0,%1,%2,%3}, {%4,%5,%6,%7}, {%8,%9}, {%0,%1,%2,%3};"
        : "+f"(d[0]), "+f"(d[1]), "+f"(d[2]), "+f"(d[3])
        : "r"(a[0]), "r"(a[1]), "r"(a[2]), "r"(a[3]), "r"(b0), "r"(b1));
}

__device__ __forceinline__ void ldsm_x4(uint32_t (&r)[4], uint32_t saddr) {
    asm volatile("ldmatrix.sync.aligned.m8n8.x4.shared.b16 {%0,%1,%2,%3}, [%4];"
                 : "=r"(r[0]), "=r"(r[1]), "=r"(r[2]), "=r"(r[3]) : "r"(saddr));
}

__device__ __forceinline__ void ldsm_x4_t(uint32_t (&r)[4], uint32_t saddr) {
    asm volatile("ldmatrix.sync.aligned.m8n8.x4.trans.shared.b16 {%0,%1,%2,%3}, [%4];"
                 : "=r"(r[0]), "=r"(r[1]), "=r"(r[2]), "=r"(r[3]) : "r"(saddr));
}

// Fast exp via MUFU.EX2 (args are <= 0 here; ex2.approx(-inf) = 0)
__device__ __forceinline__ float fexpf(float x) {
    float y = x * 1.4426950408889634f;
    float r;
    asm("ex2.approx.f32 %0, %1;" : "=f"(r) : "f"(y));
    return r;
}

// ---------------------------------------------------------------------------
// fp32 -> fp16 convert (8 elements per thread)
// ---------------------------------------------------------------------------
__global__ __launch_bounds__(256)
void f2h_kernel(const float* __restrict__ in, __half* __restrict__ out, int n)
{
    int i = (blockIdx.x * blockDim.x + threadIdx.x) * 8;
    if (i >= n) return;
    float4 a = *(const float4*)(in + i);
    float4 b = *(const float4*)(in + i + 4);
    __half2 h[4];
    h[0] = __floats2half2_rn(a.x, a.y);
    h[1] = __floats2half2_rn(a.z, a.w);
    h[2] = __floats2half2_rn(b.x, b.y);
    h[3] = __floats2half2_rn(b.z, b.w);
    *(uint4*)(out + i) = *(uint4*)h;
}

// ---------------------------------------------------------------------------
// Weight transpose + fp16: in[K][N] fp32 -> out[N][K] fp16
// ---------------------------------------------------------------------------
__global__ __launch_bounds__(256)
void transpose_h_kernel(const float* __restrict__ in, __half* __restrict__ out,
                        int K, int N)
{
    __shared__ float t[32][33];
    const int n0 = blockIdx.x * 32, k0 = blockIdx.y * 32;
    const int tx = threadIdx.x, ty = threadIdx.y;
#pragma unroll
    for (int i = 0; i < 32; i += 8)
        t[ty + i][tx] = in[(size_t)(k0 + ty + i) * N + n0 + tx];
    __syncthreads();
#pragma unroll
    for (int i = 0; i < 32; i += 8)
        out[(size_t)(n0 + ty + i) * K + k0 + tx] = __float2half_rn(t[tx][ty + i]);
}

// Batched QKV transpose: z selects Wq/Wk/Wv; writes into concat buffer
__global__ __launch_bounds__(256)
void transpose_h_qkv_kernel(const float* __restrict__ Wq,
                            const float* __restrict__ Wk,
                            const float* __restrict__ Wv,
                            __half* __restrict__ outT)
{
    __shared__ float t[32][33];
    const float* in = (blockIdx.z == 0) ? Wq : (blockIdx.z == 1) ? Wk : Wv;
    __half* out = outT + (size_t)blockIdx.z * DMODEL * DMODEL;
    const int n0 = blockIdx.x * 32, k0 = blockIdx.y * 32;
    const int tx = threadIdx.x, ty = threadIdx.y;
#pragma unroll
    for (int i = 0; i < 32; i += 8)
        t[ty + i][tx] = in[(size_t)(k0 + ty + i) * DMODEL + n0 + tx];
    __syncthreads();
#pragma unroll
    for (int i = 0; i < 32; i += 8)
        out[(size_t)(n0 + ty + i) * DMODEL + k0 + tx] = __float2half_rn(t[tx][ty + i]);
}

__global__ __launch_bounds__(256)
void concat_bias_kernel(const float* __restrict__ bq, const float* __restrict__ bk,
                        const float* __restrict__ bv, float* __restrict__ out)
{
    int i = blockIdx.x * 256 + threadIdx.x;
    if (i >= QKVN) return;
    float v = (i < DMODEL) ? bq[i] : (i < 2 * DMODEL) ? bk[i - DMODEL] : bv[i - 2 * DMODEL];
    out[i] = v;
}

// ---------------------------------------------------------------------------
// fp16 mma GEMM: 256x128x32 CTA tiles, 8 warps (4x2, 64x64 per warp),
// 3-stage cp.async pipeline, one __syncthreads per K-iteration.
// Halves smem traffic per FLOP vs 128x128 tiles (smem-BW-bound regime).
// ---------------------------------------------------------------------------
#define HG_STRIDE 40
#define HG_M 256
#define HG_N 128
#define HG_STAGES 3
#define HG_STAGE_HALVES ((HG_M + HG_N) * HG_STRIDE)       // 15360
#define HG_SMEM_BYTES (HG_STAGES * HG_STAGE_HALVES * 2)   // 92160 B

template<int RELU, int HALFOUT>
__global__ __launch_bounds__(256, 1)
void hgemm_kernel(const __half* __restrict__ A, const __half* __restrict__ Bt,
                  const float* __restrict__ bias, void* __restrict__ Cv,
                  int M, int N, int K)
{
    extern __shared__ __half hsm[];

    const int tid  = threadIdx.x;
    const int lane = tid & 31, wid = tid >> 5;
    const int wm = wid >> 1, wn = wid & 1;      // 4 x 2 warp grid, 64x64 tiles
    const int grp = lane >> 2, tig = lane & 3;
    const int m0 = blockIdx.y * HG_M, n0 = blockIdx.x * HG_N;

    const uint32_t smbase = smem_u32(hsm);

    const int l8  = lane & 7;
    const int q01 = (lane >> 3) & 1;
    const int q23 = lane >> 4;

    float acc[4][8][4];
#pragma unroll
    for (int mi = 0; mi < 4; ++mi)
#pragma unroll
        for (int nj = 0; nj < 8; ++nj)
#pragma unroll
            for (int r = 0; r < 4; ++r) acc[mi][nj][r] = 0.f;

    auto load_tiles = [&](int stage, int k0) {
        uint32_t ab = smbase + stage * HG_STAGE_HALVES * 2;
        uint32_t bb = ab + HG_M * HG_STRIDE * 2;
        // A: 256 rows x 32 cols = 1024 16B chunks (4/thread)
#pragma unroll
        for (int i = 0; i < 4; ++i) {
            int idx = tid + i * 256;
            int r = idx >> 2, c = idx & 3;
            cp_async16(ab + (uint32_t)(r * HG_STRIDE + c * 8) * 2,
                       A + (size_t)(m0 + r) * K + k0 + c * 8);
        }
        // B: 128 rows x 32 cols = 512 chunks (2/thread)
#pragma unroll
        for (int i = 0; i < 2; ++i) {
            int idx = tid + i * 256;
            int r = idx >> 2, c = idx & 3;
            cp_async16(bb + (uint32_t)(r * HG_STRIDE + c * 8) * 2,
                       Bt + (size_t)(n0 + r) * K + k0 + c * 8);
        }
    };

    const int nIt = K / 32;
    load_tiles(0, 0);
    asm volatile("cp.async.commit_group;" ::: "memory");
    load_tiles(1, 32);
    asm volatile("cp.async.commit_group;" ::: "memory");

    int st = 0, lst = 2;
    for (int it = 0; it < nIt; ++it) {
        asm volatile("cp.async.wait_group 1;" ::: "memory");
        __syncthreads();
        if (it + 2 < nIt) {
            load_tiles(lst, (it + 2) * 32);
            asm volatile("cp.async.commit_group;" ::: "memory");
            lst = (lst == 2) ? 0 : lst + 1;
        }

        const uint32_t abase = smbase + st * HG_STAGE_HALVES * 2;
        const uint32_t bbase = abase + HG_M * HG_STRIDE * 2;
        st = (st == 2) ? 0 : st + 1;

#pragma unroll
        for (int kk = 0; kk < 2; ++kk) {
            const int k = kk * 16;
            uint32_t af[4][4];
#pragma unroll
            for (int mi = 0; mi < 4; ++mi) {
                int row = wm * 64 + mi * 16 + q01 * 8 + l8;
                int col = k + q23 * 8;
                ldsm_x4(af[mi], abase + (uint32_t)(row * HG_STRIDE + col) * 2);
            }
#pragma unroll
            for (int g = 0; g < 4; ++g) {
                uint32_t bf[4];
                int row = wn * 64 + g * 16 + q23 * 8 + l8;
                int col = k + q01 * 8;
                ldsm_x4(bf, bbase + (uint32_t)(row * HG_STRIDE + col) * 2);
#pragma unroll
                for (int h2 = 0; h2 < 2; ++h2)
#pragma unroll
                    for (int mi = 0; mi < 4; ++mi)
                        mma_f16(acc[mi][g * 2 + h2], af[mi], bf[h2 * 2], bf[h2 * 2 + 1]);
            }
        }
    }

#pragma unroll
    for (int mi = 0; mi < 4; ++mi) {
        int r = m0 + wm * 64 + mi * 16 + grp;
#pragma unroll
        for (int nj = 0; nj < 8; ++nj) {
            int c = n0 + wn * 64 + nj * 8 + tig * 2;
            float bb0 = bias[c], bb1 = bias[c + 1];
            float v0 = acc[mi][nj][0] + bb0;
            float v1 = acc[mi][nj][1] + bb1;
            float v2 = acc[mi][nj][2] + bb0;
            float v3 = acc[mi][nj][3] + bb1;
            if (RELU) {
                v0 = fmaxf(v0, 0.f); v1 = fmaxf(v1, 0.f);
                v2 = fmaxf(v2, 0.f); v3 = fmaxf(v3, 0.f);
            }
            if (HALFOUT) {
                __half* C = (__half*)Cv;
                *(__half2*)&C[(size_t)r * N + c]       = __floats2half2_rn(v0, v1);
                *(__half2*)&C[(size_t)(r + 8) * N + c] = __floats2half2_rn(v2, v3);
            } else {
                float* C = (float*)Cv;
                float2 lo; lo.x = v0; lo.y = v1;
                float2 hi; hi.x = v2; hi.y = v3;
                *(float2*)&C[(size_t)r * N + c]       = lo;
                *(float2*)&C[(size_t)(r + 8) * N + c] = hi;
            }
        }
    }
}

// ---------------------------------------------------------------------------
// PoPE transform: reads fused fp16 QKV buffer, writes fp16 qp/kp.
// ---------------------------------------------------------------------------
__device__ __forceinline__ float softplus_f(float x) {
    return fmaxf(x, 0.f) + log1pf(expf(-fabsf(x)));
}

__global__ void pope_kernel(const __half* __restrict__ qkv,
                            const int* __restrict__ positions,
                            const float* __restrict__ freqs,
                            const float* __restrict__ phase_bias,
                            __half* __restrict__ qp, __half* __restrict__ kp)
{
    int idx = blockIdx.x * blockDim.x + threadIdx.x;   // B*H*S*32
    if (idx >= BATCH * NHEADS * SEQ * 32) return;
    int d = (idx & 31) * 2;
    int s = (idx >> 5) & (SEQ - 1);
    int h = (idx >> 16) & (NHEADS - 1);
    int b = idx >> 20;

    size_t rowb = (size_t)(b * SEQ + s) * QKVN + h * HEADDIM + d;
    float2 qv = __half22float2(*(const __half2*)&qkv[rowb]);
    float2 kv = __half22float2(*(const __half2*)&qkv[rowb + DMODEL]);

    float pos = (float)positions[s];
    float ph0 = pos * freqs[d]     + phase_bias[h * HEADDIM + d];
    float ph1 = pos * freqs[d + 1] + phase_bias[h * HEADDIM + d + 1];
    float c0, s0, c1, s1;
    sincosf(ph0, &s0, &c0);
    sincosf(ph1, &s1, &c1);

    float mq0 = softplus_f(qv.x) * ATTN_SCALE, mq1 = softplus_f(qv.y) * ATTN_SCALE;
    float mk0 = softplus_f(kv.x),              mk1 = softplus_f(kv.y);

    size_t base = (((size_t)(b * NHEADS + h) * SEQ) + s) * 128 + d;
    *(__half2*)&qp[base]      = __floats2half2_rn(mq0 * c0, mq1 * c1);
    *(__half2*)&qp[base + 64] = __floats2half2_rn(mq0 * s0, mq1 * s1);
    *(__half2*)&kp[base]      = __floats2half2_rn(mk0 * c0, mk1 * c1);
    *(__half2*)&kp[base + 64] = __floats2half2_rn(mk0 * s0, mk1 * s1);
}

// ---------------------------------------------------------------------------
// Flash attention with softmax1, fp16 mma + ldmatrix. 2 CTAs/SM.
// Double-buffered cp.async K/V, one sync per tile; softmax via MUFU.EX2.
// ---------------------------------------------------------------------------
#define AT_QS 136
#define AT_PS 72
#define AT_KS 136
#define AT_VS 72
#define AT_Q_HALVES (128 * AT_QS)             // aliased by Ps (128 x 72)
#define AT_K_STAGE  (64 * AT_KS)
#define AT_V_STAGE  (64 * AT_VS)
#define AT_SMEM_HALVES (AT_Q_HALVES + 2 * AT_K_STAGE + 2 * AT_V_STAGE)
#define AT_SMEM_BYTES  (AT_SMEM_HALVES * 2)   // 88064 B

__global__ __launch_bounds__(256, 2)
void attn_h_kernel(const __half* __restrict__ qp, const __half* __restrict__ kp,
                   const __half* __restrict__ qkv, __half* __restrict__ out)
{
    extern __shared__ __half hsm[];
    __half* Qs = hsm;                           // 128 x 136 (staging)
    __half* Ps = hsm;                           // 128 x 72 (aliases Qs)

    const int b = blockIdx.z;
    const int h = blockIdx.y;
    const int qtile = gridDim.x - 1 - blockIdx.x;   // heavy tiles first
    const int q0 = qtile * 128;

    const int tid  = threadIdx.x;
    const int lane = tid & 31, wid = tid >> 5;
    const int grp = lane >> 2, tig = lane & 3;
    const int r0 = wid * 16 + grp;

    const int l8  = lane & 7;
    const int q01 = (lane >> 3) & 1;
    const int q23 = lane >> 4;

    const uint32_t smbase = smem_u32(hsm);
    const uint32_t pssm  = smbase;                               // Ps
    const uint32_t kssm0 = smbase + AT_Q_HALVES * 2;             // K stage 0
    const uint32_t vssm0 = kssm0 + 2 * AT_K_STAGE * 2;           // V stage 0

    const __half* qbase = qp + (((size_t)(b * NHEADS + h)) * SEQ) * 128;
    const __half* kbase = kp + (((size_t)(b * NHEADS + h)) * SEQ) * 128;
    const __half* vbase = qkv + 2 * DMODEL + h * HEADDIM;        // V cols in fused buffer

    auto load_kv = [&](int stage, int kt) {
        uint32_t kb = kssm0 + stage * AT_K_STAGE * 2;
#pragma unroll
        for (int i = 0; i < 4; ++i) {
            int idx = tid + i * 256;
            int r = idx >> 4, c = idx & 15;
            cp_async16(kb + (uint32_t)(r * AT_KS + c * 8) * 2,
                       kbase + (size_t)(kt + r) * 128 + c * 8);
        }
        uint32_t vb = vssm0 + stage * AT_V_STAGE * 2;
#pragma unroll
        for (int i = 0; i < 2; ++i) {
            int idx = tid + i * 256;
            int r = idx >> 3, c = idx & 7;
            cp_async16(vb + (uint32_t)(r * AT_VS + c * 8) * 2,
                       vbase + ((size_t)b * SEQ + kt + r) * QKVN + c * 8);
        }
    };

    // Prologue: start K/V tile 0 fetch, then stage Q.
    load_kv(0, 0);
    asm volatile("cp.async.commit_group;" ::: "memory");

    for (int i = tid; i < 2048; i += 256) {
        int r = i >> 4, c = i & 15;
        *(uint4*)&Qs[r * AT_QS + c * 8] =
            *(const uint4*)&qbase[(size_t)(q0 + r) * 128 + c * 8];
    }
    __syncthreads();

    // Preload Q fragments via ldmatrix: 8 k16 chunks
    uint32_t qf[8][4];
    {
        int row = wid * 16 + q01 * 8 + l8;
#pragma unroll
        for (int kk = 0; kk < 8; ++kk) {
            int col = kk * 16 + q23 * 8;
            ldsm_x4(qf[kk], smbase + (uint32_t)(row * AT_QS + col) * 2);
        }
    }
    __syncthreads();   // done reading Qs before Ps overwrites

    float m0 = -INFINITY, m1 = -INFINITY, l0 = 0.f, l1 = 0.f;
    float o[8][4];
#pragma unroll
    for (int nj = 0; nj < 8; ++nj)
#pragma unroll
        for (int r = 0; r < 4; ++r) o[nj][r] = 0.f;

    const int nT = q0 / 64 + 2;
    for (int t = 0; t < nT; ++t) {
        const int kt = t * 64;
        asm volatile("cp.async.wait_group 0;" ::: "memory");
        __syncthreads();
        if (t + 1 < nT) {
            load_kv((t + 1) & 1, (t + 1) * 64);
            asm volatile("cp.async.commit_group;" ::: "memory");
        }
        const uint32_t kst = kssm0 + (t & 1) * AT_K_STAGE * 2;
        const uint32_t vst = vssm0 + (t & 1) * AT_V_STAGE * 2;

        // scores = Q @ K^T
        float sacc[8][4];
#pragma unroll
        for (int nj = 0; nj < 8; ++nj)
#pragma unroll
            for (int r = 0; r < 4; ++r) sacc[nj][r] = 0.f;

#pragma unroll
        for (int kk = 0; kk < 8; ++kk) {
            int k = kk * 16;
#pragma unroll
            for (int g = 0; g < 4; ++g) {
                uint32_t bf[4];
                int row = g * 16 + q23 * 8 + l8;
                int col = k + q01 * 8;
                ldsm_x4(bf, kst + (uint32_t)(row * AT_KS + col) * 2);
                mma_f16(sacc[g * 2 + 0], qf[kk], bf[0], bf[1]);
                mma_f16(sacc[g * 2 + 1], qf[kk], bf[2], bf[3]);
            }
        }

        // causal mask (last two key tiles only)
        if (kt >= q0) {
            int row0 = q0 + r0, row1 = row0 + 8;
#pragma unroll
            for (int nj = 0; nj < 8; ++nj) {
                int c = kt + nj * 8 + 2 * tig;
                if (c     > row0) sacc[nj][0] = -INFINITY;
                if (c + 1 > row0) sacc[nj][1] = -INFINITY;
                if (c     > row1) sacc[nj][2] = -INFINITY;
                if (c + 1 > row1) sacc[nj][3] = -INFINITY;
            }
        }

        // online softmax1 (fast ex2)
        float mx0 = -INFINITY, mx1 = -INFINITY;
#pragma unroll
        for (int nj = 0; nj < 8; ++nj) {
            mx0 = fmaxf(mx0, fmaxf(sacc[nj][0], sacc[nj][1]));
            mx1 = fmaxf(mx1, fmaxf(sacc[nj][2], sacc[nj][3]));
        }
        mx0 = fmaxf(mx0, __shfl_xor_sync(0xffffffffu, mx0, 1));
        mx0 = fmaxf(mx0, __shfl_xor_sync(0xffffffffu, mx0, 2));
        mx1 = fmaxf(mx1, __shfl_xor_sync(0xffffffffu, mx1, 1));
        mx1 = fmaxf(mx1, __shfl_xor_sync(0xffffffffu, mx1, 2));

        float m0n = fmaxf(m0, mx0), m1n = fmaxf(m1, mx1);
        float c0 = fexpf(m0 - m0n),  c1 = fexpf(m1 - m1n);
        m0 = m0n; m1 = m1n;

        float ls0 = 0.f, ls1 = 0.f;
#pragma unroll
        for (int nj = 0; nj < 8; ++nj) {
            float p0 = fexpf(sacc[nj][0] - m0n);
            float p1 = fexpf(sacc[nj][1] - m0n);
            float p2 = fexpf(sacc[nj][2] - m1n);
            float p3 = fexpf(sacc[nj][3] - m1n);
            ls0 += p0 + p1; ls1 += p2 + p3;
            *(__half2*)&Ps[r0       * AT_PS + nj * 8 + 2 * tig] = __floats2half2_rn(p0, p1);
            *(__half2*)&Ps[(r0 + 8) * AT_PS + nj * 8 + 2 * tig] = __floats2half2_rn(p2, p3);
        }
        ls0 += __shfl_xor_sync(0xffffffffu, ls0, 1);
        ls0 += __shfl_xor_sync(0xffffffffu, ls0, 2);
        ls1 += __shfl_xor_sync(0xffffffffu, ls1, 1);
        ls1 += __shfl_xor_sync(0xffffffffu, ls1, 2);
        l0 = l0 * c0 + ls0;
        l1 = l1 * c1 + ls1;

#pragma unroll
        for (int nj = 0; nj < 8; ++nj) {
            o[nj][0] *= c0; o[nj][1] *= c0;
            o[nj][2] *= c1; o[nj][3] *= c1;
        }
        __syncwarp();

        // O += P @ V (V row-major [key][dim]; B fragments via ldmatrix.trans)
#pragma unroll
        for (int kk = 0; kk < 4; ++kk) {
            int k = kk * 16;
            uint32_t af[4];
            {
                int row = wid * 16 + q01 * 8 + l8;
                int col = k + q23 * 8;
                ldsm_x4(af, pssm + (uint32_t)(row * AT_PS + col) * 2);
            }
#pragma unroll
            for (int g = 0; g < 4; ++g) {
                uint32_t bf[4];
                int row = k + q01 * 8 + l8;          // key index
                int col = g * 16 + q23 * 8;          // dim index
                ldsm_x4_t(bf, vst + (uint32_t)(row * AT_VS + col) * 2);
                mma_f16(o[g * 2 + 0], af, bf[0], bf[1]);
                mma_f16(o[g * 2 + 1], af, bf[2], bf[3]);
            }
        }
    }

    // epilogue: softmax1 denominator; write fp16 (B,S,D)
    float inv0 = 1.f / (1.f + l0);
    float inv1 = 1.f / (1.f + l1);
    int row0 = q0 + r0;
#pragma unroll
    for (int nj = 0; nj < 8; ++nj) {
        int c = h * HEADDIM + nj * 8 + 2 * tig;
        *(__half2*)&out[((size_t)b * SEQ + row0)     * DMODEL + c] =
            __floats2half2_rn(o[nj][0] * inv0, o[nj][1] * inv0);
        *(__half2*)&out[((size_t)b * SEQ + row0 + 8) * DMODEL + c] =
            __floats2half2_rn(o[nj][2] * inv1, o[nj][3] * inv1);
    }
}

// ---------------------------------------------------------------------------
// Fused residual add + LayerNorm; optional fp16 copy of the output.
// ---------------------------------------------------------------------------
template<int WRITEH>
__global__ __launch_bounds__(256)
void add_ln_kernel(const float* __restrict__ x, const float* __restrict__ y,
                   const float* __restrict__ g, const float* __restrict__ beta,
                   float* __restrict__ out, __half* __restrict__ outh)
{
    __shared__ float red_s[8];
    __shared__ float red_ss[8];
    __shared__ float s_mu, s_rstd;

    const int row = blockIdx.x;
    const int tid = threadIdx.x;
    const size_t base = (size_t)row * DMODEL;

    float4 xv = ((const float4*)(x + base))[tid];
    float4 yv = ((const float4*)(y + base))[tid];
    float v0 = xv.x + yv.x, v1 = xv.y + yv.y, v2 = xv.z + yv.z, v3 = xv.w + yv.w;

    float sum = v0 + v1 + v2 + v3;
    float ssq = v0 * v0 + v1 * v1 + v2 * v2 + v3 * v3;
#pragma unroll
    for (int off = 16; off >= 1; off >>= 1) {
        sum += __shfl_down_sync(0xffffffffu, sum, off);
        ssq += __shfl_down_sync(0xffffffffu, ssq, off);
    }
    const int warp = tid >> 5;
    if ((tid & 31) == 0) { red_s[warp] = sum; red_ss[warp] = ssq; }
    __syncthreads();
    if (tid == 0) {
        float ts = 0.f, tss = 0.f;
#pragma unroll
        for (int w = 0; w < 8; ++w) { ts += red_s[w]; tss += red_ss[w]; }
        float mu  = ts / (float)DMODEL;
        float var = tss / (float)DMODEL - mu * mu;
        s_mu = mu;
        s_rstd = rsqrtf(var + LN_EPS);
    }
    __syncthreads();
    const float mu = s_mu, rstd = s_rstd;

    float4 gv = ((const float4*)g)[tid];
    float4 bv = ((const float4*)beta)[tid];
    float4 o;
    o.x = (v0 - mu) * rstd * gv.x + bv.x;
    o.y = (v1 - mu) * rstd * gv.y + bv.y;
    o.z = (v2 - mu) * rstd * gv.z + bv.z;
    o.w = (v3 - mu) * rstd * gv.w + bv.w;
    ((float4*)(out + base))[tid] = o;
    if (WRITEH) {
        __half2 h0 = __floats2half2_rn(o.x, o.y);
        __half2 h1 = __floats2half2_rn(o.z, o.w);
        ((__half2*)(outh + base))[2 * tid]     = h0;
        ((__half2*)(outh + base))[2 * tid + 1] = h1;
    }
}

// ---------------------------------------------------------------------------
// Launcher
// ---------------------------------------------------------------------------
extern "C" void kernel_launch(void* const* d_in, const int* in_sizes, int n_in,
                              void* d_out, int out_size)
{
    (void)in_sizes; (void)n_in; (void)out_size;
    const float* x          = (const float*)d_in[0];
    const int*   positions  = (const int*)  d_in[1];
    const float* Wq         = (const float*)d_in[2];
    const float* bq         = (const float*)d_in[3];
    const float* Wk         = (const float*)d_in[4];
    const float* bk         = (const float*)d_in[5];
    const float* Wv         = (const float*)d_in[6];
    const float* bv         = (const float*)d_in[7];
    const float* Wo         = (const float*)d_in[8];
    const float* bo         = (const float*)d_in[9];
    const float* phase_bias = (const float*)d_in[10];
    const float* freqs      = (const float*)d_in[11];
    const float* W1         = (const float*)d_in[12];
    const float* b1         = (const float*)d_in[13];
    const float* W2         = (const float*)d_in[14];
    const float* b2         = (const float*)d_in[15];
    const float* g1         = (const float*)d_in[16];
    const float* beta1      = (const float*)d_in[17];
    const float* g2         = (const float*)d_in[18];
    const float* beta2      = (const float*)d_in[19];
    float* outp             = (float*)d_out;

    float  *bufA, *bufB, *bufX1, *bqkv;
    __half *xh, *QKVh, *QPh, *KPh, *AttnH, *X1h, *FFh;
    __half *WqkvT, *WoT, *W1T, *W2T;
    cudaGetSymbolAddress((void**)&bufA,  g_bufA);
    cudaGetSymbolAddress((void**)&bufB,  g_bufB);
    cudaGetSymbolAddress((void**)&bufX1, g_bufX1);
    cudaGetSymbolAddress((void**)&bqkv,  g_bqkv);
    cudaGetSymbolAddress((void**)&xh,    g_xh);
    cudaGetSymbolAddress((void**)&QKVh,  g_QKVh);
    cudaGetSymbolAddress((void**)&QPh,   g_QPh);
    cudaGetSymbolAddress((void**)&KPh,   g_KPh);
    cudaGetSymbolAddress((void**)&AttnH, g_AttnH);
    cudaGetSymbolAddress((void**)&X1h,   g_X1h);
    cudaGetSymbolAddress((void**)&FFh,   g_FFh);
    cudaGetSymbolAddress((void**)&WqkvT, g_WqkvT);
    cudaGetSymbolAddress((void**)&WoT,   g_WoT);
    cudaGetSymbolAddress((void**)&W1T,   g_W1T);
    cudaGetSymbolAddress((void**)&W2T,   g_W2T);

    cudaFuncSetAttribute(attn_h_kernel, cudaFuncAttributeMaxDynamicSharedMemorySize,
                         AT_SMEM_BYTES);
    cudaFuncSetAttribute(hgemm_kernel<0,0>, cudaFuncAttributeMaxDynamicSharedMemorySize,
                         HG_SMEM_BYTES);
    cudaFuncSetAttribute(hgemm_kernel<0,1>, cudaFuncAttributeMaxDynamicSharedMemorySize,
                         HG_SMEM_BYTES);
    cudaFuncSetAttribute(hgemm_kernel<1,1>, cudaFuncAttributeMaxDynamicSharedMemorySize,
                         HG_SMEM_BYTES);

    // 0a: x -> fp16
    f2h_kernel<<<(BS * DMODEL / 8 + 255) / 256, 256>>>(x, xh, BS * DMODEL);

    // 0b: weight transposes + fp16 (QKV batched into concat buffer)
    {
        dim3 blk(32, 8);
        transpose_h_qkv_kernel<<<dim3(DMODEL/32, DMODEL/32, 3), blk>>>(Wq, Wk, Wv, WqkvT);
        transpose_h_kernel<<<dim3(DMODEL/32, DMODEL/32), blk>>>(Wo, WoT, DMODEL, DMODEL);
        transpose_h_kernel<<<dim3(DFF/32,    DMODEL/32), blk>>>(W1, W1T, DMODEL, DFF);
        transpose_h_kernel<<<dim3(DMODEL/32, DFF/32),    blk>>>(W2, W2T, DFF, DMODEL);
        concat_bias_kernel<<<(QKVN + 255) / 256, 256>>>(bq, bk, bv, bqkv);
    }

    // 1: fused QKV projection (N=3072), fp16 out
    {
        dim3 grid(QKVN / HG_N, BS / HG_M);
        hgemm_kernel<0,1><<<grid, 256, HG_SMEM_BYTES>>>(xh, WqkvT, bqkv, QKVh, BS, QKVN, DMODEL);
    }

    // 2: PoPE (fp16 in/out)
    {
        int total = BATCH * NHEADS * SEQ * 32;
        pope_kernel<<<(total + 255) / 256, 256>>>(QKVh, positions, freqs,
                                                  phase_bias, QPh, KPh);
    }

    // 3: attention -> fp16
    {
        dim3 grid(SEQ / 128, NHEADS, BATCH);
        attn_h_kernel<<<grid, 256, AT_SMEM_BYTES>>>(QPh, KPh, QKVh, AttnH);
    }

    // 4: output projection -> fp32
    {
        dim3 grid(DMODEL / HG_N, BS / HG_M);
        hgemm_kernel<0,0><<<grid, 256, HG_SMEM_BYTES>>>(AttnH, WoT, bo, bufA, BS, DMODEL, DMODEL);
    }

    // 5: residual + LN1 -> fp32 + fp16
    add_ln_kernel<1><<<BS, 256>>>(x, bufA, g1, beta1, bufX1, X1h);

    // 6: FFN up + ReLU -> fp16
    {
        dim3 grid(DFF / HG_N, BS / HG_M);
        hgemm_kernel<1,1><<<grid, 256, HG_SMEM_BYTES>>>(X1h, W1T, b1, FFh, BS, DFF, DMODEL);
    }

    // 7: FFN down -> fp32
    {
        dim3 grid(DMODEL / HG_N, BS / HG_M);
        hgemm_kernel<0,0><<<grid, 256, HG_SMEM_BYTES>>>(FFh, W2T, b2, bufB, BS, DMODEL, DFF);
    }

    // 8: residual + LN2 -> output
    add_ln_kernel<0><<<BS, 256>>>(bufX1, bufB, g2, beta2, outp, nullptr);
}

// round 11
// speedup vs baseline: 1.0749x; 1.0749x over previous
#include <cuda_runtime.h>
#include <cuda_fp16.h>
#include <math.h>
#include <stdint.h>

// ---------------------------------------------------------------------------
// Problem constants
// ---------------------------------------------------------------------------
#define BATCH   2
#define SEQ     2048
#define DMODEL  1024
#define NHEADS  16
#define HEADDIM 64
#define DFF     4096
#define BS      (BATCH * SEQ)          // 4096 rows
#define LN_EPS  1e-5f
#define ATTN_SCALE 0.08838834764831845f   // 1/sqrt(128)
#define QKVN    (3 * DMODEL)           // fused QKV width

// ---------------------------------------------------------------------------
// Scratch buffers
// ---------------------------------------------------------------------------
__device__ float  g_bufA   [BS * DMODEL];            // Wo out (fp32)
__device__ float  g_bufB   [BS * DMODEL];            // FFN2 out (fp32)
__device__ float  g_bufX1  [BS * DMODEL];            // LN1 out fp32
__device__ __half g_xh     [BS * DMODEL];            // x in fp16
__device__ __half g_QKVh   [BS * QKVN];              // fused QKV output fp16
__device__ __half g_QPh    [BATCH * NHEADS * SEQ * 2 * HEADDIM];
__device__ __half g_KPh    [BATCH * NHEADS * SEQ * 2 * HEADDIM];
__device__ __half g_AttnH  [BS * DMODEL];            // attention out fp16
__device__ __half g_X1h    [BS * DMODEL];            // LN1 out fp16
__device__ __half g_FFh    [BS * DFF];               // FFN hidden fp16

// Pre-transposed fp16 weights: [N][K]
__device__ __half g_WqkvT[QKVN * DMODEL];            // rows: Wq | Wk | Wv
__device__ float  g_bqkv [QKVN];
__device__ __half g_WoT[DMODEL * DMODEL];
__device__ __half g_W1T[DMODEL * DFF];
__device__ __half g_W2T[DFF * DMODEL];

// ---------------------------------------------------------------------------
// Helpers
// ---------------------------------------------------------------------------
__device__ __forceinline__ uint32_t smem_u32(const void* p) {
    uint32_t a;
    asm("{ .reg .u64 t; cvta.to.shared.u64 t, %1; cvt.u32.u64 %0, t; }"
        : "=r"(a) : "l"(p));
    return a;
}

__device__ __forceinline__ void cp_async16(uint32_t saddr, const void* gptr) {
    asm volatile("cp.async.cg.shared.global [%0], [%1], 16;"
                 :: "r"(saddr), "l"(gptr) : "memory");
}

// fp16 mma m16n8k16, fp32 accumulate
__device__ __forceinline__ void mma_f16(float (&d)[4],
                                        const uint32_t (&a)[4],
                                        uint32_t b0, uint32_t b1)
{
    asm volatile(
        "mma.sync.aligned.m16n8k16.row.col.f32.f16.f16.f32 "
        "{%0,%1,%2,%3}, {%4,%5,%6,%7}, {%8,%9}, {%0,%1,%2,%3};"
        : "+f"(d[0]), "+f"(d[1]), "+f"(d[2]), "+f"(d[3])
        : "r"(a[0]), "r"(a[1]), "r"(a[2]), "r"(a[3]), "r"(b0), "r"(b1));
}

__device__ __forceinline__ void ldsm_x4(uint32_t (&r)[4], uint32_t saddr) {
    asm volatile("ldmatrix.sync.aligned.m8n8.x4.shared.b16 {%0,%1,%2,%3}, [%4];"
                 : "=r"(r[0]), "=r"(r[1]), "=r"(r[2]), "=r"(r[3]) : "r"(saddr));
}

__device__ __forceinline__ void ldsm_x4_t(uint32_t (&r)[4], uint32_t saddr) {
    asm volatile("ldmatrix.sync.aligned.m8n8.x4.trans.shared.b16 {%0,%1,%2,%3}, [%4];"
                 : "=r"(r[0]), "=r"(r[1]), "=r"(r[2]), "=r"(r[3]) : "r"(saddr));
}

// Fast exp via MUFU.EX2 (args are <= 0 here; ex2.approx(-inf) = 0)
__device__ __forceinline__ float fexpf(float x) {
    float y = x * 1.4426950408889634f;
    float r;
    asm("ex2.approx.f32 %0, %1;" : "=f"(r) : "f"(y));
    return r;
}

// ---------------------------------------------------------------------------
// fp32 -> fp16 convert (8 elements per thread)
// ---------------------------------------------------------------------------
__global__ __launch_bounds__(256)
void f2h_kernel(const float* __restrict__ in, __half* __restrict__ out, int n)
{
    int i = (blockIdx.x * blockDim.x + threadIdx.x) * 8;
    if (i >= n) return;
    float4 a = *(const float4*)(in + i);
    float4 b = *(const float4*)(in + i + 4);
    __half2 h[4];
    h[0] = __floats2half2_rn(a.x, a.y);
    h[1] = __floats2half2_rn(a.z, a.w);
    h[2] = __floats2half2_rn(b.x, b.y);
    h[3] = __floats2half2_rn(b.z, b.w);
    *(uint4*)(out + i) = *(uint4*)h;
}

// ---------------------------------------------------------------------------
// Weight transpose + fp16: in[K][N] fp32 -> out[N][K] fp16
// ---------------------------------------------------------------------------
__global__ __launch_bounds__(256)
void transpose_h_kernel(const float* __restrict__ in, __half* __restrict__ out,
                        int K, int N)
{
    __shared__ float t[32][33];
    const int n0 = blockIdx.x * 32, k0 = blockIdx.y * 32;
    const int tx = threadIdx.x, ty = threadIdx.y;
#pragma unroll
    for (int i = 0; i < 32; i += 8)
        t[ty + i][tx] = in[(size_t)(k0 + ty + i) * N + n0 + tx];
    __syncthreads();
#pragma unroll
    for (int i = 0; i < 32; i += 8)
        out[(size_t)(n0 + ty + i) * K + k0 + tx] = __float2half_rn(t[tx][ty + i]);
}

// Batched QKV transpose: z selects Wq/Wk/Wv; writes into concat buffer
__global__ __launch_bounds__(256)
void transpose_h_qkv_kernel(const float* __restrict__ Wq,
                            const float* __restrict__ Wk,
                            const float* __restrict__ Wv,
                            __half* __restrict__ outT)
{
    __shared__ float t[32][33];
    const float* in = (blockIdx.z == 0) ? Wq : (blockIdx.z == 1) ? Wk : Wv;
    __half* out = outT + (size_t)blockIdx.z * DMODEL * DMODEL;
    const int n0 = blockIdx.x * 32, k0 = blockIdx.y * 32;
    const int tx = threadIdx.x, ty = threadIdx.y;
#pragma unroll
    for (int i = 0; i < 32; i += 8)
        t[ty + i][tx] = in[(size_t)(k0 + ty + i) * DMODEL + n0 + tx];
    __syncthreads();
#pragma unroll
    for (int i = 0; i < 32; i += 8)
        out[(size_t)(n0 + ty + i) * DMODEL + k0 + tx] = __float2half_rn(t[tx][ty + i]);
}

__global__ __launch_bounds__(256)
void concat_bias_kernel(const float* __restrict__ bq, const float* __restrict__ bk,
                        const float* __restrict__ bv, float* __restrict__ out)
{
    int i = blockIdx.x * 256 + threadIdx.x;
    if (i >= QKVN) return;
    float v = (i < DMODEL) ? bq[i] : (i < 2 * DMODEL) ? bk[i - DMODEL] : bv[i - 2 * DMODEL];
    out[i] = v;
}

// ---------------------------------------------------------------------------
// fp16 mma GEMM: 128x128x32 tiles, 8 warps, 4-stage cp.async pipeline with a
// single __syncthreads per K-iteration. ldmatrix fragment loads, stride 40.
// (round-9 configuration: 2 CTAs/SM — reverted from the 256x128 regression)
// ---------------------------------------------------------------------------
#define HG_STRIDE 40
#define HG_STAGES 4
#define HG_STAGE_HALVES (2 * 128 * HG_STRIDE)         // A+B per stage
#define HG_SMEM_BYTES (HG_STAGES * HG_STAGE_HALVES * 2)   // 81920 B

template<int RELU, int HALFOUT>
__global__ __launch_bounds__(256, 2)
void hgemm_kernel(const __half* __restrict__ A, const __half* __restrict__ Bt,
                  const float* __restrict__ bias, void* __restrict__ Cv,
                  int M, int N, int K)
{
    extern __shared__ __half hsm[];

    const int tid  = threadIdx.x;
    const int lane = tid & 31, wid = tid >> 5;
    const int wm = wid >> 1, wn = wid & 1;
    const int grp = lane >> 2, tig = lane & 3;
    const int m0 = blockIdx.y * 128, n0 = blockIdx.x * 128;

    const uint32_t smbase = smem_u32(hsm);

    const int l8  = lane & 7;
    const int q01 = (lane >> 3) & 1;
    const int q23 = lane >> 4;

    float acc[2][8][4];
#pragma unroll
    for (int mi = 0; mi < 2; ++mi)
#pragma unroll
        for (int nj = 0; nj < 8; ++nj)
#pragma unroll
            for (int r = 0; r < 4; ++r) acc[mi][nj][r] = 0.f;

    auto load_tiles = [&](int stage, int k0) {
        uint32_t ab = smbase + stage * HG_STAGE_HALVES * 2;
        uint32_t bb = ab + 128 * HG_STRIDE * 2;
#pragma unroll
        for (int i = 0; i < 2; ++i) {
            int idx = tid + i * 256;
            int r = idx >> 2, c = idx & 3;
            cp_async16(ab + (uint32_t)(r * HG_STRIDE + c * 8) * 2,
                       A + (size_t)(m0 + r) * K + k0 + c * 8);
            cp_async16(bb + (uint32_t)(r * HG_STRIDE + c * 8) * 2,
                       Bt + (size_t)(n0 + r) * K + k0 + c * 8);
        }
    };

    const int nIt = K / 32;
#pragma unroll
    for (int s = 0; s < HG_STAGES - 1; ++s) {
        load_tiles(s, s * 32);
        asm volatile("cp.async.commit_group;" ::: "memory");
    }

    for (int it = 0; it < nIt; ++it) {
        asm volatile("cp.async.wait_group 2;" ::: "memory");
        __syncthreads();
        if (it + HG_STAGES - 1 < nIt) {
            load_tiles((it + HG_STAGES - 1) & (HG_STAGES - 1),
                       (it + HG_STAGES - 1) * 32);
            asm volatile("cp.async.commit_group;" ::: "memory");
        }

        const uint32_t abase = smbase + (it & (HG_STAGES - 1)) * HG_STAGE_HALVES * 2;
        const uint32_t bbase = abase + 128 * HG_STRIDE * 2;

#pragma unroll
        for (int kk = 0; kk < 2; ++kk) {
            const int k = kk * 16;
            uint32_t af[2][4];
#pragma unroll
            for (int mi = 0; mi < 2; ++mi) {
                int row = wm * 32 + mi * 16 + q01 * 8 + l8;
                int col = k + q23 * 8;
                ldsm_x4(af[mi], abase + (uint32_t)(row * HG_STRIDE + col) * 2);
            }
#pragma unroll
            for (int g = 0; g < 4; ++g) {
                uint32_t bf[4];
                int row = wn * 64 + g * 16 + q23 * 8 + l8;
                int col = k + q01 * 8;
                ldsm_x4(bf, bbase + (uint32_t)(row * HG_STRIDE + col) * 2);
#pragma unroll
                for (int h2 = 0; h2 < 2; ++h2)
#pragma unroll
                    for (int mi = 0; mi < 2; ++mi)
                        mma_f16(acc[mi][g * 2 + h2], af[mi], bf[h2 * 2], bf[h2 * 2 + 1]);
            }
        }
    }

#pragma unroll
    for (int mi = 0; mi < 2; ++mi) {
        int r = m0 + wm * 32 + mi * 16 + grp;
#pragma unroll
        for (int nj = 0; nj < 8; ++nj) {
            int c = n0 + wn * 64 + nj * 8 + tig * 2;
            float bb0 = bias[c], bb1 = bias[c + 1];
            float v0 = acc[mi][nj][0] + bb0;
            float v1 = acc[mi][nj][1] + bb1;
            float v2 = acc[mi][nj][2] + bb0;
            float v3 = acc[mi][nj][3] + bb1;
            if (RELU) {
                v0 = fmaxf(v0, 0.f); v1 = fmaxf(v1, 0.f);
                v2 = fmaxf(v2, 0.f); v3 = fmaxf(v3, 0.f);
            }
            if (HALFOUT) {
                __half* C = (__half*)Cv;
                *(__half2*)&C[(size_t)r * N + c]       = __floats2half2_rn(v0, v1);
                *(__half2*)&C[(size_t)(r + 8) * N + c] = __floats2half2_rn(v2, v3);
            } else {
                float* C = (float*)Cv;
                float2 lo; lo.x = v0; lo.y = v1;
                float2 hi; hi.x = v2; hi.y = v3;
                *(float2*)&C[(size_t)r * N + c]       = lo;
                *(float2*)&C[(size_t)(r + 8) * N + c] = hi;
            }
        }
    }
}

// ---------------------------------------------------------------------------
// PoPE transform: reads fused fp16 QKV buffer, writes fp16 qp/kp.
// ---------------------------------------------------------------------------
__device__ __forceinline__ float softplus_f(float x) {
    return fmaxf(x, 0.f) + log1pf(expf(-fabsf(x)));
}

__global__ void pope_kernel(const __half* __restrict__ qkv,
                            const int* __restrict__ positions,
                            const float* __restrict__ freqs,
                            const float* __restrict__ phase_bias,
                            __half* __restrict__ qp, __half* __restrict__ kp)
{
    int idx = blockIdx.x * blockDim.x + threadIdx.x;   // B*H*S*32
    if (idx >= BATCH * NHEADS * SEQ * 32) return;
    int d = (idx & 31) * 2;
    int s = (idx >> 5) & (SEQ - 1);
    int h = (idx >> 16) & (NHEADS - 1);
    int b = idx >> 20;

    size_t rowb = (size_t)(b * SEQ + s) * QKVN + h * HEADDIM + d;
    float2 qv = __half22float2(*(const __half2*)&qkv[rowb]);
    float2 kv = __half22float2(*(const __half2*)&qkv[rowb + DMODEL]);

    float pos = (float)positions[s];
    float ph0 = pos * freqs[d]     + phase_bias[h * HEADDIM + d];
    float ph1 = pos * freqs[d + 1] + phase_bias[h * HEADDIM + d + 1];
    float c0, s0, c1, s1;
    sincosf(ph0, &s0, &c0);
    sincosf(ph1, &s1, &c1);

    float mq0 = softplus_f(qv.x) * ATTN_SCALE, mq1 = softplus_f(qv.y) * ATTN_SCALE;
    float mk0 = softplus_f(kv.x),              mk1 = softplus_f(kv.y);

    size_t base = (((size_t)(b * NHEADS + h) * SEQ) + s) * 128 + d;
    *(__half2*)&qp[base]      = __floats2half2_rn(mq0 * c0, mq1 * c1);
    *(__half2*)&qp[base + 64] = __floats2half2_rn(mq0 * s0, mq1 * s1);
    *(__half2*)&kp[base]      = __floats2half2_rn(mk0 * c0, mk1 * c1);
    *(__half2*)&kp[base + 64] = __floats2half2_rn(mk0 * s0, mk1 * s1);
}

// ---------------------------------------------------------------------------
// Flash attention with softmax1, fp16 mma + ldmatrix. 2 CTAs/SM.
// Double-buffered cp.async K/V, one sync per tile; softmax via MUFU.EX2.
// ---------------------------------------------------------------------------
#define AT_QS 136
#define AT_PS 72
#define AT_KS 136
#define AT_VS 72
#define AT_Q_HALVES (128 * AT_QS)             // aliased by Ps (128 x 72)
#define AT_K_STAGE  (64 * AT_KS)
#define AT_V_STAGE  (64 * AT_VS)
#define AT_SMEM_HALVES (AT_Q_HALVES + 2 * AT_K_STAGE + 2 * AT_V_STAGE)
#define AT_SMEM_BYTES  (AT_SMEM_HALVES * 2)   // 88064 B

__global__ __launch_bounds__(256, 2)
void attn_h_kernel(const __half* __restrict__ qp, const __half* __restrict__ kp,
                   const __half* __restrict__ qkv, __half* __restrict__ out)
{
    extern __shared__ __half hsm[];
    __half* Qs = hsm;                           // 128 x 136 (staging)
    __half* Ps = hsm;                           // 128 x 72 (aliases Qs)

    const int b = blockIdx.z;
    const int h = blockIdx.y;
    const int qtile = gridDim.x - 1 - blockIdx.x;   // heavy tiles first
    const int q0 = qtile * 128;

    const int tid  = threadIdx.x;
    const int lane = tid & 31, wid = tid >> 5;
    const int grp = lane >> 2, tig = lane & 3;
    const int r0 = wid * 16 + grp;

    const int l8  = lane & 7;
    const int q01 = (lane >> 3) & 1;
    const int q23 = lane >> 4;

    const uint32_t smbase = smem_u32(hsm);
    const uint32_t pssm  = smbase;                               // Ps
    const uint32_t kssm0 = smbase + AT_Q_HALVES * 2;             // K stage 0
    const uint32_t vssm0 = kssm0 + 2 * AT_K_STAGE * 2;           // V stage 0

    const __half* qbase = qp + (((size_t)(b * NHEADS + h)) * SEQ) * 128;
    const __half* kbase = kp + (((size_t)(b * NHEADS + h)) * SEQ) * 128;
    const __half* vbase = qkv + 2 * DMODEL + h * HEADDIM;        // V cols in fused buffer

    auto load_kv = [&](int stage, int kt) {
        uint32_t kb = kssm0 + stage * AT_K_STAGE * 2;
#pragma unroll
        for (int i = 0; i < 4; ++i) {
            int idx = tid + i * 256;
            int r = idx >> 4, c = idx & 15;
            cp_async16(kb + (uint32_t)(r * AT_KS + c * 8) * 2,
                       kbase + (size_t)(kt + r) * 128 + c * 8);
        }
        uint32_t vb = vssm0 + stage * AT_V_STAGE * 2;
#pragma unroll
        for (int i = 0; i < 2; ++i) {
            int idx = tid + i * 256;
            int r = idx >> 3, c = idx & 7;
            cp_async16(vb + (uint32_t)(r * AT_VS + c * 8) * 2,
                       vbase + ((size_t)b * SEQ + kt + r) * QKVN + c * 8);
        }
    };

    // Prologue: start K/V tile 0 fetch, then stage Q.
    load_kv(0, 0);
    asm volatile("cp.async.commit_group;" ::: "memory");

    for (int i = tid; i < 2048; i += 256) {
        int r = i >> 4, c = i & 15;
        *(uint4*)&Qs[r * AT_QS + c * 8] =
            *(const uint4*)&qbase[(size_t)(q0 + r) * 128 + c * 8];
    }
    __syncthreads();

    // Preload Q fragments via ldmatrix: 8 k16 chunks
    uint32_t qf[8][4];
    {
        int row = wid * 16 + q01 * 8 + l8;
#pragma unroll
        for (int kk = 0; kk < 8; ++kk) {
            int col = kk * 16 + q23 * 8;
            ldsm_x4(qf[kk], smbase + (uint32_t)(row * AT_QS + col) * 2);
        }
    }
    __syncthreads();   // done reading Qs before Ps overwrites

    float m0 = -INFINITY, m1 = -INFINITY, l0 = 0.f, l1 = 0.f;
    float o[8][4];
#pragma unroll
    for (int nj = 0; nj < 8; ++nj)
#pragma unroll
        for (int r = 0; r < 4; ++r) o[nj][r] = 0.f;

    const int nT = q0 / 64 + 2;
    for (int t = 0; t < nT; ++t) {
        const int kt = t * 64;
        asm volatile("cp.async.wait_group 0;" ::: "memory");
        __syncthreads();
        if (t + 1 < nT) {
            load_kv((t + 1) & 1, (t + 1) * 64);
            asm volatile("cp.async.commit_group;" ::: "memory");
        }
        const uint32_t kst = kssm0 + (t & 1) * AT_K_STAGE * 2;
        const uint32_t vst = vssm0 + (t & 1) * AT_V_STAGE * 2;

        // scores = Q @ K^T
        float sacc[8][4];
#pragma unroll
        for (int nj = 0; nj < 8; ++nj)
#pragma unroll
            for (int r = 0; r < 4; ++r) sacc[nj][r] = 0.f;

#pragma unroll
        for (int kk = 0; kk < 8; ++kk) {
            int k = kk * 16;
#pragma unroll
            for (int g = 0; g < 4; ++g) {
                uint32_t bf[4];
                int row = g * 16 + q23 * 8 + l8;
                int col = k + q01 * 8;
                ldsm_x4(bf, kst + (uint32_t)(row * AT_KS + col) * 2);
                mma_f16(sacc[g * 2 + 0], qf[kk], bf[0], bf[1]);
                mma_f16(sacc[g * 2 + 1], qf[kk], bf[2], bf[3]);
            }
        }

        // causal mask (last two key tiles only)
        if (kt >= q0) {
            int row0 = q0 + r0, row1 = row0 + 8;
#pragma unroll
            for (int nj = 0; nj < 8; ++nj) {
                int c = kt + nj * 8 + 2 * tig;
                if (c     > row0) sacc[nj][0] = -INFINITY;
                if (c + 1 > row0) sacc[nj][1] = -INFINITY;
                if (c     > row1) sacc[nj][2] = -INFINITY;
                if (c + 1 > row1) sacc[nj][3] = -INFINITY;
            }
        }

        // online softmax1 (fast ex2)
        float mx0 = -INFINITY, mx1 = -INFINITY;
#pragma unroll
        for (int nj = 0; nj < 8; ++nj) {
            mx0 = fmaxf(mx0, fmaxf(sacc[nj][0], sacc[nj][1]));
            mx1 = fmaxf(mx1, fmaxf(sacc[nj][2], sacc[nj][3]));
        }
        mx0 = fmaxf(mx0, __shfl_xor_sync(0xffffffffu, mx0, 1));
        mx0 = fmaxf(mx0, __shfl_xor_sync(0xffffffffu, mx0, 2));
        mx1 = fmaxf(mx1, __shfl_xor_sync(0xffffffffu, mx1, 1));
        mx1 = fmaxf(mx1, __shfl_xor_sync(0xffffffffu, mx1, 2));

        float m0n = fmaxf(m0, mx0), m1n = fmaxf(m1, mx1);
        float c0 = fexpf(m0 - m0n),  c1 = fexpf(m1 - m1n);
        m0 = m0n; m1 = m1n;

        float ls0 = 0.f, ls1 = 0.f;
#pragma unroll
        for (int nj = 0; nj < 8; ++nj) {
            float p0 = fexpf(sacc[nj][0] - m0n);
            float p1 = fexpf(sacc[nj][1] - m0n);
            float p2 = fexpf(sacc[nj][2] - m1n);
            float p3 = fexpf(sacc[nj][3] - m1n);
            ls0 += p0 + p1; ls1 += p2 + p3;
            *(__half2*)&Ps[r0       * AT_PS + nj * 8 + 2 * tig] = __floats2half2_rn(p0, p1);
            *(__half2*)&Ps[(r0 + 8) * AT_PS + nj * 8 + 2 * tig] = __floats2half2_rn(p2, p3);
        }
        ls0 += __shfl_xor_sync(0xffffffffu, ls0, 1);
        ls0 += __shfl_xor_sync(0xffffffffu, ls0, 2);
        ls1 += __shfl_xor_sync(0xffffffffu, ls1, 1);
        ls1 += __shfl_xor_sync(0xffffffffu, ls1, 2);
        l0 = l0 * c0 + ls0;
        l1 = l1 * c1 + ls1;

#pragma unroll
        for (int nj = 0; nj < 8; ++nj) {
            o[nj][0] *= c0; o[nj][1] *= c0;
            o[nj][2] *= c1; o[nj][3] *= c1;
        }
        __syncwarp();

        // O += P @ V (V row-major [key][dim]; B fragments via ldmatrix.trans)
#pragma unroll
        for (int kk = 0; kk < 4; ++kk) {
            int k = kk * 16;
            uint32_t af[4];
            {
                int row = wid * 16 + q01 * 8 + l8;
                int col = k + q23 * 8;
                ldsm_x4(af, pssm + (uint32_t)(row * AT_PS + col) * 2);
            }
#pragma unroll
            for (int g = 0; g < 4; ++g) {
                uint32_t bf[4];
                int row = k + q01 * 8 + l8;          // key index
                int col = g * 16 + q23 * 8;          // dim index
                ldsm_x4_t(bf, vst + (uint32_t)(row * AT_VS + col) * 2);
                mma_f16(o[g * 2 + 0], af, bf[0], bf[1]);
                mma_f16(o[g * 2 + 1], af, bf[2], bf[3]);
            }
        }
    }

    // epilogue: softmax1 denominator; write fp16 (B,S,D)
    float inv0 = 1.f / (1.f + l0);
    float inv1 = 1.f / (1.f + l1);
    int row0 = q0 + r0;
#pragma unroll
    for (int nj = 0; nj < 8; ++nj) {
        int c = h * HEADDIM + nj * 8 + 2 * tig;
        *(__half2*)&out[((size_t)b * SEQ + row0)     * DMODEL + c] =
            __floats2half2_rn(o[nj][0] * inv0, o[nj][1] * inv0);
        *(__half2*)&out[((size_t)b * SEQ + row0 + 8) * DMODEL + c] =
            __floats2half2_rn(o[nj][2] * inv1, o[nj][3] * inv1);
    }
}

// ---------------------------------------------------------------------------
// Fused residual add + LayerNorm; optional fp16 copy of the output.
// ---------------------------------------------------------------------------
template<int WRITEH>
__global__ __launch_bounds__(256)
void add_ln_kernel(const float* __restrict__ x, const float* __restrict__ y,
                   const float* __restrict__ g, const float* __restrict__ beta,
                   float* __restrict__ out, __half* __restrict__ outh)
{
    __shared__ float red_s[8];
    __shared__ float red_ss[8];
    __shared__ float s_mu, s_rstd;

    const int row = blockIdx.x;
    const int tid = threadIdx.x;
    const size_t base = (size_t)row * DMODEL;

    float4 xv = ((const float4*)(x + base))[tid];
    float4 yv = ((const float4*)(y + base))[tid];
    float v0 = xv.x + yv.x, v1 = xv.y + yv.y, v2 = xv.z + yv.z, v3 = xv.w + yv.w;

    float sum = v0 + v1 + v2 + v3;
    float ssq = v0 * v0 + v1 * v1 + v2 * v2 + v3 * v3;
#pragma unroll
    for (int off = 16; off >= 1; off >>= 1) {
        sum += __shfl_down_sync(0xffffffffu, sum, off);
        ssq += __shfl_down_sync(0xffffffffu, ssq, off);
    }
    const int warp = tid >> 5;
    if ((tid & 31) == 0) { red_s[warp] = sum; red_ss[warp] = ssq; }
    __syncthreads();
    if (tid == 0) {
        float ts = 0.f, tss = 0.f;
#pragma unroll
        for (int w = 0; w < 8; ++w) { ts += red_s[w]; tss += red_ss[w]; }
        float mu  = ts / (float)DMODEL;
        float var = tss / (float)DMODEL - mu * mu;
        s_mu = mu;
        s_rstd = rsqrtf(var + LN_EPS);
    }
    __syncthreads();
    const float mu = s_mu, rstd = s_rstd;

    float4 gv = ((const float4*)g)[tid];
    float4 bv = ((const float4*)beta)[tid];
    float4 o;
    o.x = (v0 - mu) * rstd * gv.x + bv.x;
    o.y = (v1 - mu) * rstd * gv.y + bv.y;
    o.z = (v2 - mu) * rstd * gv.z + bv.z;
    o.w = (v3 - mu) * rstd * gv.w + bv.w;
    ((float4*)(out + base))[tid] = o;
    if (WRITEH) {
        __half2 h0 = __floats2half2_rn(o.x, o.y);
        __half2 h1 = __floats2half2_rn(o.z, o.w);
        ((__half2*)(outh + base))[2 * tid]     = h0;
        ((__half2*)(outh + base))[2 * tid + 1] = h1;
    }
}

// ---------------------------------------------------------------------------
// Launcher
// ---------------------------------------------------------------------------
extern "C" void kernel_launch(void* const* d_in, const int* in_sizes, int n_in,
                              void* d_out, int out_size)
{
    (void)in_sizes; (void)n_in; (void)out_size;
    const float* x          = (const float*)d_in[0];
    const int*   positions  = (const int*)  d_in[1];
    const float* Wq         = (const float*)d_in[2];
    const float* bq         = (const float*)d_in[3];
    const float* Wk         = (const float*)d_in[4];
    const float* bk         = (const float*)d_in[5];
    const float* Wv         = (const float*)d_in[6];
    const float* bv         = (const float*)d_in[7];
    const float* Wo         = (const float*)d_in[8];
    const float* bo         = (const float*)d_in[9];
    const float* phase_bias = (const float*)d_in[10];
    const float* freqs      = (const float*)d_in[11];
    const float* W1         = (const float*)d_in[12];
    const float* b1         = (const float*)d_in[13];
    const float* W2         = (const float*)d_in[14];
    const float* b2         = (const float*)d_in[15];
    const float* g1         = (const float*)d_in[16];
    const float* beta1      = (const float*)d_in[17];
    const float* g2         = (const float*)d_in[18];
    const float* beta2      = (const float*)d_in[19];
    float* outp             = (float*)d_out;

    float  *bufA, *bufB, *bufX1, *bqkv;
    __half *xh, *QKVh, *QPh, *KPh, *AttnH, *X1h, *FFh;
    __half *WqkvT, *WoT, *W1T, *W2T;
    cudaGetSymbolAddress((void**)&bufA,  g_bufA);
    cudaGetSymbolAddress((void**)&bufB,  g_bufB);
    cudaGetSymbolAddress((void**)&bufX1, g_bufX1);
    cudaGetSymbolAddress((void**)&bqkv,  g_bqkv);
    cudaGetSymbolAddress((void**)&xh,    g_xh);
    cudaGetSymbolAddress((void**)&QKVh,  g_QKVh);
    cudaGetSymbolAddress((void**)&QPh,   g_QPh);
    cudaGetSymbolAddress((void**)&KPh,   g_KPh);
    cudaGetSymbolAddress((void**)&AttnH, g_AttnH);
    cudaGetSymbolAddress((void**)&X1h,   g_X1h);
    cudaGetSymbolAddress((void**)&FFh,   g_FFh);
    cudaGetSymbolAddress((void**)&WqkvT, g_WqkvT);
    cudaGetSymbolAddress((void**)&WoT,   g_WoT);
    cudaGetSymbolAddress((void**)&W1T,   g_W1T);
    cudaGetSymbolAddress((void**)&W2T,   g_W2T);

    cudaFuncSetAttribute(attn_h_kernel, cudaFuncAttributeMaxDynamicSharedMemorySize,
                         AT_SMEM_BYTES);
    cudaFuncSetAttribute(hgemm_kernel<0,0>, cudaFuncAttributeMaxDynamicSharedMemorySize,
                         HG_SMEM_BYTES);
    cudaFuncSetAttribute(hgemm_kernel<0,1>, cudaFuncAttributeMaxDynamicSharedMemorySize,
                         HG_SMEM_BYTES);
    cudaFuncSetAttribute(hgemm_kernel<1,1>, cudaFuncAttributeMaxDynamicSharedMemorySize,
                         HG_SMEM_BYTES);

    // 0a: x -> fp16
    f2h_kernel<<<(BS * DMODEL / 8 + 255) / 256, 256>>>(x, xh, BS * DMODEL);

    // 0b: weight transposes + fp16 (QKV batched into concat buffer)
    {
        dim3 blk(32, 8);
        transpose_h_qkv_kernel<<<dim3(DMODEL/32, DMODEL/32, 3), blk>>>(Wq, Wk, Wv, WqkvT);
        transpose_h_kernel<<<dim3(DMODEL/32, DMODEL/32), blk>>>(Wo, WoT, DMODEL, DMODEL);
        transpose_h_kernel<<<dim3(DFF/32,    DMODEL/32), blk>>>(W1, W1T, DMODEL, DFF);
        transpose_h_kernel<<<dim3(DMODEL/32, DFF/32),    blk>>>(W2, W2T, DFF, DMODEL);
        concat_bias_kernel<<<(QKVN + 255) / 256, 256>>>(bq, bk, bv, bqkv);
    }

    // 1: fused QKV projection (N=3072), fp16 out
    {
        dim3 grid(QKVN / 128, BS / 128);
        hgemm_kernel<0,1><<<grid, 256, HG_SMEM_BYTES>>>(xh, WqkvT, bqkv, QKVh, BS, QKVN, DMODEL);
    }

    // 2: PoPE (fp16 in/out)
    {
        int total = BATCH * NHEADS * SEQ * 32;
        pope_kernel<<<(total + 255) / 256, 256>>>(QKVh, positions, freqs,
                                                  phase_bias, QPh, KPh);
    }

    // 3: attention -> fp16
    {
        dim3 grid(SEQ / 128, NHEADS, BATCH);
        attn_h_kernel<<<grid, 256, AT_SMEM_BYTES>>>(QPh, KPh, QKVh, AttnH);
    }

    // 4: output projection -> fp32
    {
        dim3 grid(DMODEL / 128, BS / 128);
        hgemm_kernel<0,0><<<grid, 256, HG_SMEM_BYTES>>>(AttnH, WoT, bo, bufA, BS, DMODEL, DMODEL);
    }

    // 5: residual + LN1 -> fp32 + fp16
    add_ln_kernel<1><<<BS, 256>>>(x, bufA, g1, beta1, bufX1, X1h);

    // 6: FFN up + ReLU -> fp16
    {
        dim3 grid(DFF / 128, BS / 128);
        hgemm_kernel<1,1><<<grid, 256, HG_SMEM_BYTES>>>(X1h, W1T, b1, FFh, BS, DFF, DMODEL);
    }

    // 7: FFN down -> fp32
    {
        dim3 grid(DMODEL / 128, BS / 128);
        hgemm_kernel<0,0><<<grid, 256, HG_SMEM_BYTES>>>(FFh, W2T, b2, bufB, BS, DMODEL, DFF);
    }

    // 8: residual + LN2 -> output
    add_ln_kernel<0><<<BS, 256>>>(bufX1, bufB, g2, beta2, outp, nullptr);
}

// round 12
// speedup vs baseline: 1.1124x; 1.0348x over previous
#include <cuda_runtime.h>
#include <cuda_fp16.h>
#include <math.h>
#include <stdint.h>

// ---------------------------------------------------------------------------
// Problem constants
// ---------------------------------------------------------------------------
#define BATCH   2
#define SEQ     2048
#define DMODEL  1024
#define NHEADS  16
#define HEADDIM 64
#define DFF     4096
#define BS      (BATCH * SEQ)          // 4096 rows
#define LN_EPS  1e-5f
#define ATTN_SCALE 0.08838834764831845f   // 1/sqrt(128)
#define QKVN    (3 * DMODEL)           // fused QKV width

// ---------------------------------------------------------------------------
// Scratch buffers
// ---------------------------------------------------------------------------
__device__ float  g_bufA   [BS * DMODEL];            // Wo out (fp32)
__device__ float  g_bufB   [BS * DMODEL];            // FFN2 out (fp32)
__device__ float  g_bufX1  [BS * DMODEL];            // LN1 out fp32
__device__ __half g_xh     [BS * DMODEL];            // x in fp16
__device__ __half g_QKVh   [BS * QKVN];              // fused QKV output fp16
__device__ __half g_QPh    [BATCH * NHEADS * SEQ * 2 * HEADDIM];
__device__ __half g_KPh    [BATCH * NHEADS * SEQ * 2 * HEADDIM];
__device__ __half g_AttnH  [BS * DMODEL];            // attention out fp16
__device__ __half g_X1h    [BS * DMODEL];            // LN1 out fp16
__device__ __half g_FFh    [BS * DFF];               // FFN hidden fp16

// fp16 weights in NATIVE [K][N] layout (no transpose needed: ldmatrix.trans)
__device__ __half g_Wcat[DMODEL * QKVN];             // cols: Wq | Wk | Wv
__device__ float  g_bqkv[QKVN];
__device__ __half g_Woh[DMODEL * DMODEL];
__device__ __half g_W1h[DMODEL * DFF];
__device__ __half g_W2h[DFF * DMODEL];

// ---------------------------------------------------------------------------
// Helpers
// ---------------------------------------------------------------------------
__device__ __forceinline__ uint32_t smem_u32(const void* p) {
    uint32_t a;
    asm("{ .reg .u64 t; cvta.to.shared.u64 t, %1; cvt.u32.u64 %0, t; }"
        : "=r"(a) : "l"(p));
    return a;
}

__device__ __forceinline__ void cp_async16(uint32_t saddr, const void* gptr) {
    asm volatile("cp.async.cg.shared.global [%0], [%1], 16;"
                 :: "r"(saddr), "l"(gptr) : "memory");
}

// fp16 mma m16n8k16, fp32 accumulate
__device__ __forceinline__ void mma_f16(float (&d)[4],
                                        const uint32_t (&a)[4],
                                        uint32_t b0, uint32_t b1)
{
    asm volatile(
        "mma.sync.aligned.m16n8k16.row.col.f32.f16.f16.f32 "
        "{%0,%1,%2,%3}, {%4,%5,%6,%7}, {%8,%9}, {%0,%1,%2,%3};"
        : "+f"(d[0]), "+f"(d[1]), "+f"(d[2]), "+f"(d[3])
        : "r"(a[0]), "r"(a[1]), "r"(a[2]), "r"(a[3]), "r"(b0), "r"(b1));
}

__device__ __forceinline__ void ldsm_x4(uint32_t (&r)[4], uint32_t saddr) {
    asm volatile("ldmatrix.sync.aligned.m8n8.x4.shared.b16 {%0,%1,%2,%3}, [%4];"
                 : "=r"(r[0]), "=r"(r[1]), "=r"(r[2]), "=r"(r[3]) : "r"(saddr));
}

__device__ __forceinline__ void ldsm_x4_t(uint32_t (&r)[4], uint32_t saddr) {
    asm volatile("ldmatrix.sync.aligned.m8n8.x4.trans.shared.b16 {%0,%1,%2,%3}, [%4];"
                 : "=r"(r[0]), "=r"(r[1]), "=r"(r[2]), "=r"(r[3]) : "r"(saddr));
}

// Fast exp via MUFU.EX2 (args are <= 0 here; ex2.approx(-inf) = 0)
__device__ __forceinline__ float fexpf(float x) {
    float y = x * 1.4426950408889634f;
    float r;
    asm("ex2.approx.f32 %0, %1;" : "=f"(r) : "f"(y));
    return r;
}

// ---------------------------------------------------------------------------
// fp32 -> fp16 convert (8 elements per thread)
// ---------------------------------------------------------------------------
__global__ __launch_bounds__(256)
void f2h_kernel(const float* __restrict__ in, __half* __restrict__ out, int n)
{
    int i = (blockIdx.x * blockDim.x + threadIdx.x) * 8;
    if (i >= n) return;
    float4 a = *(const float4*)(in + i);
    float4 b = *(const float4*)(in + i + 4);
    __half2 h[4];
    h[0] = __floats2half2_rn(a.x, a.y);
    h[1] = __floats2half2_rn(a.z, a.w);
    h[2] = __floats2half2_rn(b.x, b.y);
    h[3] = __floats2half2_rn(b.z, b.w);
    *(uint4*)(out + i) = *(uint4*)h;
}

// fp32 [K][Nin] -> fp16 written into [K][Nout] at column offset (coalesced rows)
__global__ __launch_bounds__(256)
void f2h_cat_kernel(const float* __restrict__ in, __half* __restrict__ out,
                    int K, int Nin, int Nout, int coloff)
{
    int idx = blockIdx.x * 256 + threadIdx.x;      // over K*Nin/8
    int rowlen = Nin >> 3;
    if (idx >= K * rowlen) return;
    int r = idx / rowlen, c = idx - r * rowlen;
    const float* src = in + (size_t)r * Nin + c * 8;
    float4 a = *(const float4*)src;
    float4 b = *(const float4*)(src + 4);
    __half2 h[4];
    h[0] = __floats2half2_rn(a.x, a.y);
    h[1] = __floats2half2_rn(a.z, a.w);
    h[2] = __floats2half2_rn(b.x, b.y);
    h[3] = __floats2half2_rn(b.z, b.w);
    *(uint4*)(out + (size_t)r * Nout + coloff + c * 8) = *(uint4*)h;
}

__global__ __launch_bounds__(256)
void concat_bias_kernel(const float* __restrict__ bq, const float* __restrict__ bk,
                        const float* __restrict__ bv, float* __restrict__ out)
{
    int i = blockIdx.x * 256 + threadIdx.x;
    if (i >= QKVN) return;
    float v = (i < DMODEL) ? bq[i] : (i < 2 * DMODEL) ? bk[i - DMODEL] : bv[i - 2 * DMODEL];
    out[i] = v;
}

// ---------------------------------------------------------------------------
// fp16 mma GEMM: C(MxN) = A(MxK) @ W(KxN) + bias. W in NATIVE [K][N] layout;
// B fragments via ldmatrix.trans (bank-clean: stride 136 halves -> 4r mod 32).
// 128x128x32 tiles, 8 warps, 4-stage cp.async pipeline, one sync per K-iter,
// 2 CTAs/SM.
// ---------------------------------------------------------------------------
#define HG_STRIDE 40          // A tile stride (halves)
#define HG_BS     136         // B tile stride (halves), 32 rows x 128 cols
#define HG_STAGES 4
#define HG_A_HALVES (128 * HG_STRIDE)
#define HG_B_HALVES (32 * HG_BS)
#define HG_STAGE_HALVES (HG_A_HALVES + HG_B_HALVES)       // 9472
#define HG_SMEM_BYTES (HG_STAGES * HG_STAGE_HALVES * 2)   // 75776 B

template<int RELU, int HALFOUT>
__global__ __launch_bounds__(256, 2)
void hgemm_kernel(const __half* __restrict__ A, const __half* __restrict__ W,
                  const float* __restrict__ bias, void* __restrict__ Cv,
                  int M, int N, int K)
{
    extern __shared__ __half hsm[];

    const int tid  = threadIdx.x;
    const int lane = tid & 31, wid = tid >> 5;
    const int wm = wid >> 1, wn = wid & 1;
    const int grp = lane >> 2, tig = lane & 3;
    const int m0 = blockIdx.y * 128, n0 = blockIdx.x * 128;

    const uint32_t smbase = smem_u32(hsm);

    const int l8  = lane & 7;
    const int q01 = (lane >> 3) & 1;
    const int q23 = lane >> 4;

    float acc[2][8][4];
#pragma unroll
    for (int mi = 0; mi < 2; ++mi)
#pragma unroll
        for (int nj = 0; nj < 8; ++nj)
#pragma unroll
            for (int r = 0; r < 4; ++r) acc[mi][nj][r] = 0.f;

    auto load_tiles = [&](int stage, int k0) {
        uint32_t ab = smbase + stage * HG_STAGE_HALVES * 2;
        uint32_t bb = ab + HG_A_HALVES * 2;
        // A: 128 rows x 32 k = 512 chunks (2/thread)
#pragma unroll
        for (int i = 0; i < 2; ++i) {
            int idx = tid + i * 256;
            int r = idx >> 2, c = idx & 3;
            cp_async16(ab + (uint32_t)(r * HG_STRIDE + c * 8) * 2,
                       A + (size_t)(m0 + r) * K + k0 + c * 8);
        }
        // B: 32 k-rows x 128 n = 512 chunks (2/thread), native [K][N]
#pragma unroll
        for (int i = 0; i < 2; ++i) {
            int idx = tid + i * 256;
            int r = idx >> 4, c = idx & 15;
            cp_async16(bb + (uint32_t)(r * HG_BS + c * 8) * 2,
                       W + (size_t)(k0 + r) * N + n0 + c * 8);
        }
    };

    const int nIt = K / 32;
#pragma unroll
    for (int s = 0; s < HG_STAGES - 1; ++s) {
        load_tiles(s, s * 32);
        asm volatile("cp.async.commit_group;" ::: "memory");
    }

    for (int it = 0; it < nIt; ++it) {
        asm volatile("cp.async.wait_group 2;" ::: "memory");
        __syncthreads();
        if (it + HG_STAGES - 1 < nIt) {
            load_tiles((it + HG_STAGES - 1) & (HG_STAGES - 1),
                       (it + HG_STAGES - 1) * 32);
            asm volatile("cp.async.commit_group;" ::: "memory");
        }

        const uint32_t abase = smbase + (it & (HG_STAGES - 1)) * HG_STAGE_HALVES * 2;
        const uint32_t bbase = abase + HG_A_HALVES * 2;

#pragma unroll
        for (int kk = 0; kk < 2; ++kk) {
            const int k = kk * 16;
            uint32_t af[2][4];
#pragma unroll
            for (int mi = 0; mi < 2; ++mi) {
                int row = wm * 32 + mi * 16 + q01 * 8 + l8;
                int col = k + q23 * 8;
                ldsm_x4(af[mi], abase + (uint32_t)(row * HG_STRIDE + col) * 2);
            }
#pragma unroll
            for (int g = 0; g < 4; ++g) {
                uint32_t bf[4];
                int row = k + q01 * 8 + l8;                 // k index
                int col = wn * 64 + g * 16 + q23 * 8;       // n index
                ldsm_x4_t(bf, bbase + (uint32_t)(row * HG_BS + col) * 2);
#pragma unroll
                for (int h2 = 0; h2 < 2; ++h2)
#pragma unroll
                    for (int mi = 0; mi < 2; ++mi)
                        mma_f16(acc[mi][g * 2 + h2], af[mi], bf[h2 * 2], bf[h2 * 2 + 1]);
            }
        }
    }

#pragma unroll
    for (int mi = 0; mi < 2; ++mi) {
        int r = m0 + wm * 32 + mi * 16 + grp;
#pragma unroll
        for (int nj = 0; nj < 8; ++nj) {
            int c = n0 + wn * 64 + nj * 8 + tig * 2;
            float bb0 = bias[c], bb1 = bias[c + 1];
            float v0 = acc[mi][nj][0] + bb0;
            float v1 = acc[mi][nj][1] + bb1;
            float v2 = acc[mi][nj][2] + bb0;
            float v3 = acc[mi][nj][3] + bb1;
            if (RELU) {
                v0 = fmaxf(v0, 0.f); v1 = fmaxf(v1, 0.f);
                v2 = fmaxf(v2, 0.f); v3 = fmaxf(v3, 0.f);
            }
            if (HALFOUT) {
                __half* C = (__half*)Cv;
                *(__half2*)&C[(size_t)r * N + c]       = __floats2half2_rn(v0, v1);
                *(__half2*)&C[(size_t)(r + 8) * N + c] = __floats2half2_rn(v2, v3);
            } else {
                float* C = (float*)Cv;
                float2 lo; lo.x = v0; lo.y = v1;
                float2 hi; hi.x = v2; hi.y = v3;
                *(float2*)&C[(size_t)r * N + c]       = lo;
                *(float2*)&C[(size_t)(r + 8) * N + c] = hi;
            }
        }
    }
}

// ---------------------------------------------------------------------------
// PoPE transform: reads fused fp16 QKV buffer, writes fp16 qp/kp.
// ---------------------------------------------------------------------------
__device__ __forceinline__ float softplus_f(float x) {
    return fmaxf(x, 0.f) + log1pf(expf(-fabsf(x)));
}

__global__ void pope_kernel(const __half* __restrict__ qkv,
                            const int* __restrict__ positions,
                            const float* __restrict__ freqs,
                            const float* __restrict__ phase_bias,
                            __half* __restrict__ qp, __half* __restrict__ kp)
{
    int idx = blockIdx.x * blockDim.x + threadIdx.x;   // B*H*S*32
    if (idx >= BATCH * NHEADS * SEQ * 32) return;
    int d = (idx & 31) * 2;
    int s = (idx >> 5) & (SEQ - 1);
    int h = (idx >> 16) & (NHEADS - 1);
    int b = idx >> 20;

    size_t rowb = (size_t)(b * SEQ + s) * QKVN + h * HEADDIM + d;
    float2 qv = __half22float2(*(const __half2*)&qkv[rowb]);
    float2 kv = __half22float2(*(const __half2*)&qkv[rowb + DMODEL]);

    float pos = (float)positions[s];
    float ph0 = pos * freqs[d]     + phase_bias[h * HEADDIM + d];
    float ph1 = pos * freqs[d + 1] + phase_bias[h * HEADDIM + d + 1];
    float c0, s0, c1, s1;
    sincosf(ph0, &s0, &c0);
    sincosf(ph1, &s1, &c1);

    float mq0 = softplus_f(qv.x) * ATTN_SCALE, mq1 = softplus_f(qv.y) * ATTN_SCALE;
    float mk0 = softplus_f(kv.x),              mk1 = softplus_f(kv.y);

    size_t base = (((size_t)(b * NHEADS + h) * SEQ) + s) * 128 + d;
    *(__half2*)&qp[base]      = __floats2half2_rn(mq0 * c0, mq1 * c1);
    *(__half2*)&qp[base + 64] = __floats2half2_rn(mq0 * s0, mq1 * s1);
    *(__half2*)&kp[base]      = __floats2half2_rn(mk0 * c0, mk1 * c1);
    *(__half2*)&kp[base + 64] = __floats2half2_rn(mk0 * s0, mk1 * s1);
}

// ---------------------------------------------------------------------------
// Flash attention with softmax1, fp16 mma + ldmatrix. 2 CTAs/SM.
// Double-buffered cp.async K/V, one sync per tile; softmax via MUFU.EX2.
// ---------------------------------------------------------------------------
#define AT_QS 136
#define AT_PS 72
#define AT_KS 136
#define AT_VS 72
#define AT_Q_HALVES (128 * AT_QS)             // aliased by Ps (128 x 72)
#define AT_K_STAGE  (64 * AT_KS)
#define AT_V_STAGE  (64 * AT_VS)
#define AT_SMEM_HALVES (AT_Q_HALVES + 2 * AT_K_STAGE + 2 * AT_V_STAGE)
#define AT_SMEM_BYTES  (AT_SMEM_HALVES * 2)   // 88064 B

__global__ __launch_bounds__(256, 2)
void attn_h_kernel(const __half* __restrict__ qp, const __half* __restrict__ kp,
                   const __half* __restrict__ qkv, __half* __restrict__ out)
{
    extern __shared__ __half hsm[];
    __half* Qs = hsm;                           // 128 x 136 (staging)
    __half* Ps = hsm;                           // 128 x 72 (aliases Qs)

    const int b = blockIdx.z;
    const int h = blockIdx.y;
    const int qtile = gridDim.x - 1 - blockIdx.x;   // heavy tiles first
    const int q0 = qtile * 128;

    const int tid  = threadIdx.x;
    const int lane = tid & 31, wid = tid >> 5;
    const int grp = lane >> 2, tig = lane & 3;
    const int r0 = wid * 16 + grp;

    const int l8  = lane & 7;
    const int q01 = (lane >> 3) & 1;
    const int q23 = lane >> 4;

    const uint32_t smbase = smem_u32(hsm);
    const uint32_t pssm  = smbase;                               // Ps
    const uint32_t kssm0 = smbase + AT_Q_HALVES * 2;             // K stage 0
    const uint32_t vssm0 = kssm0 + 2 * AT_K_STAGE * 2;           // V stage 0

    const __half* qbase = qp + (((size_t)(b * NHEADS + h)) * SEQ) * 128;
    const __half* kbase = kp + (((size_t)(b * NHEADS + h)) * SEQ) * 128;
    const __half* vbase = qkv + 2 * DMODEL + h * HEADDIM;        // V cols in fused buffer

    auto load_kv = [&](int stage, int kt) {
        uint32_t kb = kssm0 + stage * AT_K_STAGE * 2;
#pragma unroll
        for (int i = 0; i < 4; ++i) {
            int idx = tid + i * 256;
            int r = idx >> 4, c = idx & 15;
            cp_async16(kb + (uint32_t)(r * AT_KS + c * 8) * 2,
                       kbase + (size_t)(kt + r) * 128 + c * 8);
        }
        uint32_t vb = vssm0 + stage * AT_V_STAGE * 2;
#pragma unroll
        for (int i = 0; i < 2; ++i) {
            int idx = tid + i * 256;
            int r = idx >> 3, c = idx & 7;
            cp_async16(vb + (uint32_t)(r * AT_VS + c * 8) * 2,
                       vbase + ((size_t)b * SEQ + kt + r) * QKVN + c * 8);
        }
    };

    // Prologue: start K/V tile 0 fetch, then stage Q.
    load_kv(0, 0);
    asm volatile("cp.async.commit_group;" ::: "memory");

    for (int i = tid; i < 2048; i += 256) {
        int r = i >> 4, c = i & 15;
        *(uint4*)&Qs[r * AT_QS + c * 8] =
            *(const uint4*)&qbase[(size_t)(q0 + r) * 128 + c * 8];
    }
    __syncthreads();

    // Preload Q fragments via ldmatrix: 8 k16 chunks
    uint32_t qf[8][4];
    {
        int row = wid * 16 + q01 * 8 + l8;
#pragma unroll
        for (int kk = 0; kk < 8; ++kk) {
            int col = kk * 16 + q23 * 8;
            ldsm_x4(qf[kk], smbase + (uint32_t)(row * AT_QS + col) * 2);
        }
    }
    __syncthreads();   // done reading Qs before Ps overwrites

    float m0 = -INFINITY, m1 = -INFINITY, l0 = 0.f, l1 = 0.f;
    float o[8][4];
#pragma unroll
    for (int nj = 0; nj < 8; ++nj)
#pragma unroll
        for (int r = 0; r < 4; ++r) o[nj][r] = 0.f;

    const int nT = q0 / 64 + 2;
    for (int t = 0; t < nT; ++t) {
        const int kt = t * 64;
        asm volatile("cp.async.wait_group 0;" ::: "memory");
        __syncthreads();
        if (t + 1 < nT) {
            load_kv((t + 1) & 1, (t + 1) * 64);
            asm volatile("cp.async.commit_group;" ::: "memory");
        }
        const uint32_t kst = kssm0 + (t & 1) * AT_K_STAGE * 2;
        const uint32_t vst = vssm0 + (t & 1) * AT_V_STAGE * 2;

        // scores = Q @ K^T
        float sacc[8][4];
#pragma unroll
        for (int nj = 0; nj < 8; ++nj)
#pragma unroll
            for (int r = 0; r < 4; ++r) sacc[nj][r] = 0.f;

#pragma unroll
        for (int kk = 0; kk < 8; ++kk) {
            int k = kk * 16;
#pragma unroll
            for (int g = 0; g < 4; ++g) {
                uint32_t bf[4];
                int row = g * 16 + q23 * 8 + l8;
                int col = k + q01 * 8;
                ldsm_x4(bf, kst + (uint32_t)(row * AT_KS + col) * 2);
                mma_f16(sacc[g * 2 + 0], qf[kk], bf[0], bf[1]);
                mma_f16(sacc[g * 2 + 1], qf[kk], bf[2], bf[3]);
            }
        }

        // causal mask (last two key tiles only)
        if (kt >= q0) {
            int row0 = q0 + r0, row1 = row0 + 8;
#pragma unroll
            for (int nj = 0; nj < 8; ++nj) {
                int c = kt + nj * 8 + 2 * tig;
                if (c     > row0) sacc[nj][0] = -INFINITY;
                if (c + 1 > row0) sacc[nj][1] = -INFINITY;
                if (c     > row1) sacc[nj][2] = -INFINITY;
                if (c + 1 > row1) sacc[nj][3] = -INFINITY;
            }
        }

        // online softmax1 (fast ex2)
        float mx0 = -INFINITY, mx1 = -INFINITY;
#pragma unroll
        for (int nj = 0; nj < 8; ++nj) {
            mx0 = fmaxf(mx0, fmaxf(sacc[nj][0], sacc[nj][1]));
            mx1 = fmaxf(mx1, fmaxf(sacc[nj][2], sacc[nj][3]));
        }
        mx0 = fmaxf(mx0, __shfl_xor_sync(0xffffffffu, mx0, 1));
        mx0 = fmaxf(mx0, __shfl_xor_sync(0xffffffffu, mx0, 2));
        mx1 = fmaxf(mx1, __shfl_xor_sync(0xffffffffu, mx1, 1));
        mx1 = fmaxf(mx1, __shfl_xor_sync(0xffffffffu, mx1, 2));

        float m0n = fmaxf(m0, mx0), m1n = fmaxf(m1, mx1);
        float c0 = fexpf(m0 - m0n),  c1 = fexpf(m1 - m1n);
        m0 = m0n; m1 = m1n;

        float ls0 = 0.f, ls1 = 0.f;
#pragma unroll
        for (int nj = 0; nj < 8; ++nj) {
            float p0 = fexpf(sacc[nj][0] - m0n);
            float p1 = fexpf(sacc[nj][1] - m0n);
            float p2 = fexpf(sacc[nj][2] - m1n);
            float p3 = fexpf(sacc[nj][3] - m1n);
            ls0 += p0 + p1; ls1 += p2 + p3;
            *(__half2*)&Ps[r0       * AT_PS + nj * 8 + 2 * tig] = __floats2half2_rn(p0, p1);
            *(__half2*)&Ps[(r0 + 8) * AT_PS + nj * 8 + 2 * tig] = __floats2half2_rn(p2, p3);
        }
        ls0 += __shfl_xor_sync(0xffffffffu, ls0, 1);
        ls0 += __shfl_xor_sync(0xffffffffu, ls0, 2);
        ls1 += __shfl_xor_sync(0xffffffffu, ls1, 1);
        ls1 += __shfl_xor_sync(0xffffffffu, ls1, 2);
        l0 = l0 * c0 + ls0;
        l1 = l1 * c1 + ls1;

#pragma unroll
        for (int nj = 0; nj < 8; ++nj) {
            o[nj][0] *= c0; o[nj][1] *= c0;
            o[nj][2] *= c1; o[nj][3] *= c1;
        }
        __syncwarp();

        // O += P @ V (V row-major [key][dim]; B fragments via ldmatrix.trans)
#pragma unroll
        for (int kk = 0; kk < 4; ++kk) {
            int k = kk * 16;
            uint32_t af[4];
            {
                int row = wid * 16 + q01 * 8 + l8;
                int col = k + q23 * 8;
                ldsm_x4(af, pssm + (uint32_t)(row * AT_PS + col) * 2);
            }
#pragma unroll
            for (int g = 0; g < 4; ++g) {
                uint32_t bf[4];
                int row = k + q01 * 8 + l8;          // key index
                int col = g * 16 + q23 * 8;          // dim index
                ldsm_x4_t(bf, vst + (uint32_t)(row * AT_VS + col) * 2);
                mma_f16(o[g * 2 + 0], af, bf[0], bf[1]);
                mma_f16(o[g * 2 + 1], af, bf[2], bf[3]);
            }
        }
    }

    // epilogue: softmax1 denominator; write fp16 (B,S,D)
    float inv0 = 1.f / (1.f + l0);
    float inv1 = 1.f / (1.f + l1);
    int row0 = q0 + r0;
#pragma unroll
    for (int nj = 0; nj < 8; ++nj) {
        int c = h * HEADDIM + nj * 8 + 2 * tig;
        *(__half2*)&out[((size_t)b * SEQ + row0)     * DMODEL + c] =
            __floats2half2_rn(o[nj][0] * inv0, o[nj][1] * inv0);
        *(__half2*)&out[((size_t)b * SEQ + row0 + 8) * DMODEL + c] =
            __floats2half2_rn(o[nj][2] * inv1, o[nj][3] * inv1);
    }
}

// ---------------------------------------------------------------------------
// Fused residual add + LayerNorm; optional fp16 copy of the output.
// ---------------------------------------------------------------------------
template<int WRITEH>
__global__ __launch_bounds__(256)
void add_ln_kernel(const float* __restrict__ x, const float* __restrict__ y,
                   const float* __restrict__ g, const float* __restrict__ beta,
                   float* __restrict__ out, __half* __restrict__ outh)
{
    __shared__ float red_s[8];
    __shared__ float red_ss[8];
    __shared__ float s_mu, s_rstd;

    const int row = blockIdx.x;
    const int tid = threadIdx.x;
    const size_t base = (size_t)row * DMODEL;

    float4 xv = ((const float4*)(x + base))[tid];
    float4 yv = ((const float4*)(y + base))[tid];
    float v0 = xv.x + yv.x, v1 = xv.y + yv.y, v2 = xv.z + yv.z, v3 = xv.w + yv.w;

    float sum = v0 + v1 + v2 + v3;
    float ssq = v0 * v0 + v1 * v1 + v2 * v2 + v3 * v3;
#pragma unroll
    for (int off = 16; off >= 1; off >>= 1) {
        sum += __shfl_down_sync(0xffffffffu, sum, off);
        ssq += __shfl_down_sync(0xffffffffu, ssq, off);
    }
    const int warp = tid >> 5;
    if ((tid & 31) == 0) { red_s[warp] = sum; red_ss[warp] = ssq; }
    __syncthreads();
    if (tid == 0) {
        float ts = 0.f, tss = 0.f;
#pragma unroll
        for (int w = 0; w < 8; ++w) { ts += red_s[w]; tss += red_ss[w]; }
        float mu  = ts / (float)DMODEL;
        float var = tss / (float)DMODEL - mu * mu;
        s_mu = mu;
        s_rstd = rsqrtf(var + LN_EPS);
    }
    __syncthreads();
    const float mu = s_mu, rstd = s_rstd;

    float4 gv = ((const float4*)g)[tid];
    float4 bv = ((const float4*)beta)[tid];
    float4 o;
    o.x = (v0 - mu) * rstd * gv.x + bv.x;
    o.y = (v1 - mu) * rstd * gv.y + bv.y;
    o.z = (v2 - mu) * rstd * gv.z + bv.z;
    o.w = (v3 - mu) * rstd * gv.w + bv.w;
    ((float4*)(out + base))[tid] = o;
    if (WRITEH) {
        __half2 h0 = __floats2half2_rn(o.x, o.y);
        __half2 h1 = __floats2half2_rn(o.z, o.w);
        ((__half2*)(outh + base))[2 * tid]     = h0;
        ((__half2*)(outh + base))[2 * tid + 1] = h1;
    }
}

// ---------------------------------------------------------------------------
// Launcher
// ---------------------------------------------------------------------------
extern "C" void kernel_launch(void* const* d_in, const int* in_sizes, int n_in,
                              void* d_out, int out_size)
{
    (void)in_sizes; (void)n_in; (void)out_size;
    const float* x          = (const float*)d_in[0];
    const int*   positions  = (const int*)  d_in[1];
    const float* Wq         = (const float*)d_in[2];
    const float* bq         = (const float*)d_in[3];
    const float* Wk         = (const float*)d_in[4];
    const float* bk         = (const float*)d_in[5];
    const float* Wv         = (const float*)d_in[6];
    const float* bv         = (const float*)d_in[7];
    const float* Wo         = (const float*)d_in[8];
    const float* bo         = (const float*)d_in[9];
    const float* phase_bias = (const float*)d_in[10];
    const float* freqs      = (const float*)d_in[11];
    const float* W1         = (const float*)d_in[12];
    const float* b1         = (const float*)d_in[13];
    const float* W2         = (const float*)d_in[14];
    const float* b2         = (const float*)d_in[15];
    const float* g1         = (const float*)d_in[16];
    const float* beta1      = (const float*)d_in[17];
    const float* g2         = (const float*)d_in[18];
    const float* beta2      = (const float*)d_in[19];
    float* outp             = (float*)d_out;

    float  *bufA, *bufB, *bufX1, *bqkv;
    __half *xh, *QKVh, *QPh, *KPh, *AttnH, *X1h, *FFh;
    __half *Wcat, *Woh, *W1h, *W2h;
    cudaGetSymbolAddress((void**)&bufA,  g_bufA);
    cudaGetSymbolAddress((void**)&bufB,  g_bufB);
    cudaGetSymbolAddress((void**)&bufX1, g_bufX1);
    cudaGetSymbolAddress((void**)&bqkv,  g_bqkv);
    cudaGetSymbolAddress((void**)&xh,    g_xh);
    cudaGetSymbolAddress((void**)&QKVh,  g_QKVh);
    cudaGetSymbolAddress((void**)&QPh,   g_QPh);
    cudaGetSymbolAddress((void**)&KPh,   g_KPh);
    cudaGetSymbolAddress((void**)&AttnH, g_AttnH);
    cudaGetSymbolAddress((void**)&X1h,   g_X1h);
    cudaGetSymbolAddress((void**)&FFh,   g_FFh);
    cudaGetSymbolAddress((void**)&Wcat,  g_Wcat);
    cudaGetSymbolAddress((void**)&Woh,   g_Woh);
    cudaGetSymbolAddress((void**)&W1h,   g_W1h);
    cudaGetSymbolAddress((void**)&W2h,   g_W2h);

    cudaFuncSetAttribute(attn_h_kernel, cudaFuncAttributeMaxDynamicSharedMemorySize,
                         AT_SMEM_BYTES);
    cudaFuncSetAttribute(hgemm_kernel<0,0>, cudaFuncAttributeMaxDynamicSharedMemorySize,
                         HG_SMEM_BYTES);
    cudaFuncSetAttribute(hgemm_kernel<0,1>, cudaFuncAttributeMaxDynamicSharedMemorySize,
                         HG_SMEM_BYTES);
    cudaFuncSetAttribute(hgemm_kernel<1,1>, cudaFuncAttributeMaxDynamicSharedMemorySize,
                         HG_SMEM_BYTES);

    // 0a: x -> fp16
    f2h_kernel<<<(BS * DMODEL / 8 + 255) / 256, 256>>>(x, xh, BS * DMODEL);

    // 0b: weight fp16 conversions (NATIVE layout; QKV concatenated column-wise)
    {
        int nqk = DMODEL * DMODEL / 8;
        f2h_cat_kernel<<<(nqk + 255) / 256, 256>>>(Wq, Wcat, DMODEL, DMODEL, QKVN, 0);
        f2h_cat_kernel<<<(nqk + 255) / 256, 256>>>(Wk, Wcat, DMODEL, DMODEL, QKVN, DMODEL);
        f2h_cat_kernel<<<(nqk + 255) / 256, 256>>>(Wv, Wcat, DMODEL, DMODEL, QKVN, 2 * DMODEL);
        f2h_kernel<<<(DMODEL * DMODEL / 8 + 255) / 256, 256>>>(Wo, Woh, DMODEL * DMODEL);
        f2h_kernel<<<(DMODEL * DFF / 8 + 255) / 256, 256>>>(W1, W1h, DMODEL * DFF);
        f2h_kernel<<<(DFF * DMODEL / 8 + 255) / 256, 256>>>(W2, W2h, DFF * DMODEL);
        concat_bias_kernel<<<(QKVN + 255) / 256, 256>>>(bq, bk, bv, bqkv);
    }

    // 1: fused QKV projection (N=3072), fp16 out
    {
        dim3 grid(QKVN / 128, BS / 128);
        hgemm_kernel<0,1><<<grid, 256, HG_SMEM_BYTES>>>(xh, Wcat, bqkv, QKVh, BS, QKVN, DMODEL);
    }

    // 2: PoPE (fp16 in/out)
    {
        int total = BATCH * NHEADS * SEQ * 32;
        pope_kernel<<<(total + 255) / 256, 256>>>(QKVh, positions, freqs,
                                                  phase_bias, QPh, KPh);
    }

    // 3: attention -> fp16
    {
        dim3 grid(SEQ / 128, NHEADS, BATCH);
        attn_h_kernel<<<grid, 256, AT_SMEM_BYTES>>>(QPh, KPh, QKVh, AttnH);
    }

    // 4: output projection -> fp32
    {
        dim3 grid(DMODEL / 128, BS / 128);
        hgemm_kernel<0,0><<<grid, 256, HG_SMEM_BYTES>>>(AttnH, Woh, bo, bufA, BS, DMODEL, DMODEL);
    }

    // 5: residual + LN1 -> fp32 + fp16
    add_ln_kernel<1><<<BS, 256>>>(x, bufA, g1, beta1, bufX1, X1h);

    // 6: FFN up + ReLU -> fp16
    {
        dim3 grid(DFF / 128, BS / 128);
        hgemm_kernel<1,1><<<grid, 256, HG_SMEM_BYTES>>>(X1h, W1h, b1, FFh, BS, DFF, DMODEL);
    }

    // 7: FFN down -> fp32
    {
        dim3 grid(DMODEL / 128, BS / 128);
        hgemm_kernel<0,0><<<grid, 256, HG_SMEM_BYTES>>>(FFh, W2h, b2, bufB, BS, DMODEL, DFF);
    }

    // 8: residual + LN2 -> output
    add_ln_kernel<0><<<BS, 256>>>(bufX1, bufB, g2, beta2, outp, nullptr);
}

// round 13
// speedup vs baseline: 1.1299x; 1.0157x over previous
#include <cuda_runtime.h>
#include <cuda_fp16.h>
#include <math.h>
#include <stdint.h>

// ---------------------------------------------------------------------------
// Problem constants
// ---------------------------------------------------------------------------
#define BATCH   2
#define SEQ     2048
#define DMODEL  1024
#define NHEADS  16
#define HEADDIM 64
#define DFF     4096
#define BS      (BATCH * SEQ)          // 4096 rows
#define LN_EPS  1e-5f
#define ATTN_SCALE 0.08838834764831845f   // 1/sqrt(128)
#define QKVN    (3 * DMODEL)           // fused QKV width

// ---------------------------------------------------------------------------
// Scratch buffers
// ---------------------------------------------------------------------------
__device__ float  g_bufA   [BS * DMODEL];            // Wo out (fp32)
__device__ float  g_bufB   [BS * DMODEL];            // FFN2 out (fp32)
__device__ float  g_bufX1  [BS * DMODEL];            // LN1 out fp32
__device__ __half g_xh     [BS * DMODEL];            // x in fp16
__device__ __half g_QKVh   [BS * QKVN];              // fused QKV output fp16
__device__ __half g_QPh    [BATCH * NHEADS * SEQ * 2 * HEADDIM];
__device__ __half g_KPh    [BATCH * NHEADS * SEQ * 2 * HEADDIM];
__device__ __half g_AttnH  [BS * DMODEL];            // attention out fp16
__device__ __half g_X1h    [BS * DMODEL];            // LN1 out fp16
__device__ __half g_FFh    [BS * DFF];               // FFN hidden fp16

// fp16 weights in NATIVE [K][N] layout (no transpose needed: ldmatrix.trans)
__device__ __half g_Wcat[DMODEL * QKVN];             // cols: Wq | Wk | Wv
__device__ float  g_bqkv[QKVN];
__device__ __half g_Woh[DMODEL * DMODEL];
__device__ __half g_W1h[DMODEL * DFF];
__device__ __half g_W2h[DFF * DMODEL];

// ---------------------------------------------------------------------------
// Helpers
// ---------------------------------------------------------------------------
__device__ __forceinline__ uint32_t smem_u32(const void* p) {
    uint32_t a;
    asm("{ .reg .u64 t; cvta.to.shared.u64 t, %1; cvt.u32.u64 %0, t; }"
        : "=r"(a) : "l"(p));
    return a;
}

__device__ __forceinline__ void cp_async16(uint32_t saddr, const void* gptr) {
    asm volatile("cp.async.cg.shared.global [%0], [%1], 16;"
                 :: "r"(saddr), "l"(gptr) : "memory");
}

// fp16 mma m16n8k16, fp32 accumulate
__device__ __forceinline__ void mma_f16(float (&d)[4],
                                        const uint32_t (&a)[4],
                                        uint32_t b0, uint32_t b1)
{
    asm volatile(
        "mma.sync.aligned.m16n8k16.row.col.f32.f16.f16.f32 "
        "{%0,%1,%2,%3}, {%4,%5,%6,%7}, {%8,%9}, {%0,%1,%2,%3};"
        : "+f"(d[0]), "+f"(d[1]), "+f"(d[2]), "+f"(d[3])
        : "r"(a[0]), "r"(a[1]), "r"(a[2]), "r"(a[3]), "r"(b0), "r"(b1));
}

__device__ __forceinline__ void ldsm_x4(uint32_t (&r)[4], uint32_t saddr) {
    asm volatile("ldmatrix.sync.aligned.m8n8.x4.shared.b16 {%0,%1,%2,%3}, [%4];"
                 : "=r"(r[0]), "=r"(r[1]), "=r"(r[2]), "=r"(r[3]) : "r"(saddr));
}

__device__ __forceinline__ void ldsm_x4_t(uint32_t (&r)[4], uint32_t saddr) {
    asm volatile("ldmatrix.sync.aligned.m8n8.x4.trans.shared.b16 {%0,%1,%2,%3}, [%4];"
                 : "=r"(r[0]), "=r"(r[1]), "=r"(r[2]), "=r"(r[3]) : "r"(saddr));
}

// Fast exp via MUFU.EX2 (args are <= 0 here; ex2.approx(-inf) = 0)
__device__ __forceinline__ float fexpf(float x) {
    float y = x * 1.4426950408889634f;
    float r;
    asm("ex2.approx.f32 %0, %1;" : "=f"(r) : "f"(y));
    return r;
}

// ---------------------------------------------------------------------------
// fp32 -> fp16 convert (8 elements per thread)
// ---------------------------------------------------------------------------
__global__ __launch_bounds__(256)
void f2h_kernel(const float* __restrict__ in, __half* __restrict__ out, int n)
{
    int i = (blockIdx.x * blockDim.x + threadIdx.x) * 8;
    if (i >= n) return;
    float4 a = *(const float4*)(in + i);
    float4 b = *(const float4*)(in + i + 4);
    __half2 h[4];
    h[0] = __floats2half2_rn(a.x, a.y);
    h[1] = __floats2half2_rn(a.z, a.w);
    h[2] = __floats2half2_rn(b.x, b.y);
    h[3] = __floats2half2_rn(b.z, b.w);
    *(uint4*)(out + i) = *(uint4*)h;
}

// ---------------------------------------------------------------------------
// ALL weight conversions + bias concat in ONE launch. grid.y selects item:
//   0..2: Wq/Wk/Wv -> Wcat (strided rows, column-concat)
//   3: Wo, 4: W1, 5: W2 (flat), 6: bias concat
// ---------------------------------------------------------------------------
__global__ __launch_bounds__(256)
void f2h_weights_kernel(const float* __restrict__ Wq, const float* __restrict__ Wk,
                        const float* __restrict__ Wv, const float* __restrict__ Wo,
                        const float* __restrict__ W1, const float* __restrict__ W2,
                        const float* __restrict__ bq, const float* __restrict__ bk,
                        const float* __restrict__ bv,
                        __half* __restrict__ Wcat, __half* __restrict__ Woh,
                        __half* __restrict__ W1h, __half* __restrict__ W2h,
                        float* __restrict__ bqkv)
{
    const int id  = blockIdx.y;
    const int idx = blockIdx.x * 256 + threadIdx.x;   // chunk of 8 elems

    if (id == 6) {
        if (idx >= QKVN) return;
        float v = (idx < DMODEL) ? bq[idx]
                : (idx < 2 * DMODEL) ? bk[idx - DMODEL] : bv[idx - 2 * DMODEL];
        bqkv[idx] = v;
        return;
    }

    const float* src;
    __half* dst;
    int nchunks;
    if (id < 3)      { src = (id == 0) ? Wq : (id == 1) ? Wk : Wv;
                       dst = Wcat; nchunks = DMODEL * DMODEL / 8; }
    else if (id == 3){ src = Wo; dst = Woh; nchunks = DMODEL * DMODEL / 8; }
    else if (id == 4){ src = W1; dst = W1h; nchunks = DMODEL * DFF / 8; }
    else             { src = W2; dst = W2h; nchunks = DFF * DMODEL / 8; }
    if (idx >= nchunks) return;

    float4 a = *(const float4*)(src + idx * 8);
    float4 b = *(const float4*)(src + idx * 8 + 4);
    __half2 h[4];
    h[0] = __floats2half2_rn(a.x, a.y);
    h[1] = __floats2half2_rn(a.z, a.w);
    h[2] = __floats2half2_rn(b.x, b.y);
    h[3] = __floats2half2_rn(b.z, b.w);

    if (id < 3) {
        int r = idx >> 7;            // 128 chunks per 1024-wide row
        int c = idx & 127;
        *(uint4*)(dst + (size_t)r * QKVN + id * DMODEL + c * 8) = *(uint4*)h;
    } else {
        *(uint4*)(dst + (size_t)idx * 8) = *(uint4*)h;
    }
}

// ---------------------------------------------------------------------------
// fp16 mma GEMM: C(MxN) = A(MxK) @ W(KxN) + bias. W in NATIVE [K][N] layout;
// B fragments via ldmatrix.trans. 128x128x32 tiles, 8 warps, 5-stage cp.async
// pipeline (prefetch distance 4), one sync per K-iter, 2 CTAs/SM.
// ---------------------------------------------------------------------------
#define HG_STRIDE 40          // A tile stride (halves)
#define HG_BS     136         // B tile stride (halves), 32 rows x 128 cols
#define HG_STAGES 5
#define HG_A_HALVES (128 * HG_STRIDE)
#define HG_B_HALVES (32 * HG_BS)
#define HG_STAGE_HALVES (HG_A_HALVES + HG_B_HALVES)       // 9472
#define HG_SMEM_BYTES (HG_STAGES * HG_STAGE_HALVES * 2)   // 94720 B

template<int RELU, int HALFOUT>
__global__ __launch_bounds__(256, 2)
void hgemm_kernel(const __half* __restrict__ A, const __half* __restrict__ W,
                  const float* __restrict__ bias, void* __restrict__ Cv,
                  int M, int N, int K)
{
    extern __shared__ __half hsm[];

    const int tid  = threadIdx.x;
    const int lane = tid & 31, wid = tid >> 5;
    const int wm = wid >> 1, wn = wid & 1;
    const int grp = lane >> 2, tig = lane & 3;
    const int m0 = blockIdx.y * 128, n0 = blockIdx.x * 128;

    const uint32_t smbase = smem_u32(hsm);

    const int l8  = lane & 7;
    const int q01 = (lane >> 3) & 1;
    const int q23 = lane >> 4;

    float acc[2][8][4];
#pragma unroll
    for (int mi = 0; mi < 2; ++mi)
#pragma unroll
        for (int nj = 0; nj < 8; ++nj)
#pragma unroll
            for (int r = 0; r < 4; ++r) acc[mi][nj][r] = 0.f;

    auto load_tiles = [&](int stage, int k0) {
        uint32_t ab = smbase + stage * HG_STAGE_HALVES * 2;
        uint32_t bb = ab + HG_A_HALVES * 2;
#pragma unroll
        for (int i = 0; i < 2; ++i) {
            int idx = tid + i * 256;
            int r = idx >> 2, c = idx & 3;
            cp_async16(ab + (uint32_t)(r * HG_STRIDE + c * 8) * 2,
                       A + (size_t)(m0 + r) * K + k0 + c * 8);
        }
#pragma unroll
        for (int i = 0; i < 2; ++i) {
            int idx = tid + i * 256;
            int r = idx >> 4, c = idx & 15;
            cp_async16(bb + (uint32_t)(r * HG_BS + c * 8) * 2,
                       W + (size_t)(k0 + r) * N + n0 + c * 8);
        }
    };

    const int nIt = K / 32;
#pragma unroll
    for (int s = 0; s < HG_STAGES - 1; ++s) {
        load_tiles(s, s * 32);
        asm volatile("cp.async.commit_group;" ::: "memory");
    }

    int st = 0, lst = HG_STAGES - 1;
    for (int it = 0; it < nIt; ++it) {
        asm volatile("cp.async.wait_group 3;" ::: "memory");
        __syncthreads();
        if (it + HG_STAGES - 1 < nIt) {
            load_tiles(lst, (it + HG_STAGES - 1) * 32);
            asm volatile("cp.async.commit_group;" ::: "memory");
            lst = (lst == HG_STAGES - 1) ? 0 : lst + 1;
        }

        const uint32_t abase = smbase + st * HG_STAGE_HALVES * 2;
        const uint32_t bbase = abase + HG_A_HALVES * 2;
        st = (st == HG_STAGES - 1) ? 0 : st + 1;

#pragma unroll
        for (int kk = 0; kk < 2; ++kk) {
            const int k = kk * 16;
            uint32_t af[2][4];
#pragma unroll
            for (int mi = 0; mi < 2; ++mi) {
                int row = wm * 32 + mi * 16 + q01 * 8 + l8;
                int col = k + q23 * 8;
                ldsm_x4(af[mi], abase + (uint32_t)(row * HG_STRIDE + col) * 2);
            }
#pragma unroll
            for (int g = 0; g < 4; ++g) {
                uint32_t bf[4];
                int row = k + q01 * 8 + l8;                 // k index
                int col = wn * 64 + g * 16 + q23 * 8;       // n index
                ldsm_x4_t(bf, bbase + (uint32_t)(row * HG_BS + col) * 2);
#pragma unroll
                for (int h2 = 0; h2 < 2; ++h2)
#pragma unroll
                    for (int mi = 0; mi < 2; ++mi)
                        mma_f16(acc[mi][g * 2 + h2], af[mi], bf[h2 * 2], bf[h2 * 2 + 1]);
            }
        }
    }

#pragma unroll
    for (int mi = 0; mi < 2; ++mi) {
        int r = m0 + wm * 32 + mi * 16 + grp;
#pragma unroll
        for (int nj = 0; nj < 8; ++nj) {
            int c = n0 + wn * 64 + nj * 8 + tig * 2;
            float bb0 = bias[c], bb1 = bias[c + 1];
            float v0 = acc[mi][nj][0] + bb0;
            float v1 = acc[mi][nj][1] + bb1;
            float v2 = acc[mi][nj][2] + bb0;
            float v3 = acc[mi][nj][3] + bb1;
            if (RELU) {
                v0 = fmaxf(v0, 0.f); v1 = fmaxf(v1, 0.f);
                v2 = fmaxf(v2, 0.f); v3 = fmaxf(v3, 0.f);
            }
            if (HALFOUT) {
                __half* C = (__half*)Cv;
                *(__half2*)&C[(size_t)r * N + c]       = __floats2half2_rn(v0, v1);
                *(__half2*)&C[(size_t)(r + 8) * N + c] = __floats2half2_rn(v2, v3);
            } else {
                float* C = (float*)Cv;
                float2 lo; lo.x = v0; lo.y = v1;
                float2 hi; hi.x = v2; hi.y = v3;
                *(float2*)&C[(size_t)r * N + c]       = lo;
                *(float2*)&C[(size_t)(r + 8) * N + c] = hi;
            }
        }
    }
}

// ---------------------------------------------------------------------------
// PoPE transform: reads fused fp16 QKV buffer, writes fp16 qp/kp.
// ---------------------------------------------------------------------------
__device__ __forceinline__ float softplus_f(float x) {
    return fmaxf(x, 0.f) + log1pf(expf(-fabsf(x)));
}

__global__ void pope_kernel(const __half* __restrict__ qkv,
                            const int* __restrict__ positions,
                            const float* __restrict__ freqs,
                            const float* __restrict__ phase_bias,
                            __half* __restrict__ qp, __half* __restrict__ kp)
{
    int idx = blockIdx.x * blockDim.x + threadIdx.x;   // B*H*S*32
    if (idx >= BATCH * NHEADS * SEQ * 32) return;
    int d = (idx & 31) * 2;
    int s = (idx >> 5) & (SEQ - 1);
    int h = (idx >> 16) & (NHEADS - 1);
    int b = idx >> 20;

    size_t rowb = (size_t)(b * SEQ + s) * QKVN + h * HEADDIM + d;
    float2 qv = __half22float2(*(const __half2*)&qkv[rowb]);
    float2 kv = __half22float2(*(const __half2*)&qkv[rowb + DMODEL]);

    float pos = (float)positions[s];
    float ph0 = pos * freqs[d]     + phase_bias[h * HEADDIM + d];
    float ph1 = pos * freqs[d + 1] + phase_bias[h * HEADDIM + d + 1];
    float c0, s0, c1, s1;
    sincosf(ph0, &s0, &c0);
    sincosf(ph1, &s1, &c1);

    float mq0 = softplus_f(qv.x) * ATTN_SCALE, mq1 = softplus_f(qv.y) * ATTN_SCALE;
    float mk0 = softplus_f(kv.x),              mk1 = softplus_f(kv.y);

    size_t base = (((size_t)(b * NHEADS + h) * SEQ) + s) * 128 + d;
    *(__half2*)&qp[base]      = __floats2half2_rn(mq0 * c0, mq1 * c1);
    *(__half2*)&qp[base + 64] = __floats2half2_rn(mq0 * s0, mq1 * s1);
    *(__half2*)&kp[base]      = __floats2half2_rn(mk0 * c0, mk1 * c1);
    *(__half2*)&kp[base + 64] = __floats2half2_rn(mk0 * s0, mk1 * s1);
}

// ---------------------------------------------------------------------------
// Flash attention with softmax1, fp16 mma + ldmatrix. 2 CTAs/SM.
// Double-buffered cp.async K/V, one sync per tile; softmax via MUFU.EX2.
// ---------------------------------------------------------------------------
#define AT_QS 136
#define AT_PS 72
#define AT_KS 136
#define AT_VS 72
#define AT_Q_HALVES (128 * AT_QS)             // aliased by Ps (128 x 72)
#define AT_K_STAGE  (64 * AT_KS)
#define AT_V_STAGE  (64 * AT_VS)
#define AT_SMEM_HALVES (AT_Q_HALVES + 2 * AT_K_STAGE + 2 * AT_V_STAGE)
#define AT_SMEM_BYTES  (AT_SMEM_HALVES * 2)   // 88064 B

__global__ __launch_bounds__(256, 2)
void attn_h_kernel(const __half* __restrict__ qp, const __half* __restrict__ kp,
                   const __half* __restrict__ qkv, __half* __restrict__ out)
{
    extern __shared__ __half hsm[];
    __half* Qs = hsm;                           // 128 x 136 (staging)
    __half* Ps = hsm;                           // 128 x 72 (aliases Qs)

    const int b = blockIdx.z;
    const int h = blockIdx.y;
    const int qtile = gridDim.x - 1 - blockIdx.x;   // heavy tiles first
    const int q0 = qtile * 128;

    const int tid  = threadIdx.x;
    const int lane = tid & 31, wid = tid >> 5;
    const int grp = lane >> 2, tig = lane & 3;
    const int r0 = wid * 16 + grp;

    const int l8  = lane & 7;
    const int q01 = (lane >> 3) & 1;
    const int q23 = lane >> 4;

    const uint32_t smbase = smem_u32(hsm);
    const uint32_t pssm  = smbase;                               // Ps
    const uint32_t kssm0 = smbase + AT_Q_HALVES * 2;             // K stage 0
    const uint32_t vssm0 = kssm0 + 2 * AT_K_STAGE * 2;           // V stage 0

    const __half* qbase = qp + (((size_t)(b * NHEADS + h)) * SEQ) * 128;
    const __half* kbase = kp + (((size_t)(b * NHEADS + h)) * SEQ) * 128;
    const __half* vbase = qkv + 2 * DMODEL + h * HEADDIM;        // V cols in fused buffer

    auto load_kv = [&](int stage, int kt) {
        uint32_t kb = kssm0 + stage * AT_K_STAGE * 2;
#pragma unroll
        for (int i = 0; i < 4; ++i) {
            int idx = tid + i * 256;
            int r = idx >> 4, c = idx & 15;
            cp_async16(kb + (uint32_t)(r * AT_KS + c * 8) * 2,
                       kbase + (size_t)(kt + r) * 128 + c * 8);
        }
        uint32_t vb = vssm0 + stage * AT_V_STAGE * 2;
#pragma unroll
        for (int i = 0; i < 2; ++i) {
            int idx = tid + i * 256;
            int r = idx >> 3, c = idx & 7;
            cp_async16(vb + (uint32_t)(r * AT_VS + c * 8) * 2,
                       vbase + ((size_t)b * SEQ + kt + r) * QKVN + c * 8);
        }
    };

    // Prologue: start K/V tile 0 fetch, then stage Q.
    load_kv(0, 0);
    asm volatile("cp.async.commit_group;" ::: "memory");

    for (int i = tid; i < 2048; i += 256) {
        int r = i >> 4, c = i & 15;
        *(uint4*)&Qs[r * AT_QS + c * 8] =
            *(const uint4*)&qbase[(size_t)(q0 + r) * 128 + c * 8];
    }
    __syncthreads();

    // Preload Q fragments via ldmatrix: 8 k16 chunks
    uint32_t qf[8][4];
    {
        int row = wid * 16 + q01 * 8 + l8;
#pragma unroll
        for (int kk = 0; kk < 8; ++kk) {
            int col = kk * 16 + q23 * 8;
            ldsm_x4(qf[kk], smbase + (uint32_t)(row * AT_QS + col) * 2);
        }
    }
    __syncthreads();   // done reading Qs before Ps overwrites

    float m0 = -INFINITY, m1 = -INFINITY, l0 = 0.f, l1 = 0.f;
    float o[8][4];
#pragma unroll
    for (int nj = 0; nj < 8; ++nj)
#pragma unroll
        for (int r = 0; r < 4; ++r) o[nj][r] = 0.f;

    const int nT = q0 / 64 + 2;
    for (int t = 0; t < nT; ++t) {
        const int kt = t * 64;
        asm volatile("cp.async.wait_group 0;" ::: "memory");
        __syncthreads();
        if (t + 1 < nT) {
            load_kv((t + 1) & 1, (t + 1) * 64);
            asm volatile("cp.async.commit_group;" ::: "memory");
        }
        const uint32_t kst = kssm0 + (t & 1) * AT_K_STAGE * 2;
        const uint32_t vst = vssm0 + (t & 1) * AT_V_STAGE * 2;

        // scores = Q @ K^T
        float sacc[8][4];
#pragma unroll
        for (int nj = 0; nj < 8; ++nj)
#pragma unroll
            for (int r = 0; r < 4; ++r) sacc[nj][r] = 0.f;

#pragma unroll
        for (int kk = 0; kk < 8; ++kk) {
            int k = kk * 16;
#pragma unroll
            for (int g = 0; g < 4; ++g) {
                uint32_t bf[4];
                int row = g * 16 + q23 * 8 + l8;
                int col = k + q01 * 8;
                ldsm_x4(bf, kst + (uint32_t)(row * AT_KS + col) * 2);
                mma_f16(sacc[g * 2 + 0], qf[kk], bf[0], bf[1]);
                mma_f16(sacc[g * 2 + 1], qf[kk], bf[2], bf[3]);
            }
        }

        // causal mask (last two key tiles only)
        if (kt >= q0) {
            int row0 = q0 + r0, row1 = row0 + 8;
#pragma unroll
            for (int nj = 0; nj < 8; ++nj) {
                int c = kt + nj * 8 + 2 * tig;
                if (c     > row0) sacc[nj][0] = -INFINITY;
                if (c + 1 > row0) sacc[nj][1] = -INFINITY;
                if (c     > row1) sacc[nj][2] = -INFINITY;
                if (c + 1 > row1) sacc[nj][3] = -INFINITY;
            }
        }

        // online softmax1 (fast ex2)
        float mx0 = -INFINITY, mx1 = -INFINITY;
#pragma unroll
        for (int nj = 0; nj < 8; ++nj) {
            mx0 = fmaxf(mx0, fmaxf(sacc[nj][0], sacc[nj][1]));
            mx1 = fmaxf(mx1, fmaxf(sacc[nj][2], sacc[nj][3]));
        }
        mx0 = fmaxf(mx0, __shfl_xor_sync(0xffffffffu, mx0, 1));
        mx0 = fmaxf(mx0, __shfl_xor_sync(0xffffffffu, mx0, 2));
        mx1 = fmaxf(mx1, __shfl_xor_sync(0xffffffffu, mx1, 1));
        mx1 = fmaxf(mx1, __shfl_xor_sync(0xffffffffu, mx1, 2));

        float m0n = fmaxf(m0, mx0), m1n = fmaxf(m1, mx1);
        float c0 = fexpf(m0 - m0n),  c1 = fexpf(m1 - m1n);
        m0 = m0n; m1 = m1n;

        float ls0 = 0.f, ls1 = 0.f;
#pragma unroll
        for (int nj = 0; nj < 8; ++nj) {
            float p0 = fexpf(sacc[nj][0] - m0n);
            float p1 = fexpf(sacc[nj][1] - m0n);
            float p2 = fexpf(sacc[nj][2] - m1n);
            float p3 = fexpf(sacc[nj][3] - m1n);
            ls0 += p0 + p1; ls1 += p2 + p3;
            *(__half2*)&Ps[r0       * AT_PS + nj * 8 + 2 * tig] = __floats2half2_rn(p0, p1);
            *(__half2*)&Ps[(r0 + 8) * AT_PS + nj * 8 + 2 * tig] = __floats2half2_rn(p2, p3);
        }
        ls0 += __shfl_xor_sync(0xffffffffu, ls0, 1);
        ls0 += __shfl_xor_sync(0xffffffffu, ls0, 2);
        ls1 += __shfl_xor_sync(0xffffffffu, ls1, 1);
        ls1 += __shfl_xor_sync(0xffffffffu, ls1, 2);
        l0 = l0 * c0 + ls0;
        l1 = l1 * c1 + ls1;

#pragma unroll
        for (int nj = 0; nj < 8; ++nj) {
            o[nj][0] *= c0; o[nj][1] *= c0;
            o[nj][2] *= c1; o[nj][3] *= c1;
        }
        __syncwarp();

        // O += P @ V (V row-major [key][dim]; B fragments via ldmatrix.trans)
#pragma unroll
        for (int kk = 0; kk < 4; ++kk) {
            int k = kk * 16;
            uint32_t af[4];
            {
                int row = wid * 16 + q01 * 8 + l8;
                int col = k + q23 * 8;
                ldsm_x4(af, pssm + (uint32_t)(row * AT_PS + col) * 2);
            }
#pragma unroll
            for (int g = 0; g < 4; ++g) {
                uint32_t bf[4];
                int row = k + q01 * 8 + l8;          // key index
                int col = g * 16 + q23 * 8;          // dim index
                ldsm_x4_t(bf, vst + (uint32_t)(row * AT_VS + col) * 2);
                mma_f16(o[g * 2 + 0], af, bf[0], bf[1]);
                mma_f16(o[g * 2 + 1], af, bf[2], bf[3]);
            }
        }
    }

    // epilogue: softmax1 denominator; write fp16 (B,S,D)
    float inv0 = 1.f / (1.f + l0);
    float inv1 = 1.f / (1.f + l1);
    int row0 = q0 + r0;
#pragma unroll
    for (int nj = 0; nj < 8; ++nj) {
        int c = h * HEADDIM + nj * 8 + 2 * tig;
        *(__half2*)&out[((size_t)b * SEQ + row0)     * DMODEL + c] =
            __floats2half2_rn(o[nj][0] * inv0, o[nj][1] * inv0);
        *(__half2*)&out[((size_t)b * SEQ + row0 + 8) * DMODEL + c] =
            __floats2half2_rn(o[nj][2] * inv1, o[nj][3] * inv1);
    }
}

// ---------------------------------------------------------------------------
// Fused residual add + LayerNorm; optional fp16 copy of the output.
// ---------------------------------------------------------------------------
template<int WRITEH>
__global__ __launch_bounds__(256)
void add_ln_kernel(const float* __restrict__ x, const float* __restrict__ y,
                   const float* __restrict__ g, const float* __restrict__ beta,
                   float* __restrict__ out, __half* __restrict__ outh)
{
    __shared__ float red_s[8];
    __shared__ float red_ss[8];
    __shared__ float s_mu, s_rstd;

    const int row = blockIdx.x;
    const int tid = threadIdx.x;
    const size_t base = (size_t)row * DMODEL;

    float4 xv = ((const float4*)(x + base))[tid];
    float4 yv = ((const float4*)(y + base))[tid];
    float v0 = xv.x + yv.x, v1 = xv.y + yv.y, v2 = xv.z + yv.z, v3 = xv.w + yv.w;

    float sum = v0 + v1 + v2 + v3;
    float ssq = v0 * v0 + v1 * v1 + v2 * v2 + v3 * v3;
#pragma unroll
    for (int off = 16; off >= 1; off >>= 1) {
        sum += __shfl_down_sync(0xffffffffu, sum, off);
        ssq += __shfl_down_sync(0xffffffffu, ssq, off);
    }
    const int warp = tid >> 5;
    if ((tid & 31) == 0) { red_s[warp] = sum; red_ss[warp] = ssq; }
    __syncthreads();
    if (tid == 0) {
        float ts = 0.f, tss = 0.f;
#pragma unroll
        for (int w = 0; w < 8; ++w) { ts += red_s[w]; tss += red_ss[w]; }
        float mu  = ts / (float)DMODEL;
        float var = tss / (float)DMODEL - mu * mu;
        s_mu = mu;
        s_rstd = rsqrtf(var + LN_EPS);
    }
    __syncthreads();
    const float mu = s_mu, rstd = s_rstd;

    float4 gv = ((const float4*)g)[tid];
    float4 bv = ((const float4*)beta)[tid];
    float4 o;
    o.x = (v0 - mu) * rstd * gv.x + bv.x;
    o.y = (v1 - mu) * rstd * gv.y + bv.y;
    o.z = (v2 - mu) * rstd * gv.z + bv.z;
    o.w = (v3 - mu) * rstd * gv.w + bv.w;
    ((float4*)(out + base))[tid] = o;
    if (WRITEH) {
        __half2 h0 = __floats2half2_rn(o.x, o.y);
        __half2 h1 = __floats2half2_rn(o.z, o.w);
        ((__half2*)(outh + base))[2 * tid]     = h0;
        ((__half2*)(outh + base))[2 * tid + 1] = h1;
    }
}

// ---------------------------------------------------------------------------
// Launcher
// ---------------------------------------------------------------------------
extern "C" void kernel_launch(void* const* d_in, const int* in_sizes, int n_in,
                              void* d_out, int out_size)
{
    (void)in_sizes; (void)n_in; (void)out_size;
    const float* x          = (const float*)d_in[0];
    const int*   positions  = (const int*)  d_in[1];
    const float* Wq         = (const float*)d_in[2];
    const float* bq         = (const float*)d_in[3];
    const float* Wk         = (const float*)d_in[4];
    const float* bk         = (const float*)d_in[5];
    const float* Wv         = (const float*)d_in[6];
    const float* bv         = (const float*)d_in[7];
    const float* Wo         = (const float*)d_in[8];
    const float* bo         = (const float*)d_in[9];
    const float* phase_bias = (const float*)d_in[10];
    const float* freqs      = (const float*)d_in[11];
    const float* W1         = (const float*)d_in[12];
    const float* b1         = (const float*)d_in[13];
    const float* W2         = (const float*)d_in[14];
    const float* b2         = (const float*)d_in[15];
    const float* g1         = (const float*)d_in[16];
    const float* beta1      = (const float*)d_in[17];
    const float* g2         = (const float*)d_in[18];
    const float* beta2      = (const float*)d_in[19];
    float* outp             = (float*)d_out;

    float  *bufA, *bufB, *bufX1, *bqkv;
    __half *xh, *QKVh, *QPh, *KPh, *AttnH, *X1h, *FFh;
    __half *Wcat, *Woh, *W1h, *W2h;
    cudaGetSymbolAddress((void**)&bufA,  g_bufA);
    cudaGetSymbolAddress((void**)&bufB,  g_bufB);
    cudaGetSymbolAddress((void**)&bufX1, g_bufX1);
    cudaGetSymbolAddress((void**)&bqkv,  g_bqkv);
    cudaGetSymbolAddress((void**)&xh,    g_xh);
    cudaGetSymbolAddress((void**)&QKVh,  g_QKVh);
    cudaGetSymbolAddress((void**)&QPh,   g_QPh);
    cudaGetSymbolAddress((void**)&KPh,   g_KPh);
    cudaGetSymbolAddress((void**)&AttnH, g_AttnH);
    cudaGetSymbolAddress((void**)&X1h,   g_X1h);
    cudaGetSymbolAddress((void**)&FFh,   g_FFh);
    cudaGetSymbolAddress((void**)&Wcat,  g_Wcat);
    cudaGetSymbolAddress((void**)&Woh,   g_Woh);
    cudaGetSymbolAddress((void**)&W1h,   g_W1h);
    cudaGetSymbolAddress((void**)&W2h,   g_W2h);

    cudaFuncSetAttribute(attn_h_kernel, cudaFuncAttributeMaxDynamicSharedMemorySize,
                         AT_SMEM_BYTES);
    cudaFuncSetAttribute(hgemm_kernel<0,0>, cudaFuncAttributeMaxDynamicSharedMemorySize,
                         HG_SMEM_BYTES);
    cudaFuncSetAttribute(hgemm_kernel<0,1>, cudaFuncAttributeMaxDynamicSharedMemorySize,
                         HG_SMEM_BYTES);
    cudaFuncSetAttribute(hgemm_kernel<1,1>, cudaFuncAttributeMaxDynamicSharedMemorySize,
                         HG_SMEM_BYTES);

    // 0a: x -> fp16
    f2h_kernel<<<(BS * DMODEL / 8 + 255) / 256, 256>>>(x, xh, BS * DMODEL);

    // 0b: ALL weight conversions + bias concat in one launch
    {
        dim3 grid(DFF * DMODEL / 8 / 256, 7);    // 2048 x 7 (largest weight bounds)
        f2h_weights_kernel<<<grid, 256>>>(Wq, Wk, Wv, Wo, W1, W2, bq, bk, bv,
                                          Wcat, Woh, W1h, W2h, bqkv);
    }

    // 1: fused QKV projection (N=3072), fp16 out
    {
        dim3 grid(QKVN / 128, BS / 128);
        hgemm_kernel<0,1><<<grid, 256, HG_SMEM_BYTES>>>(xh, Wcat, bqkv, QKVh, BS, QKVN, DMODEL);
    }

    // 2: PoPE (fp16 in/out)
    {
        int total = BATCH * NHEADS * SEQ * 32;
        pope_kernel<<<(total + 255) / 256, 256>>>(QKVh, positions, freqs,
                                                  phase_bias, QPh, KPh);
    }

    // 3: attention -> fp16
    {
        dim3 grid(SEQ / 128, NHEADS, BATCH);
        attn_h_kernel<<<grid, 256, AT_SMEM_BYTES>>>(QPh, KPh, QKVh, AttnH);
    }

    // 4: output projection -> fp32
    {
        dim3 grid(DMODEL / 128, BS / 128);
        hgemm_kernel<0,0><<<grid, 256, HG_SMEM_BYTES>>>(AttnH, Woh, bo, bufA, BS, DMODEL, DMODEL);
    }

    // 5: residual + LN1 -> fp32 + fp16
    add_ln_kernel<1><<<BS, 256>>>(x, bufA, g1, beta1, bufX1, X1h);

    // 6: FFN up + ReLU -> fp16
    {
        dim3 grid(DFF / 128, BS / 128);
        hgemm_kernel<1,1><<<grid, 256, HG_SMEM_BYTES>>>(X1h, W1h, b1, FFh, BS, DFF, DMODEL);
    }

    // 7: FFN down -> fp32
    {
        dim3 grid(DMODEL / 128, BS / 128);
        hgemm_kernel<0,0><<<grid, 256, HG_SMEM_BYTES>>>(FFh, W2h, b2, bufB, BS, DMODEL, DFF);
    }

    // 8: residual + LN2 -> output
    add_ln_kernel<0><<<BS, 256>>>(bufX1, bufB, g2, beta2, outp, nullptr);
}

// round 14
// speedup vs baseline: 1.1477x; 1.0157x over previous
#include <cuda_runtime.h>
#include <cuda_fp16.h>
#include <math.h>
#include <stdint.h>

// ---------------------------------------------------------------------------
// Problem constants
// ---------------------------------------------------------------------------
#define BATCH   2
#define SEQ     2048
#define DMODEL  1024
#define NHEADS  16
#define HEADDIM 64
#define DFF     4096
#define BS      (BATCH * SEQ)          // 4096 rows
#define LN_EPS  1e-5f
#define ATTN_SCALE 0.08838834764831845f   // 1/sqrt(128)
#define QKVN    (3 * DMODEL)           // fused QKV width

// ---------------------------------------------------------------------------
// Scratch buffers
// ---------------------------------------------------------------------------
__device__ float  g_bufA   [BS * DMODEL];            // Wo out (fp32)
__device__ float  g_bufB   [BS * DMODEL];            // FFN2 out (fp32)
__device__ float  g_bufX1  [BS * DMODEL];            // LN1 out fp32
__device__ __half g_xh     [BS * DMODEL];            // x in fp16
__device__ __half g_QKVh   [BS * QKVN];              // fused QKV output fp16
__device__ __half g_QPh    [BATCH * NHEADS * SEQ * 2 * HEADDIM];
__device__ __half g_KPh    [BATCH * NHEADS * SEQ * 2 * HEADDIM];
__device__ __half g_AttnH  [BS * DMODEL];            // attention out fp16
__device__ __half g_X1h    [BS * DMODEL];            // LN1 out fp16
__device__ __half g_FFh    [BS * DFF];               // FFN hidden fp16

// fp16 weights in NATIVE [K][N] layout (no transpose needed: ldmatrix.trans)
__device__ __half g_Wcat[DMODEL * QKVN];             // cols: Wq | Wk | Wv
__device__ float  g_bqkv[QKVN];
__device__ __half g_Woh[DMODEL * DMODEL];
__device__ __half g_W1h[DMODEL * DFF];
__device__ __half g_W2h[DFF * DMODEL];

// ---------------------------------------------------------------------------
// Helpers
// ---------------------------------------------------------------------------
__device__ __forceinline__ uint32_t smem_u32(const void* p) {
    uint32_t a;
    asm("{ .reg .u64 t; cvta.to.shared.u64 t, %1; cvt.u32.u64 %0, t; }"
        : "=r"(a) : "l"(p));
    return a;
}

__device__ __forceinline__ void cp_async16(uint32_t saddr, const void* gptr) {
    asm volatile("cp.async.cg.shared.global [%0], [%1], 16;"
                 :: "r"(saddr), "l"(gptr) : "memory");
}

// fp16 mma m16n8k16, fp32 accumulate
__device__ __forceinline__ void mma_f16(float (&d)[4],
                                        const uint32_t (&a)[4],
                                        uint32_t b0, uint32_t b1)
{
    asm volatile(
        "mma.sync.aligned.m16n8k16.row.col.f32.f16.f16.f32 "
        "{%0,%1,%2,%3}, {%4,%5,%6,%7}, {%8,%9}, {%0,%1,%2,%3};"
        : "+f"(d[0]), "+f"(d[1]), "+f"(d[2]), "+f"(d[3])
        : "r"(a[0]), "r"(a[1]), "r"(a[2]), "r"(a[3]), "r"(b0), "r"(b1));
}

__device__ __forceinline__ void ldsm_x4(uint32_t (&r)[4], uint32_t saddr) {
    asm volatile("ldmatrix.sync.aligned.m8n8.x4.shared.b16 {%0,%1,%2,%3}, [%4];"
                 : "=r"(r[0]), "=r"(r[1]), "=r"(r[2]), "=r"(r[3]) : "r"(saddr));
}

__device__ __forceinline__ void ldsm_x4_t(uint32_t (&r)[4], uint32_t saddr) {
    asm volatile("ldmatrix.sync.aligned.m8n8.x4.trans.shared.b16 {%0,%1,%2,%3}, [%4];"
                 : "=r"(r[0]), "=r"(r[1]), "=r"(r[2]), "=r"(r[3]) : "r"(saddr));
}

// Fast exp via MUFU.EX2 (args are <= 0 here; ex2.approx(-inf) = 0)
__device__ __forceinline__ float fexpf(float x) {
    float y = x * 1.4426950408889634f;
    float r;
    asm("ex2.approx.f32 %0, %1;" : "=f"(r) : "f"(y));
    return r;
}

__device__ __forceinline__ float fex2(float x) {
    float r; asm("ex2.approx.f32 %0, %1;" : "=f"(r) : "f"(x)); return r;
}
__device__ __forceinline__ float flg2(float x) {
    float r; asm("lg2.approx.f32 %0, %1;" : "=f"(r) : "f"(x)); return r;
}
__device__ __forceinline__ float fsin(float x) {
    float r; asm("sin.approx.f32 %0, %1;" : "=f"(r) : "f"(x)); return r;
}
__device__ __forceinline__ float fcos(float x) {
    float r; asm("cos.approx.f32 %0, %1;" : "=f"(r) : "f"(x)); return r;
}

// Fast softplus: max(x,0) + ln2 * lg2(1 + 2^(-|x|*log2e))
__device__ __forceinline__ float fsoftplus(float x) {
    float t = fex2(-fabsf(x) * 1.4426950408889634f);
    return fmaxf(x, 0.f) + 0.6931471805599453f * flg2(1.f + t);
}

// Fast sincos with Cody-Waite range reduction (|ph| < ~2100, n <= ~340).
__device__ __forceinline__ void fsincos(float ph, float* s, float* c) {
    float n = rintf(ph * 0.15915494309189535f);       // ph / 2pi
    float r = fmaf(n, -6.28125f, ph);                 // 2pi hi (exact products)
    r = fmaf(n, -1.9353071795864769e-3f, r);          // 2pi lo
    *s = fsin(r);
    *c = fcos(r);
}

// ---------------------------------------------------------------------------
// ALL conversions in ONE launch. grid.y selects item:
//   0..2: Wq/Wk/Wv -> Wcat (column-concat) 3: Wo, 4: W1, 5: W2, 6: bias, 7: x
// ---------------------------------------------------------------------------
__global__ __launch_bounds__(256)
void f2h_weights_kernel(const float* __restrict__ Wq, const float* __restrict__ Wk,
                        const float* __restrict__ Wv, const float* __restrict__ Wo,
                        const float* __restrict__ W1, const float* __restrict__ W2,
                        const float* __restrict__ bq, const float* __restrict__ bk,
                        const float* __restrict__ bv, const float* __restrict__ x,
                        __half* __restrict__ Wcat, __half* __restrict__ Woh,
                        __half* __restrict__ W1h, __half* __restrict__ W2h,
                        float* __restrict__ bqkv, __half* __restrict__ xh)
{
    const int id  = blockIdx.y;
    const int idx = blockIdx.x * 256 + threadIdx.x;   // chunk of 8 elems

    if (id == 6) {
        if (idx >= QKVN) return;
        float v = (idx < DMODEL) ? bq[idx]
                : (idx < 2 * DMODEL) ? bk[idx - DMODEL] : bv[idx - 2 * DMODEL];
        bqkv[idx] = v;
        return;
    }

    const float* src;
    __half* dst;
    int nchunks;
    if (id < 3)      { src = (id == 0) ? Wq : (id == 1) ? Wk : Wv;
                       dst = Wcat; nchunks = DMODEL * DMODEL / 8; }
    else if (id == 3){ src = Wo; dst = Woh; nchunks = DMODEL * DMODEL / 8; }
    else if (id == 4){ src = W1; dst = W1h; nchunks = DMODEL * DFF / 8; }
    else if (id == 5){ src = W2; dst = W2h; nchunks = DFF * DMODEL / 8; }
    else             { src = x;  dst = xh;  nchunks = BS * DMODEL / 8; }
    if (idx >= nchunks) return;

    float4 a = *(const float4*)(src + idx * 8);
    float4 b = *(const float4*)(src + idx * 8 + 4);
    __half2 h[4];
    h[0] = __floats2half2_rn(a.x, a.y);
    h[1] = __floats2half2_rn(a.z, a.w);
    h[2] = __floats2half2_rn(b.x, b.y);
    h[3] = __floats2half2_rn(b.z, b.w);

    if (id < 3) {
        int r = idx >> 7;            // 128 chunks per 1024-wide row
        int c = idx & 127;
        *(uint4*)(dst + (size_t)r * QKVN + id * DMODEL + c * 8) = *(uint4*)h;
    } else {
        *(uint4*)(dst + (size_t)idx * 8) = *(uint4*)h;
    }
}

// ---------------------------------------------------------------------------
// fp16 mma GEMM: C(MxN) = A(MxK) @ W(KxN) + bias. W in NATIVE [K][N] layout;
// B fragments via ldmatrix.trans. 128x128x32 tiles, 8 warps, 5-stage cp.async
// pipeline, one sync per K-iter, 2 CTAs/SM.
// ---------------------------------------------------------------------------
#define HG_STRIDE 40          // A tile stride (halves)
#define HG_BS     136         // B tile stride (halves), 32 rows x 128 cols
#define HG_STAGES 5
#define HG_A_HALVES (128 * HG_STRIDE)
#define HG_B_HALVES (32 * HG_BS)
#define HG_STAGE_HALVES (HG_A_HALVES + HG_B_HALVES)       // 9472
#define HG_SMEM_BYTES (HG_STAGES * HG_STAGE_HALVES * 2)   // 94720 B

template<int RELU, int HALFOUT>
__global__ __launch_bounds__(256, 2)
void hgemm_kernel(const __half* __restrict__ A, const __half* __restrict__ W,
                  const float* __restrict__ bias, void* __restrict__ Cv,
                  int M, int N, int K)
{
    extern __shared__ __half hsm[];

    const int tid  = threadIdx.x;
    const int lane = tid & 31, wid = tid >> 5;
    const int wm = wid >> 1, wn = wid & 1;
    const int grp = lane >> 2, tig = lane & 3;
    const int m0 = blockIdx.y * 128, n0 = blockIdx.x * 128;

    const uint32_t smbase = smem_u32(hsm);

    const int l8  = lane & 7;
    const int q01 = (lane >> 3) & 1;
    const int q23 = lane >> 4;

    float acc[2][8][4];
#pragma unroll
    for (int mi = 0; mi < 2; ++mi)
#pragma unroll
        for (int nj = 0; nj < 8; ++nj)
#pragma unroll
            for (int r = 0; r < 4; ++r) acc[mi][nj][r] = 0.f;

    auto load_tiles = [&](int stage, int k0) {
        uint32_t ab = smbase + stage * HG_STAGE_HALVES * 2;
        uint32_t bb = ab + HG_A_HALVES * 2;
#pragma unroll
        for (int i = 0; i < 2; ++i) {
            int idx = tid + i * 256;
            int r = idx >> 2, c = idx & 3;
            cp_async16(ab + (uint32_t)(r * HG_STRIDE + c * 8) * 2,
                       A + (size_t)(m0 + r) * K + k0 + c * 8);
        }
#pragma unroll
        for (int i = 0; i < 2; ++i) {
            int idx = tid + i * 256;
            int r = idx >> 4, c = idx & 15;
            cp_async16(bb + (uint32_t)(r * HG_BS + c * 8) * 2,
                       W + (size_t)(k0 + r) * N + n0 + c * 8);
        }
    };

    const int nIt = K / 32;
#pragma unroll
    for (int s = 0; s < HG_STAGES - 1; ++s) {
        load_tiles(s, s * 32);
        asm volatile("cp.async.commit_group;" ::: "memory");
    }

    int st = 0, lst = HG_STAGES - 1;
    for (int it = 0; it < nIt; ++it) {
        asm volatile("cp.async.wait_group 3;" ::: "memory");
        __syncthreads();
        if (it + HG_STAGES - 1 < nIt) {
            load_tiles(lst, (it + HG_STAGES - 1) * 32);
            asm volatile("cp.async.commit_group;" ::: "memory");
            lst = (lst == HG_STAGES - 1) ? 0 : lst + 1;
        }

        const uint32_t abase = smbase + st * HG_STAGE_HALVES * 2;
        const uint32_t bbase = abase + HG_A_HALVES * 2;
        st = (st == HG_STAGES - 1) ? 0 : st + 1;

#pragma unroll
        for (int kk = 0; kk < 2; ++kk) {
            const int k = kk * 16;
            uint32_t af[2][4];
#pragma unroll
            for (int mi = 0; mi < 2; ++mi) {
                int row = wm * 32 + mi * 16 + q01 * 8 + l8;
                int col = k + q23 * 8;
                ldsm_x4(af[mi], abase + (uint32_t)(row * HG_STRIDE + col) * 2);
            }
#pragma unroll
            for (int g = 0; g < 4; ++g) {
                uint32_t bf[4];
                int row = k + q01 * 8 + l8;                 // k index
                int col = wn * 64 + g * 16 + q23 * 8;       // n index
                ldsm_x4_t(bf, bbase + (uint32_t)(row * HG_BS + col) * 2);
#pragma unroll
                for (int h2 = 0; h2 < 2; ++h2)
#pragma unroll
                    for (int mi = 0; mi < 2; ++mi)
                        mma_f16(acc[mi][g * 2 + h2], af[mi], bf[h2 * 2], bf[h2 * 2 + 1]);
            }
        }
    }

#pragma unroll
    for (int mi = 0; mi < 2; ++mi) {
        int r = m0 + wm * 32 + mi * 16 + grp;
#pragma unroll
        for (int nj = 0; nj < 8; ++nj) {
            int c = n0 + wn * 64 + nj * 8 + tig * 2;
            float bb0 = bias[c], bb1 = bias[c + 1];
            float v0 = acc[mi][nj][0] + bb0;
            float v1 = acc[mi][nj][1] + bb1;
            float v2 = acc[mi][nj][2] + bb0;
            float v3 = acc[mi][nj][3] + bb1;
            if (RELU) {
                v0 = fmaxf(v0, 0.f); v1 = fmaxf(v1, 0.f);
                v2 = fmaxf(v2, 0.f); v3 = fmaxf(v3, 0.f);
            }
            if (HALFOUT) {
                __half* C = (__half*)Cv;
                *(__half2*)&C[(size_t)r * N + c]       = __floats2half2_rn(v0, v1);
                *(__half2*)&C[(size_t)(r + 8) * N + c] = __floats2half2_rn(v2, v3);
            } else {
                float* C = (float*)Cv;
                float2 lo; lo.x = v0; lo.y = v1;
                float2 hi; hi.x = v2; hi.y = v3;
                *(float2*)&C[(size_t)r * N + c]       = lo;
                *(float2*)&C[(size_t)(r + 8) * N + c] = hi;
            }
        }
    }
}

// ---------------------------------------------------------------------------
// PoPE transform: fast MUFU math (range-reduced sin/cos, ex2/lg2 softplus).
// ---------------------------------------------------------------------------
__global__ void pope_kernel(const __half* __restrict__ qkv,
                            const int* __restrict__ positions,
                            const float* __restrict__ freqs,
                            const float* __restrict__ phase_bias,
                            __half* __restrict__ qp, __half* __restrict__ kp)
{
    int idx = blockIdx.x * blockDim.x + threadIdx.x;   // B*H*S*32
    if (idx >= BATCH * NHEADS * SEQ * 32) return;
    int d = (idx & 31) * 2;
    int s = (idx >> 5) & (SEQ - 1);
    int h = (idx >> 16) & (NHEADS - 1);
    int b = idx >> 20;

    size_t rowb = (size_t)(b * SEQ + s) * QKVN + h * HEADDIM + d;
    float2 qv = __half22float2(*(const __half2*)&qkv[rowb]);
    float2 kv = __half22float2(*(const __half2*)&qkv[rowb + DMODEL]);

    float pos = (float)positions[s];
    float ph0 = fmaf(pos, freqs[d],     phase_bias[h * HEADDIM + d]);
    float ph1 = fmaf(pos, freqs[d + 1], phase_bias[h * HEADDIM + d + 1]);
    float c0, s0, c1, s1;
    fsincos(ph0, &s0, &c0);
    fsincos(ph1, &s1, &c1);

    float mq0 = fsoftplus(qv.x) * ATTN_SCALE, mq1 = fsoftplus(qv.y) * ATTN_SCALE;
    float mk0 = fsoftplus(kv.x),              mk1 = fsoftplus(kv.y);

    size_t base = (((size_t)(b * NHEADS + h) * SEQ) + s) * 128 + d;
    *(__half2*)&qp[base]      = __floats2half2_rn(mq0 * c0, mq1 * c1);
    *(__half2*)&qp[base + 64] = __floats2half2_rn(mq0 * s0, mq1 * s1);
    *(__half2*)&kp[base]      = __floats2half2_rn(mk0 * c0, mk1 * c1);
    *(__half2*)&kp[base + 64] = __floats2half2_rn(mk0 * s0, mk1 * s1);
}

// ---------------------------------------------------------------------------
// Flash attention with softmax1, fp16 mma + ldmatrix. 2 CTAs/SM.
// Double-buffered cp.async K/V, one sync per tile; softmax via MUFU.EX2.
// ---------------------------------------------------------------------------
#define AT_QS 136
#define AT_PS 72
#define AT_KS 136
#define AT_VS 72
#define AT_Q_HALVES (128 * AT_QS)             // aliased by Ps (128 x 72)
#define AT_K_STAGE  (64 * AT_KS)
#define AT_V_STAGE  (64 * AT_VS)
#define AT_SMEM_HALVES (AT_Q_HALVES + 2 * AT_K_STAGE + 2 * AT_V_STAGE)
#define AT_SMEM_BYTES  (AT_SMEM_HALVES * 2)   // 88064 B

__global__ __launch_bounds__(256, 2)
void attn_h_kernel(const __half* __restrict__ qp, const __half* __restrict__ kp,
                   const __half* __restrict__ qkv, __half* __restrict__ out)
{
    extern __shared__ __half hsm[];
    __half* Qs = hsm;                           // 128 x 136 (staging)
    __half* Ps = hsm;                           // 128 x 72 (aliases Qs)

    const int b = blockIdx.z;
    const int h = blockIdx.y;
    const int qtile = gridDim.x - 1 - blockIdx.x;   // heavy tiles first
    const int q0 = qtile * 128;

    const int tid  = threadIdx.x;
    const int lane = tid & 31, wid = tid >> 5;
    const int grp = lane >> 2, tig = lane & 3;
    const int r0 = wid * 16 + grp;

    const int l8  = lane & 7;
    const int q01 = (lane >> 3) & 1;
    const int q23 = lane >> 4;

    const uint32_t smbase = smem_u32(hsm);
    const uint32_t pssm  = smbase;                               // Ps
    const uint32_t kssm0 = smbase + AT_Q_HALVES * 2;             // K stage 0
    const uint32_t vssm0 = kssm0 + 2 * AT_K_STAGE * 2;           // V stage 0

    const __half* qbase = qp + (((size_t)(b * NHEADS + h)) * SEQ) * 128;
    const __half* kbase = kp + (((size_t)(b * NHEADS + h)) * SEQ) * 128;
    const __half* vbase = qkv + 2 * DMODEL + h * HEADDIM;        // V cols in fused buffer

    auto load_kv = [&](int stage, int kt) {
        uint32_t kb = kssm0 + stage * AT_K_STAGE * 2;
#pragma unroll
        for (int i = 0; i < 4; ++i) {
            int idx = tid + i * 256;
            int r = idx >> 4, c = idx & 15;
            cp_async16(kb + (uint32_t)(r * AT_KS + c * 8) * 2,
                       kbase + (size_t)(kt + r) * 128 + c * 8);
        }
        uint32_t vb = vssm0 + stage * AT_V_STAGE * 2;
#pragma unroll
        for (int i = 0; i < 2; ++i) {
            int idx = tid + i * 256;
            int r = idx >> 3, c = idx & 7;
            cp_async16(vb + (uint32_t)(r * AT_VS + c * 8) * 2,
                       vbase + ((size_t)b * SEQ + kt + r) * QKVN + c * 8);
        }
    };

    // Prologue: start K/V tile 0 fetch, then stage Q.
    load_kv(0, 0);
    asm volatile("cp.async.commit_group;" ::: "memory");

    for (int i = tid; i < 2048; i += 256) {
        int r = i >> 4, c = i & 15;
        *(uint4*)&Qs[r * AT_QS + c * 8] =
            *(const uint4*)&qbase[(size_t)(q0 + r) * 128 + c * 8];
    }
    __syncthreads();

    // Preload Q fragments via ldmatrix: 8 k16 chunks
    uint32_t qf[8][4];
    {
        int row = wid * 16 + q01 * 8 + l8;
#pragma unroll
        for (int kk = 0; kk < 8; ++kk) {
            int col = kk * 16 + q23 * 8;
            ldsm_x4(qf[kk], smbase + (uint32_t)(row * AT_QS + col) * 2);
        }
    }
    __syncthreads();   // done reading Qs before Ps overwrites

    float m0 = -INFINITY, m1 = -INFINITY, l0 = 0.f, l1 = 0.f;
    float o[8][4];
#pragma unroll
    for (int nj = 0; nj < 8; ++nj)
#pragma unroll
        for (int r = 0; r < 4; ++r) o[nj][r] = 0.f;

    const int nT = q0 / 64 + 2;
    for (int t = 0; t < nT; ++t) {
        const int kt = t * 64;
        asm volatile("cp.async.wait_group 0;" ::: "memory");
        __syncthreads();
        if (t + 1 < nT) {
            load_kv((t + 1) & 1, (t + 1) * 64);
            asm volatile("cp.async.commit_group;" ::: "memory");
        }
        const uint32_t kst = kssm0 + (t & 1) * AT_K_STAGE * 2;
        const uint32_t vst = vssm0 + (t & 1) * AT_V_STAGE * 2;

        // scores = Q @ K^T
        float sacc[8][4];
#pragma unroll
        for (int nj = 0; nj < 8; ++nj)
#pragma unroll
            for (int r = 0; r < 4; ++r) sacc[nj][r] = 0.f;

#pragma unroll
        for (int kk = 0; kk < 8; ++kk) {
            int k = kk * 16;
#pragma unroll
            for (int g = 0; g < 4; ++g) {
                uint32_t bf[4];
                int row = g * 16 + q23 * 8 + l8;
                int col = k + q01 * 8;
                ldsm_x4(bf, kst + (uint32_t)(row * AT_KS + col) * 2);
                mma_f16(sacc[g * 2 + 0], qf[kk], bf[0], bf[1]);
                mma_f16(sacc[g * 2 + 1], qf[kk], bf[2], bf[3]);
            }
        }

        // causal mask (last two key tiles only)
        if (kt >= q0) {
            int row0 = q0 + r0, row1 = row0 + 8;
#pragma unroll
            for (int nj = 0; nj < 8; ++nj) {
                int c = kt + nj * 8 + 2 * tig;
                if (c     > row0) sacc[nj][0] = -INFINITY;
                if (c + 1 > row0) sacc[nj][1] = -INFINITY;
                if (c     > row1) sacc[nj][2] = -INFINITY;
                if (c + 1 > row1) sacc[nj][3] = -INFINITY;
            }
        }

        // online softmax1 (fast ex2)
        float mx0 = -INFINITY, mx1 = -INFINITY;
#pragma unroll
        for (int nj = 0; nj < 8; ++nj) {
            mx0 = fmaxf(mx0, fmaxf(sacc[nj][0], sacc[nj][1]));
            mx1 = fmaxf(mx1, fmaxf(sacc[nj][2], sacc[nj][3]));
        }
        mx0 = fmaxf(mx0, __shfl_xor_sync(0xffffffffu, mx0, 1));
        mx0 = fmaxf(mx0, __shfl_xor_sync(0xffffffffu, mx0, 2));
        mx1 = fmaxf(mx1, __shfl_xor_sync(0xffffffffu, mx1, 1));
        mx1 = fmaxf(mx1, __shfl_xor_sync(0xffffffffu, mx1, 2));

        float m0n = fmaxf(m0, mx0), m1n = fmaxf(m1, mx1);
        float c0 = fexpf(m0 - m0n),  c1 = fexpf(m1 - m1n);
        m0 = m0n; m1 = m1n;

        float ls0 = 0.f, ls1 = 0.f;
#pragma unroll
        for (int nj = 0; nj < 8; ++nj) {
            float p0 = fexpf(sacc[nj][0] - m0n);
            float p1 = fexpf(sacc[nj][1] - m0n);
            float p2 = fexpf(sacc[nj][2] - m1n);
            float p3 = fexpf(sacc[nj][3] - m1n);
            ls0 += p0 + p1; ls1 += p2 + p3;
            *(__half2*)&Ps[r0       * AT_PS + nj * 8 + 2 * tig] = __floats2half2_rn(p0, p1);
            *(__half2*)&Ps[(r0 + 8) * AT_PS + nj * 8 + 2 * tig] = __floats2half2_rn(p2, p3);
        }
        ls0 += __shfl_xor_sync(0xffffffffu, ls0, 1);
        ls0 += __shfl_xor_sync(0xffffffffu, ls0, 2);
        ls1 += __shfl_xor_sync(0xffffffffu, ls1, 1);
        ls1 += __shfl_xor_sync(0xffffffffu, ls1, 2);
        l0 = l0 * c0 + ls0;
        l1 = l1 * c1 + ls1;

#pragma unroll
        for (int nj = 0; nj < 8; ++nj) {
            o[nj][0] *= c0; o[nj][1] *= c0;
            o[nj][2] *= c1; o[nj][3] *= c1;
        }
        __syncwarp();

        // O += P @ V (V row-major [key][dim]; B fragments via ldmatrix.trans)
#pragma unroll
        for (int kk = 0; kk < 4; ++kk) {
            int k = kk * 16;
            uint32_t af[4];
            {
                int row = wid * 16 + q01 * 8 + l8;
                int col = k + q23 * 8;
                ldsm_x4(af, pssm + (uint32_t)(row * AT_PS + col) * 2);
            }
#pragma unroll
            for (int g = 0; g < 4; ++g) {
                uint32_t bf[4];
                int row = k + q01 * 8 + l8;          // key index
                int col = g * 16 + q23 * 8;          // dim index
                ldsm_x4_t(bf, vst + (uint32_t)(row * AT_VS + col) * 2);
                mma_f16(o[g * 2 + 0], af, bf[0], bf[1]);
                mma_f16(o[g * 2 + 1], af, bf[2], bf[3]);
            }
        }
    }

    // epilogue: softmax1 denominator; write fp16 (B,S,D)
    float inv0 = 1.f / (1.f + l0);
    float inv1 = 1.f / (1.f + l1);
    int row0 = q0 + r0;
#pragma unroll
    for (int nj = 0; nj < 8; ++nj) {
        int c = h * HEADDIM + nj * 8 + 2 * tig;
        *(__half2*)&out[((size_t)b * SEQ + row0)     * DMODEL + c] =
            __floats2half2_rn(o[nj][0] * inv0, o[nj][1] * inv0);
        *(__half2*)&out[((size_t)b * SEQ + row0 + 8) * DMODEL + c] =
            __floats2half2_rn(o[nj][2] * inv1, o[nj][3] * inv1);
    }
}

// ---------------------------------------------------------------------------
// Fused residual add + LayerNorm; optional fp16 copy of the output.
// ---------------------------------------------------------------------------
template<int WRITEH>
__global__ __launch_bounds__(256)
void add_ln_kernel(const float* __restrict__ x, const float* __restrict__ y,
                   const float* __restrict__ g, const float* __restrict__ beta,
                   float* __restrict__ out, __half* __restrict__ outh)
{
    __shared__ float red_s[8];
    __shared__ float red_ss[8];
    __shared__ float s_mu, s_rstd;

    const int row = blockIdx.x;
    const int tid = threadIdx.x;
    const size_t base = (size_t)row * DMODEL;

    float4 xv = ((const float4*)(x + base))[tid];
    float4 yv = ((const float4*)(y + base))[tid];
    float v0 = xv.x + yv.x, v1 = xv.y + yv.y, v2 = xv.z + yv.z, v3 = xv.w + yv.w;

    float sum = v0 + v1 + v2 + v3;
    float ssq = v0 * v0 + v1 * v1 + v2 * v2 + v3 * v3;
#pragma unroll
    for (int off = 16; off >= 1; off >>= 1) {
        sum += __shfl_down_sync(0xffffffffu, sum, off);
        ssq += __shfl_down_sync(0xffffffffu, ssq, off);
    }
    const int warp = tid >> 5;
    if ((tid & 31) == 0) { red_s[warp] = sum; red_ss[warp] = ssq; }
    __syncthreads();
    if (tid == 0) {
        float ts = 0.f, tss = 0.f;
#pragma unroll
        for (int w = 0; w < 8; ++w) { ts += red_s[w]; tss += red_ss[w]; }
        float mu  = ts / (float)DMODEL;
        float var = tss / (float)DMODEL - mu * mu;
        s_mu = mu;
        s_rstd = rsqrtf(var + LN_EPS);
    }
    __syncthreads();
    const float mu = s_mu, rstd = s_rstd;

    float4 gv = ((const float4*)g)[tid];
    float4 bv = ((const float4*)beta)[tid];
    float4 o;
    o.x = (v0 - mu) * rstd * gv.x + bv.x;
    o.y = (v1 - mu) * rstd * gv.y + bv.y;
    o.z = (v2 - mu) * rstd * gv.z + bv.z;
    o.w = (v3 - mu) * rstd * gv.w + bv.w;
    ((float4*)(out + base))[tid] = o;
    if (WRITEH) {
        __half2 h0 = __floats2half2_rn(o.x, o.y);
        __half2 h1 = __floats2half2_rn(o.z, o.w);
        ((__half2*)(outh + base))[2 * tid]     = h0;
        ((__half2*)(outh + base))[2 * tid + 1] = h1;
    }
}

// ---------------------------------------------------------------------------
// Launcher
// ---------------------------------------------------------------------------
extern "C" void kernel_launch(void* const* d_in, const int* in_sizes, int n_in,
                              void* d_out, int out_size)
{
    (void)in_sizes; (void)n_in; (void)out_size;
    const float* x          = (const float*)d_in[0];
    const int*   positions  = (const int*)  d_in[1];
    const float* Wq         = (const float*)d_in[2];
    const float* bq         = (const float*)d_in[3];
    const float* Wk         = (const float*)d_in[4];
    const float* bk         = (const float*)d_in[5];
    const float* Wv         = (const float*)d_in[6];
    const float* bv         = (const float*)d_in[7];
    const float* Wo         = (const float*)d_in[8];
    const float* bo         = (const float*)d_in[9];
    const float* phase_bias = (const float*)d_in[10];
    const float* freqs      = (const float*)d_in[11];
    const float* W1         = (const float*)d_in[12];
    const float* b1         = (const float*)d_in[13];
    const float* W2         = (const float*)d_in[14];
    const float* b2         = (const float*)d_in[15];
    const float* g1         = (const float*)d_in[16];
    const float* beta1      = (const float*)d_in[17];
    const float* g2         = (const float*)d_in[18];
    const float* beta2      = (const float*)d_in[19];
    float* outp             = (float*)d_out;

    float  *bufA, *bufB, *bufX1, *bqkv;
    __half *xh, *QKVh, *QPh, *KPh, *AttnH, *X1h, *FFh;
    __half *Wcat, *Woh, *W1h, *W2h;
    cudaGetSymbolAddress((void**)&bufA,  g_bufA);
    cudaGetSymbolAddress((void**)&bufB,  g_bufB);
    cudaGetSymbolAddress((void**)&bufX1, g_bufX1);
    cudaGetSymbolAddress((void**)&bqkv,  g_bqkv);
    cudaGetSymbolAddress((void**)&xh,    g_xh);
    cudaGetSymbolAddress((void**)&QKVh,  g_QKVh);
    cudaGetSymbolAddress((void**)&QPh,   g_QPh);
    cudaGetSymbolAddress((void**)&KPh,   g_KPh);
    cudaGetSymbolAddress((void**)&AttnH, g_AttnH);
    cudaGetSymbolAddress((void**)&X1h,   g_X1h);
    cudaGetSymbolAddress((void**)&FFh,   g_FFh);
    cudaGetSymbolAddress((void**)&Wcat,  g_Wcat);
    cudaGetSymbolAddress((void**)&Woh,   g_Woh);
    cudaGetSymbolAddress((void**)&W1h,   g_W1h);
    cudaGetSymbolAddress((void**)&W2h,   g_W2h);

    cudaFuncSetAttribute(attn_h_kernel, cudaFuncAttributeMaxDynamicSharedMemorySize,
                         AT_SMEM_BYTES);
    cudaFuncSetAttribute(hgemm_kernel<0,0>, cudaFuncAttributeMaxDynamicSharedMemorySize,
                         HG_SMEM_BYTES);
    cudaFuncSetAttribute(hgemm_kernel<0,1>, cudaFuncAttributeMaxDynamicSharedMemorySize,
                         HG_SMEM_BYTES);
    cudaFuncSetAttribute(hgemm_kernel<1,1>, cudaFuncAttributeMaxDynamicSharedMemorySize,
                         HG_SMEM_BYTES);

    // 0: ALL conversions (weights + bias + x) in one launch
    {
        dim3 grid(DFF * DMODEL / 8 / 256, 8);    // 2048 x 8
        f2h_weights_kernel<<<grid, 256>>>(Wq, Wk, Wv, Wo, W1, W2, bq, bk, bv, x,
                                          Wcat, Woh, W1h, W2h, bqkv, xh);
    }

    // 1: fused QKV projection (N=3072), fp16 out
    {
        dim3 grid(QKVN / 128, BS / 128);
        hgemm_kernel<0,1><<<grid, 256, HG_SMEM_BYTES>>>(xh, Wcat, bqkv, QKVh, BS, QKVN, DMODEL);
    }

    // 2: PoPE (fp16 in/out, fast MUFU math)
    {
        int total = BATCH * NHEADS * SEQ * 32;
        pope_kernel<<<(total + 255) / 256, 256>>>(QKVh, positions, freqs,
                                                  phase_bias, QPh, KPh);
    }

    // 3: attention -> fp16
    {
        dim3 grid(SEQ / 128, NHEADS, BATCH);
        attn_h_kernel<<<grid, 256, AT_SMEM_BYTES>>>(QPh, KPh, QKVh, AttnH);
    }

    // 4: output projection -> fp32
    {
        dim3 grid(DMODEL / 128, BS / 128);
        hgemm_kernel<0,0><<<grid, 256, HG_SMEM_BYTES>>>(AttnH, Woh, bo, bufA, BS, DMODEL, DMODEL);
    }

    // 5: residual + LN1 -> fp32 + fp16
    add_ln_kernel<1><<<BS, 256>>>(x, bufA, g1, beta1, bufX1, X1h);

    // 6: FFN up + ReLU -> fp16
    {
        dim3 grid(DFF / 128, BS / 128);
        hgemm_kernel<1,1><<<grid, 256, HG_SMEM_BYTES>>>(X1h, W1h, b1, FFh, BS, DFF, DMODEL);
    }

    // 7: FFN down -> fp32
    {
        dim3 grid(DMODEL / 128, BS / 128);
        hgemm_kernel<0,0><<<grid, 256, HG_SMEM_BYTES>>>(FFh, W2h, b2, bufB, BS, DMODEL, DFF);
    }

    // 8: residual + LN2 -> output
    add_ln_kernel<0><<<BS, 256>>>(bufX1, bufB, g2, beta2, outp, nullptr);
}

// round 15
// speedup vs baseline: 1.1529x; 1.0046x over previous
#include <cuda_runtime.h>
#include <cuda_fp16.h>
#include <math.h>
#include <stdint.h>

// ---------------------------------------------------------------------------
// Problem constants
// ---------------------------------------------------------------------------
#define BATCH   2
#define SEQ     2048
#define DMODEL  1024
#define NHEADS  16
#define HEADDIM 64
#define DFF     4096
#define BS      (BATCH * SEQ)          // 4096 rows
#define LN_EPS  1e-5f
#define ATTN_SCALE 0.08838834764831845f   // 1/sqrt(128)
#define QKVN    (3 * DMODEL)           // fused QKV width

// ---------------------------------------------------------------------------
// Scratch buffers
// ---------------------------------------------------------------------------
__device__ float  g_bufA   [BS * DMODEL];            // Wo out (fp32)
__device__ float  g_bufB   [BS * DMODEL];            // FFN2 out (fp32)
__device__ float  g_bufX1  [BS * DMODEL];            // LN1 out fp32
__device__ __half g_xh     [BS * DMODEL];            // x in fp16
__device__ __half g_QKVh   [BS * QKVN];              // fused QKV output fp16
__device__ __half g_QPh    [BATCH * NHEADS * SEQ * 2 * HEADDIM];
__device__ __half g_KPh    [BATCH * NHEADS * SEQ * 2 * HEADDIM];
__device__ __half g_AttnH  [BS * DMODEL];            // attention out fp16
__device__ __half g_X1h    [BS * DMODEL];            // LN1 out fp16
__device__ __half g_FFh    [BS * DFF];               // FFN hidden fp16

// fp16 weights in NATIVE [K][N] layout (no transpose needed: ldmatrix.trans)
__device__ __half g_Wcat[DMODEL * QKVN];             // cols: Wq | Wk | Wv
__device__ float  g_bqkv[QKVN];
__device__ __half g_Woh[DMODEL * DMODEL];
__device__ __half g_W1h[DMODEL * DFF];
__device__ __half g_W2h[DFF * DMODEL];

// ---------------------------------------------------------------------------
// Helpers
// ---------------------------------------------------------------------------
__device__ __forceinline__ uint32_t smem_u32(const void* p) {
    uint32_t a;
    asm("{ .reg .u64 t; cvta.to.shared.u64 t, %1; cvt.u32.u64 %0, t; }"
        : "=r"(a) : "l"(p));
    return a;
}

__device__ __forceinline__ void cp_async16(uint32_t saddr, const void* gptr) {
    asm volatile("cp.async.cg.shared.global [%0], [%1], 16;"
                 :: "r"(saddr), "l"(gptr) : "memory");
}

// fp16 mma m16n8k16, fp32 accumulate
__device__ __forceinline__ void mma_f16(float (&d)[4],
                                        const uint32_t (&a)[4],
                                        uint32_t b0, uint32_t b1)
{
    asm volatile(
        "mma.sync.aligned.m16n8k16.row.col.f32.f16.f16.f32 "
        "{%0,%1,%2,%3}, {%4,%5,%6,%7}, {%8,%9}, {%0,%1,%2,%3};"
        : "+f"(d[0]), "+f"(d[1]), "+f"(d[2]), "+f"(d[3])
        : "r"(a[0]), "r"(a[1]), "r"(a[2]), "r"(a[3]), "r"(b0), "r"(b1));
}

__device__ __forceinline__ void ldsm_x4(uint32_t (&r)[4], uint32_t saddr) {
    asm volatile("ldmatrix.sync.aligned.m8n8.x4.shared.b16 {%0,%1,%2,%3}, [%4];"
                 : "=r"(r[0]), "=r"(r[1]), "=r"(r[2]), "=r"(r[3]) : "r"(saddr));
}

__device__ __forceinline__ void ldsm_x4_t(uint32_t (&r)[4], uint32_t saddr) {
    asm volatile("ldmatrix.sync.aligned.m8n8.x4.trans.shared.b16 {%0,%1,%2,%3}, [%4];"
                 : "=r"(r[0]), "=r"(r[1]), "=r"(r[2]), "=r"(r[3]) : "r"(saddr));
}

// Fast exp via MUFU.EX2 (args are <= 0 here; ex2.approx(-inf) = 0)
__device__ __forceinline__ float fexpf(float x) {
    float y = x * 1.4426950408889634f;
    float r;
    asm("ex2.approx.f32 %0, %1;" : "=f"(r) : "f"(y));
    return r;
}

__device__ __forceinline__ float fex2(float x) {
    float r; asm("ex2.approx.f32 %0, %1;" : "=f"(r) : "f"(x)); return r;
}
__device__ __forceinline__ float flg2(float x) {
    float r; asm("lg2.approx.f32 %0, %1;" : "=f"(r) : "f"(x)); return r;
}
__device__ __forceinline__ float fsin(float x) {
    float r; asm("sin.approx.f32 %0, %1;" : "=f"(r) : "f"(x)); return r;
}
__device__ __forceinline__ float fcos(float x) {
    float r; asm("cos.approx.f32 %0, %1;" : "=f"(r) : "f"(x)); return r;
}

// Fast softplus: max(x,0) + ln2 * lg2(1 + 2^(-|x|*log2e))
__device__ __forceinline__ float fsoftplus(float x) {
    float t = fex2(-fabsf(x) * 1.4426950408889634f);
    return fmaxf(x, 0.f) + 0.6931471805599453f * flg2(1.f + t);
}

// Fast sincos with Cody-Waite range reduction (|ph| < ~2100, n <= ~340).
__device__ __forceinline__ void fsincos(float ph, float* s, float* c) {
    float n = rintf(ph * 0.15915494309189535f);       // ph / 2pi
    float r = fmaf(n, -6.28125f, ph);                 // 2pi hi (exact products)
    r = fmaf(n, -1.9353071795864769e-3f, r);          // 2pi lo
    *s = fsin(r);
    *c = fcos(r);
}

// ---------------------------------------------------------------------------
// ALL conversions in ONE launch. grid.y selects item:
//   0..2: Wq/Wk/Wv -> Wcat (column-concat) 3: Wo, 4: W1, 5: W2, 6: bias, 7: x
// ---------------------------------------------------------------------------
__global__ __launch_bounds__(256)
void f2h_weights_kernel(const float* __restrict__ Wq, const float* __restrict__ Wk,
                        const float* __restrict__ Wv, const float* __restrict__ Wo,
                        const float* __restrict__ W1, const float* __restrict__ W2,
                        const float* __restrict__ bq, const float* __restrict__ bk,
                        const float* __restrict__ bv, const float* __restrict__ x,
                        __half* __restrict__ Wcat, __half* __restrict__ Woh,
                        __half* __restrict__ W1h, __half* __restrict__ W2h,
                        float* __restrict__ bqkv, __half* __restrict__ xh)
{
    const int id  = blockIdx.y;
    const int idx = blockIdx.x * 256 + threadIdx.x;   // chunk of 8 elems

    if (id == 6) {
        if (idx >= QKVN) return;
        float v = (idx < DMODEL) ? bq[idx]
                : (idx < 2 * DMODEL) ? bk[idx - DMODEL] : bv[idx - 2 * DMODEL];
        bqkv[idx] = v;
        return;
    }

    const float* src;
    __half* dst;
    int nchunks;
    if (id < 3)      { src = (id == 0) ? Wq : (id == 1) ? Wk : Wv;
                       dst = Wcat; nchunks = DMODEL * DMODEL / 8; }
    else if (id == 3){ src = Wo; dst = Woh; nchunks = DMODEL * DMODEL / 8; }
    else if (id == 4){ src = W1; dst = W1h; nchunks = DMODEL * DFF / 8; }
    else if (id == 5){ src = W2; dst = W2h; nchunks = DFF * DMODEL / 8; }
    else             { src = x;  dst = xh;  nchunks = BS * DMODEL / 8; }
    if (idx >= nchunks) return;

    float4 a = *(const float4*)(src + idx * 8);
    float4 b = *(const float4*)(src + idx * 8 + 4);
    __half2 h[4];
    h[0] = __floats2half2_rn(a.x, a.y);
    h[1] = __floats2half2_rn(a.z, a.w);
    h[2] = __floats2half2_rn(b.x, b.y);
    h[3] = __floats2half2_rn(b.z, b.w);

    if (id < 3) {
        int r = idx >> 7;            // 128 chunks per 1024-wide row
        int c = idx & 127;
        *(uint4*)(dst + (size_t)r * QKVN + id * DMODEL + c * 8) = *(uint4*)h;
    } else {
        *(uint4*)(dst + (size_t)idx * 8) = *(uint4*)h;
    }
}

// ---------------------------------------------------------------------------
// fp16 mma GEMM: C(MxN) = A(MxK) @ W(KxN) + bias. W in NATIVE [K][N] layout;
// B fragments via ldmatrix.trans. 128x128x32 tiles, 8 warps, 5-stage cp.async
// pipeline, one sync per K-iter, 2 CTAs/SM.
// ---------------------------------------------------------------------------
#define HG_STRIDE 40          // A tile stride (halves)
#define HG_BS     136         // B tile stride (halves), 32 rows x 128 cols
#define HG_STAGES 5
#define HG_A_HALVES (128 * HG_STRIDE)
#define HG_B_HALVES (32 * HG_BS)
#define HG_STAGE_HALVES (HG_A_HALVES + HG_B_HALVES)       // 9472
#define HG_SMEM_BYTES (HG_STAGES * HG_STAGE_HALVES * 2)   // 94720 B

template<int RELU, int HALFOUT>
__global__ __launch_bounds__(256, 2)
void hgemm_kernel(const __half* __restrict__ A, const __half* __restrict__ W,
                  const float* __restrict__ bias, void* __restrict__ Cv,
                  int M, int N, int K)
{
    extern __shared__ __half hsm[];

    const int tid  = threadIdx.x;
    const int lane = tid & 31, wid = tid >> 5;
    const int wm = wid >> 1, wn = wid & 1;
    const int grp = lane >> 2, tig = lane & 3;
    const int m0 = blockIdx.y * 128, n0 = blockIdx.x * 128;

    const uint32_t smbase = smem_u32(hsm);

    const int l8  = lane & 7;
    const int q01 = (lane >> 3) & 1;
    const int q23 = lane >> 4;

    float acc[2][8][4];
#pragma unroll
    for (int mi = 0; mi < 2; ++mi)
#pragma unroll
        for (int nj = 0; nj < 8; ++nj)
#pragma unroll
            for (int r = 0; r < 4; ++r) acc[mi][nj][r] = 0.f;

    auto load_tiles = [&](int stage, int k0) {
        uint32_t ab = smbase + stage * HG_STAGE_HALVES * 2;
        uint32_t bb = ab + HG_A_HALVES * 2;
#pragma unroll
        for (int i = 0; i < 2; ++i) {
            int idx = tid + i * 256;
            int r = idx >> 2, c = idx & 3;
            cp_async16(ab + (uint32_t)(r * HG_STRIDE + c * 8) * 2,
                       A + (size_t)(m0 + r) * K + k0 + c * 8);
        }
#pragma unroll
        for (int i = 0; i < 2; ++i) {
            int idx = tid + i * 256;
            int r = idx >> 4, c = idx & 15;
            cp_async16(bb + (uint32_t)(r * HG_BS + c * 8) * 2,
                       W + (size_t)(k0 + r) * N + n0 + c * 8);
        }
    };

    const int nIt = K / 32;
#pragma unroll
    for (int s = 0; s < HG_STAGES - 1; ++s) {
        load_tiles(s, s * 32);
        asm volatile("cp.async.commit_group;" ::: "memory");
    }

    int st = 0, lst = HG_STAGES - 1;
    for (int it = 0; it < nIt; ++it) {
        asm volatile("cp.async.wait_group 3;" ::: "memory");
        __syncthreads();
        if (it + HG_STAGES - 1 < nIt) {
            load_tiles(lst, (it + HG_STAGES - 1) * 32);
            asm volatile("cp.async.commit_group;" ::: "memory");
            lst = (lst == HG_STAGES - 1) ? 0 : lst + 1;
        }

        const uint32_t abase = smbase + st * HG_STAGE_HALVES * 2;
        const uint32_t bbase = abase + HG_A_HALVES * 2;
        st = (st == HG_STAGES - 1) ? 0 : st + 1;

#pragma unroll
        for (int kk = 0; kk < 2; ++kk) {
            const int k = kk * 16;
            uint32_t af[2][4];
#pragma unroll
            for (int mi = 0; mi < 2; ++mi) {
                int row = wm * 32 + mi * 16 + q01 * 8 + l8;
                int col = k + q23 * 8;
                ldsm_x4(af[mi], abase + (uint32_t)(row * HG_STRIDE + col) * 2);
            }
#pragma unroll
            for (int g = 0; g < 4; ++g) {
                uint32_t bf[4];
                int row = k + q01 * 8 + l8;                 // k index
                int col = wn * 64 + g * 16 + q23 * 8;       // n index
                ldsm_x4_t(bf, bbase + (uint32_t)(row * HG_BS + col) * 2);
#pragma unroll
                for (int h2 = 0; h2 < 2; ++h2)
#pragma unroll
                    for (int mi = 0; mi < 2; ++mi)
                        mma_f16(acc[mi][g * 2 + h2], af[mi], bf[h2 * 2], bf[h2 * 2 + 1]);
            }
        }
    }

#pragma unroll
    for (int mi = 0; mi < 2; ++mi) {
        int r = m0 + wm * 32 + mi * 16 + grp;
#pragma unroll
        for (int nj = 0; nj < 8; ++nj) {
            int c = n0 + wn * 64 + nj * 8 + tig * 2;
            float bb0 = bias[c], bb1 = bias[c + 1];
            float v0 = acc[mi][nj][0] + bb0;
            float v1 = acc[mi][nj][1] + bb1;
            float v2 = acc[mi][nj][2] + bb0;
            float v3 = acc[mi][nj][3] + bb1;
            if (RELU) {
                v0 = fmaxf(v0, 0.f); v1 = fmaxf(v1, 0.f);
                v2 = fmaxf(v2, 0.f); v3 = fmaxf(v3, 0.f);
            }
            if (HALFOUT) {
                __half* C = (__half*)Cv;
                *(__half2*)&C[(size_t)r * N + c]       = __floats2half2_rn(v0, v1);
                *(__half2*)&C[(size_t)(r + 8) * N + c] = __floats2half2_rn(v2, v3);
            } else {
                float* C = (float*)Cv;
                float2 lo; lo.x = v0; lo.y = v1;
                float2 hi; hi.x = v2; hi.y = v3;
                *(float2*)&C[(size_t)r * N + c]       = lo;
                *(float2*)&C[(size_t)(r + 8) * N + c] = hi;
            }
        }
    }
}

// ---------------------------------------------------------------------------
// PoPE transform: fast MUFU math (range-reduced sin/cos, ex2/lg2 softplus).
// ---------------------------------------------------------------------------
__global__ void pope_kernel(const __half* __restrict__ qkv,
                            const int* __restrict__ positions,
                            const float* __restrict__ freqs,
                            const float* __restrict__ phase_bias,
                            __half* __restrict__ qp, __half* __restrict__ kp)
{
    int idx = blockIdx.x * blockDim.x + threadIdx.x;   // B*H*S*32
    if (idx >= BATCH * NHEADS * SEQ * 32) return;
    int d = (idx & 31) * 2;
    int s = (idx >> 5) & (SEQ - 1);
    int h = (idx >> 16) & (NHEADS - 1);
    int b = idx >> 20;

    size_t rowb = (size_t)(b * SEQ + s) * QKVN + h * HEADDIM + d;
    float2 qv = __half22float2(*(const __half2*)&qkv[rowb]);
    float2 kv = __half22float2(*(const __half2*)&qkv[rowb + DMODEL]);

    float pos = (float)positions[s];
    float ph0 = fmaf(pos, freqs[d],     phase_bias[h * HEADDIM + d]);
    float ph1 = fmaf(pos, freqs[d + 1], phase_bias[h * HEADDIM + d + 1]);
    float c0, s0, c1, s1;
    fsincos(ph0, &s0, &c0);
    fsincos(ph1, &s1, &c1);

    float mq0 = fsoftplus(qv.x) * ATTN_SCALE, mq1 = fsoftplus(qv.y) * ATTN_SCALE;
    float mk0 = fsoftplus(kv.x),              mk1 = fsoftplus(kv.y);

    size_t base = (((size_t)(b * NHEADS + h) * SEQ) + s) * 128 + d;
    *(__half2*)&qp[base]      = __floats2half2_rn(mq0 * c0, mq1 * c1);
    *(__half2*)&qp[base + 64] = __floats2half2_rn(mq0 * s0, mq1 * s1);
    *(__half2*)&kp[base]      = __floats2half2_rn(mk0 * c0, mk1 * c1);
    *(__half2*)&kp[base + 64] = __floats2half2_rn(mk0 * s0, mk1 * s1);
}

// ---------------------------------------------------------------------------
// Flash attention with softmax1, fp16 mma + ldmatrix. 2 CTAs/SM.
// P kept entirely in registers: QK C-fragment == PV A-fragment layout
// (keys are the k-dim), so no smem round-trip for probabilities.
// ---------------------------------------------------------------------------
#define AT_QS 136
#define AT_KS 136
#define AT_VS 72
#define AT_Q_HALVES (128 * AT_QS)
#define AT_K_STAGE  (64 * AT_KS)
#define AT_V_STAGE  (64 * AT_VS)
#define AT_SMEM_HALVES (AT_Q_HALVES + 2 * AT_K_STAGE + 2 * AT_V_STAGE)
#define AT_SMEM_BYTES  (AT_SMEM_HALVES * 2)   // 88064 B

__global__ __launch_bounds__(256, 2)
void attn_h_kernel(const __half* __restrict__ qp, const __half* __restrict__ kp,
                   const __half* __restrict__ qkv, __half* __restrict__ out)
{
    extern __shared__ __half hsm[];
    __half* Qs = hsm;                           // 128 x 136 (staging)

    const int b = blockIdx.z;
    const int h = blockIdx.y;
    const int qtile = gridDim.x - 1 - blockIdx.x;   // heavy tiles first
    const int q0 = qtile * 128;

    const int tid  = threadIdx.x;
    const int lane = tid & 31, wid = tid >> 5;
    const int grp = lane >> 2, tig = lane & 3;
    const int r0 = wid * 16 + grp;

    const int l8  = lane & 7;
    const int q01 = (lane >> 3) & 1;
    const int q23 = lane >> 4;

    const uint32_t smbase = smem_u32(hsm);
    const uint32_t kssm0 = smbase + AT_Q_HALVES * 2;             // K stage 0
    const uint32_t vssm0 = kssm0 + 2 * AT_K_STAGE * 2;           // V stage 0

    const __half* qbase = qp + (((size_t)(b * NHEADS + h)) * SEQ) * 128;
    const __half* kbase = kp + (((size_t)(b * NHEADS + h)) * SEQ) * 128;
    const __half* vbase = qkv + 2 * DMODEL + h * HEADDIM;        // V cols in fused buffer

    auto load_kv = [&](int stage, int kt) {
        uint32_t kb = kssm0 + stage * AT_K_STAGE * 2;
#pragma unroll
        for (int i = 0; i < 4; ++i) {
            int idx = tid + i * 256;
            int r = idx >> 4, c = idx & 15;
            cp_async16(kb + (uint32_t)(r * AT_KS + c * 8) * 2,
                       kbase + (size_t)(kt + r) * 128 + c * 8);
        }
        uint32_t vb = vssm0 + stage * AT_V_STAGE * 2;
#pragma unroll
        for (int i = 0; i < 2; ++i) {
            int idx = tid + i * 256;
            int r = idx >> 3, c = idx & 7;
            cp_async16(vb + (uint32_t)(r * AT_VS + c * 8) * 2,
                       vbase + ((size_t)b * SEQ + kt + r) * QKVN + c * 8);
        }
    };

    // Prologue: start K/V tile 0 fetch, then stage Q.
    load_kv(0, 0);
    asm volatile("cp.async.commit_group;" ::: "memory");

    for (int i = tid; i < 2048; i += 256) {
        int r = i >> 4, c = i & 15;
        *(uint4*)&Qs[r * AT_QS + c * 8] =
            *(const uint4*)&qbase[(size_t)(q0 + r) * 128 + c * 8];
    }
    __syncthreads();

    // Preload Q fragments via ldmatrix: 8 k16 chunks
    uint32_t qf[8][4];
    {
        int row = wid * 16 + q01 * 8 + l8;
#pragma unroll
        for (int kk = 0; kk < 8; ++kk) {
            int col = kk * 16 + q23 * 8;
            ldsm_x4(qf[kk], smbase + (uint32_t)(row * AT_QS + col) * 2);
        }
    }

    float m0 = -INFINITY, m1 = -INFINITY, l0 = 0.f, l1 = 0.f;
    float o[8][4];
#pragma unroll
    for (int nj = 0; nj < 8; ++nj)
#pragma unroll
        for (int r = 0; r < 4; ++r) o[nj][r] = 0.f;

    const int nT = q0 / 64 + 2;
    for (int t = 0; t < nT; ++t) {
        const int kt = t * 64;
        asm volatile("cp.async.wait_group 0;" ::: "memory");
        __syncthreads();
        if (t + 1 < nT) {
            load_kv((t + 1) & 1, (t + 1) * 64);
            asm volatile("cp.async.commit_group;" ::: "memory");
        }
        const uint32_t kst = kssm0 + (t & 1) * AT_K_STAGE * 2;
        const uint32_t vst = vssm0 + (t & 1) * AT_V_STAGE * 2;

        // scores = Q @ K^T
        float sacc[8][4];
#pragma unroll
        for (int nj = 0; nj < 8; ++nj)
#pragma unroll
            for (int r = 0; r < 4; ++r) sacc[nj][r] = 0.f;

#pragma unroll
        for (int kk = 0; kk < 8; ++kk) {
            int k = kk * 16;
#pragma unroll
            for (int g = 0; g < 4; ++g) {
                uint32_t bf[4];
                int row = g * 16 + q23 * 8 + l8;
                int col = k + q01 * 8;
                ldsm_x4(bf, kst + (uint32_t)(row * AT_KS + col) * 2);
                mma_f16(sacc[g * 2 + 0], qf[kk], bf[0], bf[1]);
                mma_f16(sacc[g * 2 + 1], qf[kk], bf[2], bf[3]);
            }
        }

        // causal mask (last two key tiles only)
        if (kt >= q0) {
            int row0 = q0 + r0, row1 = row0 + 8;
#pragma unroll
            for (int nj = 0; nj < 8; ++nj) {
                int c = kt + nj * 8 + 2 * tig;
                if (c     > row0) sacc[nj][0] = -INFINITY;
                if (c + 1 > row0) sacc[nj][1] = -INFINITY;
                if (c     > row1) sacc[nj][2] = -INFINITY;
                if (c + 1 > row1) sacc[nj][3] = -INFINITY;
            }
        }

        // online softmax1 (fast ex2)
        float mx0 = -INFINITY, mx1 = -INFINITY;
#pragma unroll
        for (int nj = 0; nj < 8; ++nj) {
            mx0 = fmaxf(mx0, fmaxf(sacc[nj][0], sacc[nj][1]));
            mx1 = fmaxf(mx1, fmaxf(sacc[nj][2], sacc[nj][3]));
        }
        mx0 = fmaxf(mx0, __shfl_xor_sync(0xffffffffu, mx0, 1));
        mx0 = fmaxf(mx0, __shfl_xor_sync(0xffffffffu, mx0, 2));
        mx1 = fmaxf(mx1, __shfl_xor_sync(0xffffffffu, mx1, 1));
        mx1 = fmaxf(mx1, __shfl_xor_sync(0xffffffffu, mx1, 2));

        float m0n = fmaxf(m0, mx0), m1n = fmaxf(m1, mx1);
        float c0 = fexpf(m0 - m0n),  c1 = fexpf(m1 - m1n);
        m0 = m0n; m1 = m1n;

        // P in registers: C-fragment(keys) == A-fragment(k) layout.
        // pf[kk]: reg0 = p[2kk][0,1], reg1 = p[2kk][2,3],
        //         reg2 = p[2kk+1][0,1], reg3 = p[2kk+1][2,3]
        uint32_t pf[4][4];
        float ls0 = 0.f, ls1 = 0.f;
#pragma unroll
        for (int nj = 0; nj < 8; ++nj) {
            float p0 = fexpf(sacc[nj][0] - m0n);
            float p1 = fexpf(sacc[nj][1] - m0n);
            float p2 = fexpf(sacc[nj][2] - m1n);
            float p3 = fexpf(sacc[nj][3] - m1n);
            ls0 += p0 + p1; ls1 += p2 + p3;
            int kk = nj >> 1, hh = (nj & 1) * 2;
            __half2 lo = __floats2half2_rn(p0, p1);
            __half2 hi = __floats2half2_rn(p2, p3);
            pf[kk][hh + 0] = *(uint32_t*)&lo;
            pf[kk][hh + 1] = *(uint32_t*)&hi;
        }
        ls0 += __shfl_xor_sync(0xffffffffu, ls0, 1);
        ls0 += __shfl_xor_sync(0xffffffffu, ls0, 2);
        ls1 += __shfl_xor_sync(0xffffffffu, ls1, 1);
        ls1 += __shfl_xor_sync(0xffffffffu, ls1, 2);
        l0 = l0 * c0 + ls0;
        l1 = l1 * c1 + ls1;

#pragma unroll
        for (int nj = 0; nj < 8; ++nj) {
            o[nj][0] *= c0; o[nj][1] *= c0;
            o[nj][2] *= c1; o[nj][3] *= c1;
        }

        // O += P @ V (V row-major [key][dim]; B fragments via ldmatrix.trans)
#pragma unroll
        for (int kk = 0; kk < 4; ++kk) {
            int k = kk * 16;
#pragma unroll
            for (int g = 0; g < 4; ++g) {
                uint32_t bf[4];
                int row = k + q01 * 8 + l8;          // key index
                int col = g * 16 + q23 * 8;          // dim index
                ldsm_x4_t(bf, vst + (uint32_t)(row * AT_VS + col) * 2);
                mma_f16(o[g * 2 + 0], pf[kk], bf[0], bf[1]);
                mma_f16(o[g * 2 + 1], pf[kk], bf[2], bf[3]);
            }
        }
    }

    // epilogue: softmax1 denominator; write fp16 (B,S,D)
    float inv0 = 1.f / (1.f + l0);
    float inv1 = 1.f / (1.f + l1);
    int row0 = q0 + r0;
#pragma unroll
    for (int nj = 0; nj < 8; ++nj) {
        int c = h * HEADDIM + nj * 8 + 2 * tig;
        *(__half2*)&out[((size_t)b * SEQ + row0)     * DMODEL + c] =
            __floats2half2_rn(o[nj][0] * inv0, o[nj][1] * inv0);
        *(__half2*)&out[((size_t)b * SEQ + row0 + 8) * DMODEL + c] =
            __floats2half2_rn(o[nj][2] * inv1, o[nj][3] * inv1);
    }
}

// ---------------------------------------------------------------------------
// Fused residual add + LayerNorm; optional fp16 copy of the output.
// ---------------------------------------------------------------------------
template<int WRITEH>
__global__ __launch_bounds__(256)
void add_ln_kernel(const float* __restrict__ x, const float* __restrict__ y,
                   const float* __restrict__ g, const float* __restrict__ beta,
                   float* __restrict__ out, __half* __restrict__ outh)
{
    __shared__ float red_s[8];
    __shared__ float red_ss[8];
    __shared__ float s_mu, s_rstd;

    const int row = blockIdx.x;
    const int tid = threadIdx.x;
    const size_t base = (size_t)row * DMODEL;

    float4 xv = ((const float4*)(x + base))[tid];
    float4 yv = ((const float4*)(y + base))[tid];
    float v0 = xv.x + yv.x, v1 = xv.y + yv.y, v2 = xv.z + yv.z, v3 = xv.w + yv.w;

    float sum = v0 + v1 + v2 + v3;
    float ssq = v0 * v0 + v1 * v1 + v2 * v2 + v3 * v3;
#pragma unroll
    for (int off = 16; off >= 1; off >>= 1) {
        sum += __shfl_down_sync(0xffffffffu, sum, off);
        ssq += __shfl_down_sync(0xffffffffu, ssq, off);
    }
    const int warp = tid >> 5;
    if ((tid & 31) == 0) { red_s[warp] = sum; red_ss[warp] = ssq; }
    __syncthreads();
    if (tid == 0) {
        float ts = 0.f, tss = 0.f;
#pragma unroll
        for (int w = 0; w < 8; ++w) { ts += red_s[w]; tss += red_ss[w]; }
        float mu  = ts / (float)DMODEL;
        float var = tss / (float)DMODEL - mu * mu;
        s_mu = mu;
        s_rstd = rsqrtf(var + LN_EPS);
    }
    __syncthreads();
    const float mu = s_mu, rstd = s_rstd;

    float4 gv = ((const float4*)g)[tid];
    float4 bv = ((const float4*)beta)[tid];
    float4 o;
    o.x = (v0 - mu) * rstd * gv.x + bv.x;
    o.y = (v1 - mu) * rstd * gv.y + bv.y;
    o.z = (v2 - mu) * rstd * gv.z + bv.z;
    o.w = (v3 - mu) * rstd * gv.w + bv.w;
    ((float4*)(out + base))[tid] = o;
    if (WRITEH) {
        __half2 h0 = __floats2half2_rn(o.x, o.y);
        __half2 h1 = __floats2half2_rn(o.z, o.w);
        ((__half2*)(outh + base))[2 * tid]     = h0;
        ((__half2*)(outh + base))[2 * tid + 1] = h1;
    }
}

// ---------------------------------------------------------------------------
// Launcher
// ---------------------------------------------------------------------------
extern "C" void kernel_launch(void* const* d_in, const int* in_sizes, int n_in,
                              void* d_out, int out_size)
{
    (void)in_sizes; (void)n_in; (void)out_size;
    const float* x          = (const float*)d_in[0];
    const int*   positions  = (const int*)  d_in[1];
    const float* Wq         = (const float*)d_in[2];
    const float* bq         = (const float*)d_in[3];
    const float* Wk         = (const float*)d_in[4];
    const float* bk         = (const float*)d_in[5];
    const float* Wv         = (const float*)d_in[6];
    const float* bv         = (const float*)d_in[7];
    const float* Wo         = (const float*)d_in[8];
    const float* bo         = (const float*)d_in[9];
    const float* phase_bias = (const float*)d_in[10];
    const float* freqs      = (const float*)d_in[11];
    const float* W1         = (const float*)d_in[12];
    const float* b1         = (const float*)d_in[13];
    const float* W2         = (const float*)d_in[14];
    const float* b2         = (const float*)d_in[15];
    const float* g1         = (const float*)d_in[16];
    const float* beta1      = (const float*)d_in[17];
    const float* g2         = (const float*)d_in[18];
    const float* beta2      = (const float*)d_in[19];
    float* outp             = (float*)d_out;

    float  *bufA, *bufB, *bufX1, *bqkv;
    __half *xh, *QKVh, *QPh, *KPh, *AttnH, *X1h, *FFh;
    __half *Wcat, *Woh, *W1h, *W2h;
    cudaGetSymbolAddress((void**)&bufA,  g_bufA);
    cudaGetSymbolAddress((void**)&bufB,  g_bufB);
    cudaGetSymbolAddress((void**)&bufX1, g_bufX1);
    cudaGetSymbolAddress((void**)&bqkv,  g_bqkv);
    cudaGetSymbolAddress((void**)&xh,    g_xh);
    cudaGetSymbolAddress((void**)&QKVh,  g_QKVh);
    cudaGetSymbolAddress((void**)&QPh,   g_QPh);
    cudaGetSymbolAddress((void**)&KPh,   g_KPh);
    cudaGetSymbolAddress((void**)&AttnH, g_AttnH);
    cudaGetSymbolAddress((void**)&X1h,   g_X1h);
    cudaGetSymbolAddress((void**)&FFh,   g_FFh);
    cudaGetSymbolAddress((void**)&Wcat,  g_Wcat);
    cudaGetSymbolAddress((void**)&Woh,   g_Woh);
    cudaGetSymbolAddress((void**)&W1h,   g_W1h);
    cudaGetSymbolAddress((void**)&W2h,   g_W2h);

    cudaFuncSetAttribute(attn_h_kernel, cudaFuncAttributeMaxDynamicSharedMemorySize,
                         AT_SMEM_BYTES);
    cudaFuncSetAttribute(hgemm_kernel<0,0>, cudaFuncAttributeMaxDynamicSharedMemorySize,
                         HG_SMEM_BYTES);
    cudaFuncSetAttribute(hgemm_kernel<0,1>, cudaFuncAttributeMaxDynamicSharedMemorySize,
                         HG_SMEM_BYTES);
    cudaFuncSetAttribute(hgemm_kernel<1,1>, cudaFuncAttributeMaxDynamicSharedMemorySize,
                         HG_SMEM_BYTES);

    // 0: ALL conversions (weights + bias + x) in one launch
    {
        dim3 grid(DFF * DMODEL / 8 / 256, 8);    // 2048 x 8
        f2h_weights_kernel<<<grid, 256>>>(Wq, Wk, Wv, Wo, W1, W2, bq, bk, bv, x,
                                          Wcat, Woh, W1h, W2h, bqkv, xh);
    }

    // 1: fused QKV projection (N=3072), fp16 out
    {
        dim3 grid(QKVN / 128, BS / 128);
        hgemm_kernel<0,1><<<grid, 256, HG_SMEM_BYTES>>>(xh, Wcat, bqkv, QKVh, BS, QKVN, DMODEL);
    }

    // 2: PoPE (fp16 in/out, fast MUFU math)
    {
        int total = BATCH * NHEADS * SEQ * 32;
        pope_kernel<<<(total + 255) / 256, 256>>>(QKVh, positions, freqs,
                                                  phase_bias, QPh, KPh);
    }

    // 3: attention -> fp16
    {
        dim3 grid(SEQ / 128, NHEADS, BATCH);
        attn_h_kernel<<<grid, 256, AT_SMEM_BYTES>>>(QPh, KPh, QKVh, AttnH);
    }

    // 4: output projection -> fp32
    {
        dim3 grid(DMODEL / 128, BS / 128);
        hgemm_kernel<0,0><<<grid, 256, HG_SMEM_BYTES>>>(AttnH, Woh, bo, bufA, BS, DMODEL, DMODEL);
    }

    // 5: residual + LN1 -> fp32 + fp16
    add_ln_kernel<1><<<BS, 256>>>(x, bufA, g1, beta1, bufX1, X1h);

    // 6: FFN up + ReLU -> fp16
    {
        dim3 grid(DFF / 128, BS / 128);
        hgemm_kernel<1,1><<<grid, 256, HG_SMEM_BYTES>>>(X1h, W1h, b1, FFh, BS, DFF, DMODEL);
    }

    // 7: FFN down -> fp32
    {
        dim3 grid(DMODEL / 128, BS / 128);
        hgemm_kernel<0,0><<<grid, 256, HG_SMEM_BYTES>>>(FFh, W2h, b2, bufB, BS, DMODEL, DFF);
    }

    // 8: residual + LN2 -> output
    add_ln_kernel<0><<<BS, 256>>>(bufX1, bufB, g2, beta2, outp, nullptr);
}

// round 16
// speedup vs baseline: 1.1661x; 1.0114x over previous
#include <cuda_runtime.h>
#include <cuda_fp16.h>
#include <math.h>
#include <stdint.h>

// ---------------------------------------------------------------------------
// Problem constants
// ---------------------------------------------------------------------------
#define BATCH   2
#define SEQ     2048
#define DMODEL  1024
#define NHEADS  16
#define HEADDIM 64
#define DFF     4096
#define BS      (BATCH * SEQ)          // 4096 rows
#define LN_EPS  1e-5f
#define ATTN_SCALE 0.08838834764831845f   // 1/sqrt(128)
#define QKVN    (3 * DMODEL)           // fused QKV width

// ---------------------------------------------------------------------------
// Scratch buffers
// ---------------------------------------------------------------------------
__device__ float  g_bufA   [BS * DMODEL];            // Wo out (fp32)
__device__ float  g_bufB   [BS * DMODEL];            // FFN2 out (fp32)
__device__ float  g_bufX1  [BS * DMODEL];            // LN1 out fp32
__device__ __half g_xh     [BS * DMODEL];            // x in fp16
__device__ __half g_Vh     [BS * DMODEL];            // V fp16 (compact)
__device__ __half g_QPh    [BATCH * NHEADS * SEQ * 2 * HEADDIM];
__device__ __half g_KPh    [BATCH * NHEADS * SEQ * 2 * HEADDIM];
__device__ __half g_AttnH  [BS * DMODEL];            // attention out fp16
__device__ __half g_X1h    [BS * DMODEL];            // LN1 out fp16
__device__ __half g_FFh    [BS * DFF];               // FFN hidden fp16

// fp16 weights in NATIVE [K][N] layout (no transpose needed: ldmatrix.trans)
__device__ __half g_Wcat[DMODEL * QKVN];             // cols: Wq | Wk | Wv
__device__ float  g_bqkv[QKVN];
__device__ __half g_Woh[DMODEL * DMODEL];
__device__ __half g_W1h[DMODEL * DFF];
__device__ __half g_W2h[DFF * DMODEL];

// ---------------------------------------------------------------------------
// Helpers
// ---------------------------------------------------------------------------
__device__ __forceinline__ uint32_t smem_u32(const void* p) {
    uint32_t a;
    asm("{ .reg .u64 t; cvta.to.shared.u64 t, %1; cvt.u32.u64 %0, t; }"
        : "=r"(a) : "l"(p));
    return a;
}

__device__ __forceinline__ void cp_async16(uint32_t saddr, const void* gptr) {
    asm volatile("cp.async.cg.shared.global [%0], [%1], 16;"
                 :: "r"(saddr), "l"(gptr) : "memory");
}

// fp16 mma m16n8k16, fp32 accumulate
__device__ __forceinline__ void mma_f16(float (&d)[4],
                                        const uint32_t (&a)[4],
                                        uint32_t b0, uint32_t b1)
{
    asm volatile(
        "mma.sync.aligned.m16n8k16.row.col.f32.f16.f16.f32 "
        "{%0,%1,%2,%3}, {%4,%5,%6,%7}, {%8,%9}, {%0,%1,%2,%3};"
        : "+f"(d[0]), "+f"(d[1]), "+f"(d[2]), "+f"(d[3])
        : "r"(a[0]), "r"(a[1]), "r"(a[2]), "r"(a[3]), "r"(b0), "r"(b1));
}

__device__ __forceinline__ void ldsm_x4(uint32_t (&r)[4], uint32_t saddr) {
    asm volatile("ldmatrix.sync.aligned.m8n8.x4.shared.b16 {%0,%1,%2,%3}, [%4];"
                 : "=r"(r[0]), "=r"(r[1]), "=r"(r[2]), "=r"(r[3]) : "r"(saddr));
}

__device__ __forceinline__ void ldsm_x4_t(uint32_t (&r)[4], uint32_t saddr) {
    asm volatile("ldmatrix.sync.aligned.m8n8.x4.trans.shared.b16 {%0,%1,%2,%3}, [%4];"
                 : "=r"(r[0]), "=r"(r[1]), "=r"(r[2]), "=r"(r[3]) : "r"(saddr));
}

// Fast exp via MUFU.EX2 (args are <= 0 here; ex2.approx(-inf) = 0)
__device__ __forceinline__ float fexpf(float x) {
    float y = x * 1.4426950408889634f;
    float r;
    asm("ex2.approx.f32 %0, %1;" : "=f"(r) : "f"(y));
    return r;
}

__device__ __forceinline__ float fex2(float x) {
    float r; asm("ex2.approx.f32 %0, %1;" : "=f"(r) : "f"(x)); return r;
}
__device__ __forceinline__ float flg2(float x) {
    float r; asm("lg2.approx.f32 %0, %1;" : "=f"(r) : "f"(x)); return r;
}
__device__ __forceinline__ float fsin(float x) {
    float r; asm("sin.approx.f32 %0, %1;" : "=f"(r) : "f"(x)); return r;
}
__device__ __forceinline__ float fcos(float x) {
    float r; asm("cos.approx.f32 %0, %1;" : "=f"(r) : "f"(x)); return r;
}

// Fast softplus: max(x,0) + ln2 * lg2(1 + 2^(-|x|*log2e))
__device__ __forceinline__ float fsoftplus(float x) {
    float t = fex2(-fabsf(x) * 1.4426950408889634f);
    return fmaxf(x, 0.f) + 0.6931471805599453f * flg2(1.f + t);
}

// Fast sincos with Cody-Waite range reduction (|ph| < ~2100, n <= ~340).
__device__ __forceinline__ void fsincos(float ph, float* s, float* c) {
    float n = rintf(ph * 0.15915494309189535f);       // ph / 2pi
    float r = fmaf(n, -6.28125f, ph);                 // 2pi hi (exact products)
    r = fmaf(n, -1.9353071795864769e-3f, r);          // 2pi lo
    *s = fsin(r);
    *c = fcos(r);
}

// ---------------------------------------------------------------------------
// ALL conversions in ONE launch. grid.y selects item:
//   0..2: Wq/Wk/Wv -> Wcat (column-concat) 3: Wo, 4: W1, 5: W2, 6: bias, 7: x
// ---------------------------------------------------------------------------
__global__ __launch_bounds__(256)
void f2h_weights_kernel(const float* __restrict__ Wq, const float* __restrict__ Wk,
                        const float* __restrict__ Wv, const float* __restrict__ Wo,
                        const float* __restrict__ W1, const float* __restrict__ W2,
                        const float* __restrict__ bq, const float* __restrict__ bk,
                        const float* __restrict__ bv, const float* __restrict__ x,
                        __half* __restrict__ Wcat, __half* __restrict__ Woh,
                        __half* __restrict__ W1h, __half* __restrict__ W2h,
                        float* __restrict__ bqkv, __half* __restrict__ xh)
{
    const int id  = blockIdx.y;
    const int idx = blockIdx.x * 256 + threadIdx.x;   // chunk of 8 elems

    if (id == 6) {
        if (idx >= QKVN) return;
        float v = (idx < DMODEL) ? bq[idx]
                : (idx < 2 * DMODEL) ? bk[idx - DMODEL] : bv[idx - 2 * DMODEL];
        bqkv[idx] = v;
        return;
    }

    const float* src;
    __half* dst;
    int nchunks;
    if (id < 3)      { src = (id == 0) ? Wq : (id == 1) ? Wk : Wv;
                       dst = Wcat; nchunks = DMODEL * DMODEL / 8; }
    else if (id == 3){ src = Wo; dst = Woh; nchunks = DMODEL * DMODEL / 8; }
    else if (id == 4){ src = W1; dst = W1h; nchunks = DMODEL * DFF / 8; }
    else if (id == 5){ src = W2; dst = W2h; nchunks = DFF * DMODEL / 8; }
    else             { src = x;  dst = xh;  nchunks = BS * DMODEL / 8; }
    if (idx >= nchunks) return;

    float4 a = *(const float4*)(src + idx * 8);
    float4 b = *(const float4*)(src + idx * 8 + 4);
    __half2 h[4];
    h[0] = __floats2half2_rn(a.x, a.y);
    h[1] = __floats2half2_rn(a.z, a.w);
    h[2] = __floats2half2_rn(b.x, b.y);
    h[3] = __floats2half2_rn(b.z, b.w);

    if (id < 3) {
        int r = idx >> 7;            // 128 chunks per 1024-wide row
        int c = idx & 127;
        *(uint4*)(dst + (size_t)r * QKVN + id * DMODEL + c * 8) = *(uint4*)h;
    } else {
        *(uint4*)(dst + (size_t)idx * 8) = *(uint4*)h;
    }
}

// ---------------------------------------------------------------------------
// fp16 mma GEMM: C(MxN) = A(MxK) @ W(KxN) + bias. W in NATIVE [K][N] layout;
// B fragments via ldmatrix.trans. 128x128x32 tiles, 8 warps, 5-stage cp.async
// pipeline, one sync per K-iter, 2 CTAs/SM.
// POPE=1: fused PoPE epilogue. Columns [0,1024) -> qp, [1024,2048) -> kp
// (softplus magnitude x sincos phase, (B,H,S,128) layout); [2048,3072) -> Vh.
// ---------------------------------------------------------------------------
#define HG_STRIDE 40          // A tile stride (halves)
#define HG_BS     136         // B tile stride (halves), 32 rows x 128 cols
#define HG_STAGES 5
#define HG_A_HALVES (128 * HG_STRIDE)
#define HG_B_HALVES (32 * HG_BS)
#define HG_STAGE_HALVES (HG_A_HALVES + HG_B_HALVES)       // 9472
#define HG_SMEM_BYTES (HG_STAGES * HG_STAGE_HALVES * 2)   // 94720 B

template<int RELU, int HALFOUT, int POPE>
__global__ __launch_bounds__(256, 2)
void hgemm_kernel(const __half* __restrict__ A, const __half* __restrict__ W,
                  const float* __restrict__ bias, void* __restrict__ Cv,
                  int M, int N, int K,
                  const int* __restrict__ positions,
                  const float* __restrict__ freqs,
                  const float* __restrict__ phase_bias,
                  __half* __restrict__ qp, __half* __restrict__ kp)
{
    extern __shared__ __half hsm[];

    const int tid  = threadIdx.x;
    const int lane = tid & 31, wid = tid >> 5;
    const int wm = wid >> 1, wn = wid & 1;
    const int grp = lane >> 2, tig = lane & 3;
    const int m0 = blockIdx.y * 128, n0 = blockIdx.x * 128;

    const uint32_t smbase = smem_u32(hsm);

    const int l8  = lane & 7;
    const int q01 = (lane >> 3) & 1;
    const int q23 = lane >> 4;

    float acc[2][8][4];
#pragma unroll
    for (int mi = 0; mi < 2; ++mi)
#pragma unroll
        for (int nj = 0; nj < 8; ++nj)
#pragma unroll
            for (int r = 0; r < 4; ++r) acc[mi][nj][r] = 0.f;

    auto load_tiles = [&](int stage, int k0) {
        uint32_t ab = smbase + stage * HG_STAGE_HALVES * 2;
        uint32_t bb = ab + HG_A_HALVES * 2;
#pragma unroll
        for (int i = 0; i < 2; ++i) {
            int idx = tid + i * 256;
            int r = idx >> 2, c = idx & 3;
            cp_async16(ab + (uint32_t)(r * HG_STRIDE + c * 8) * 2,
                       A + (size_t)(m0 + r) * K + k0 + c * 8);
        }
#pragma unroll
        for (int i = 0; i < 2; ++i) {
            int idx = tid + i * 256;
            int r = idx >> 4, c = idx & 15;
            cp_async16(bb + (uint32_t)(r * HG_BS + c * 8) * 2,
                       W + (size_t)(k0 + r) * N + n0 + c * 8);
        }
    };

    const int nIt = K / 32;
#pragma unroll
    for (int s = 0; s < HG_STAGES - 1; ++s) {
        load_tiles(s, s * 32);
        asm volatile("cp.async.commit_group;" ::: "memory");
    }

    int st = 0, lst = HG_STAGES - 1;
    for (int it = 0; it < nIt; ++it) {
        asm volatile("cp.async.wait_group 3;" ::: "memory");
        __syncthreads();
        if (it + HG_STAGES - 1 < nIt) {
            load_tiles(lst, (it + HG_STAGES - 1) * 32);
            asm volatile("cp.async.commit_group;" ::: "memory");
            lst = (lst == HG_STAGES - 1) ? 0 : lst + 1;
        }

        const uint32_t abase = smbase + st * HG_STAGE_HALVES * 2;
        const uint32_t bbase = abase + HG_A_HALVES * 2;
        st = (st == HG_STAGES - 1) ? 0 : st + 1;

#pragma unroll
        for (int kk = 0; kk < 2; ++kk) {
            const int k = kk * 16;
            uint32_t af[2][4];
#pragma unroll
            for (int mi = 0; mi < 2; ++mi) {
                int row = wm * 32 + mi * 16 + q01 * 8 + l8;
                int col = k + q23 * 8;
                ldsm_x4(af[mi], abase + (uint32_t)(row * HG_STRIDE + col) * 2);
            }
#pragma unroll
            for (int g = 0; g < 4; ++g) {
                uint32_t bf[4];
                int row = k + q01 * 8 + l8;                 // k index
                int col = wn * 64 + g * 16 + q23 * 8;       // n index
                ldsm_x4_t(bf, bbase + (uint32_t)(row * HG_BS + col) * 2);
#pragma unroll
                for (int h2 = 0; h2 < 2; ++h2)
#pragma unroll
                    for (int mi = 0; mi < 2; ++mi)
                        mma_f16(acc[mi][g * 2 + h2], af[mi], bf[h2 * 2], bf[h2 * 2 + 1]);
            }
        }
    }

#pragma unroll
    for (int mi = 0; mi < 2; ++mi) {
        int r = m0 + wm * 32 + mi * 16 + grp;
#pragma unroll
        for (int nj = 0; nj < 8; ++nj) {
            int c = n0 + wn * 64 + nj * 8 + tig * 2;
            float bb0 = bias[c], bb1 = bias[c + 1];
            float v0 = acc[mi][nj][0] + bb0;
            float v1 = acc[mi][nj][1] + bb1;
            float v2 = acc[mi][nj][2] + bb0;
            float v3 = acc[mi][nj][3] + bb1;
            if (POPE) {
                if (c < 2 * DMODEL) {
                    // q or k column: PoPE transform (branch is warp-uniform)
                    int which = c >> 10;                 // 0=q, 1=k
                    int d  = c & 63;
                    int hh = (c >> 6) & 15;
                    float fr0 = freqs[d], fr1 = freqs[d + 1];
                    float pb0 = phase_bias[hh * HEADDIM + d];
                    float pb1 = phase_bias[hh * HEADDIM + d + 1];
                    float scale = which ? 1.f : ATTN_SCALE;
                    __half* dst = which ? kp : qp;
#pragma unroll
                    for (int rr = 0; rr < 2; ++rr) {
                        int row = r + rr * 8;
                        float va = rr ? v2 : v0;
                        float vb = rr ? v3 : v1;
                        int bidx = row >> 11, s = row & (SEQ - 1);
                        float pos = (float)positions[s];
                        float sn0, cs0, sn1, cs1;
                        fsincos(fmaf(pos, fr0, pb0), &sn0, &cs0);
                        fsincos(fmaf(pos, fr1, pb1), &sn1, &cs1);
                        float ma = fsoftplus(va) * scale;
                        float mb = fsoftplus(vb) * scale;
                        size_t base = (((size_t)(bidx * NHEADS + hh) * SEQ) + s) * 128 + d;
                        *(__half2*)&dst[base]      = __floats2half2_rn(ma * cs0, mb * cs1);
                        *(__half2*)&dst[base + 64] = __floats2half2_rn(ma * sn0, mb * sn1);
                    }
                } else {
                    __half* V = (__half*)Cv;
                    int cc = c - 2 * DMODEL;
                    *(__half2*)&V[(size_t)r * DMODEL + cc]       = __floats2half2_rn(v0, v1);
                    *(__half2*)&V[(size_t)(r + 8) * DMODEL + cc] = __floats2half2_rn(v2, v3);
                }
            } else {
                if (RELU) {
                    v0 = fmaxf(v0, 0.f); v1 = fmaxf(v1, 0.f);
                    v2 = fmaxf(v2, 0.f); v3 = fmaxf(v3, 0.f);
                }
                if (HALFOUT) {
                    __half* C = (__half*)Cv;
                    *(__half2*)&C[(size_t)r * N + c]       = __floats2half2_rn(v0, v1);
                    *(__half2*)&C[(size_t)(r + 8) * N + c] = __floats2half2_rn(v2, v3);
                } else {
                    float* C = (float*)Cv;
                    float2 lo; lo.x = v0; lo.y = v1;
                    float2 hi; hi.x = v2; hi.y = v3;
                    *(float2*)&C[(size_t)r * N + c]       = lo;
                    *(float2*)&C[(size_t)(r + 8) * N + c] = hi;
                }
            }
        }
    }
}

// ---------------------------------------------------------------------------
// Flash attention with softmax1, fp16 mma + ldmatrix. 2 CTAs/SM.
// P kept entirely in registers (QK C-fragment == PV A-fragment layout).
// ---------------------------------------------------------------------------
#define AT_QS 136
#define AT_KS 136
#define AT_VS 72
#define AT_Q_HALVES (128 * AT_QS)
#define AT_K_STAGE  (64 * AT_KS)
#define AT_V_STAGE  (64 * AT_VS)
#define AT_SMEM_HALVES (AT_Q_HALVES + 2 * AT_K_STAGE + 2 * AT_V_STAGE)
#define AT_SMEM_BYTES  (AT_SMEM_HALVES * 2)   // 88064 B

__global__ __launch_bounds__(256, 2)
void attn_h_kernel(const __half* __restrict__ qp, const __half* __restrict__ kp,
                   const __half* __restrict__ v, __half* __restrict__ out)
{
    extern __shared__ __half hsm[];
    __half* Qs = hsm;                           // 128 x 136 (staging)

    const int b = blockIdx.z;
    const int h = blockIdx.y;
    const int qtile = gridDim.x - 1 - blockIdx.x;   // heavy tiles first
    const int q0 = qtile * 128;

    const int tid  = threadIdx.x;
    const int lane = tid & 31, wid = tid >> 5;
    const int grp = lane >> 2, tig = lane & 3;
    const int r0 = wid * 16 + grp;

    const int l8  = lane & 7;
    const int q01 = (lane >> 3) & 1;
    const int q23 = lane >> 4;

    const uint32_t smbase = smem_u32(hsm);
    const uint32_t kssm0 = smbase + AT_Q_HALVES * 2;             // K stage 0
    const uint32_t vssm0 = kssm0 + 2 * AT_K_STAGE * 2;           // V stage 0

    const __half* qbase = qp + (((size_t)(b * NHEADS + h)) * SEQ) * 128;
    const __half* kbase = kp + (((size_t)(b * NHEADS + h)) * SEQ) * 128;
    const __half* vbase = v + h * HEADDIM;                       // compact V

    auto load_kv = [&](int stage, int kt) {
        uint32_t kb = kssm0 + stage * AT_K_STAGE * 2;
#pragma unroll
        for (int i = 0; i < 4; ++i) {
            int idx = tid + i * 256;
            int r = idx >> 4, c = idx & 15;
            cp_async16(kb + (uint32_t)(r * AT_KS + c * 8) * 2,
                       kbase + (size_t)(kt + r) * 128 + c * 8);
        }
        uint32_t vb = vssm0 + stage * AT_V_STAGE * 2;
#pragma unroll
        for (int i = 0; i < 2; ++i) {
            int idx = tid + i * 256;
            int r = idx >> 3, c = idx & 7;
            cp_async16(vb + (uint32_t)(r * AT_VS + c * 8) * 2,
                       vbase + ((size_t)b * SEQ + kt + r) * DMODEL + c * 8);
        }
    };

    // Prologue: start K/V tile 0 fetch, then stage Q.
    load_kv(0, 0);
    asm volatile("cp.async.commit_group;" ::: "memory");

    for (int i = tid; i < 2048; i += 256) {
        int r = i >> 4, c = i & 15;
        *(uint4*)&Qs[r * AT_QS + c * 8] =
            *(const uint4*)&qbase[(size_t)(q0 + r) * 128 + c * 8];
    }
    __syncthreads();

    // Preload Q fragments via ldmatrix: 8 k16 chunks
    uint32_t qf[8][4];
    {
        int row = wid * 16 + q01 * 8 + l8;
#pragma unroll
        for (int kk = 0; kk < 8; ++kk) {
            int col = kk * 16 + q23 * 8;
            ldsm_x4(qf[kk], smbase + (uint32_t)(row * AT_QS + col) * 2);
        }
    }

    float m0 = -INFINITY, m1 = -INFINITY, l0 = 0.f, l1 = 0.f;
    float o[8][4];
#pragma unroll
    for (int nj = 0; nj < 8; ++nj)
#pragma unroll
        for (int r = 0; r < 4; ++r) o[nj][r] = 0.f;

    const int nT = q0 / 64 + 2;
    for (int t = 0; t < nT; ++t) {
        const int kt = t * 64;
        asm volatile("cp.async.wait_group 0;" ::: "memory");
        __syncthreads();
        if (t + 1 < nT) {
            load_kv((t + 1) & 1, (t + 1) * 64);
            asm volatile("cp.async.commit_group;" ::: "memory");
        }
        const uint32_t kst = kssm0 + (t & 1) * AT_K_STAGE * 2;
        const uint32_t vst = vssm0 + (t & 1) * AT_V_STAGE * 2;

        // scores = Q @ K^T
        float sacc[8][4];
#pragma unroll
        for (int nj = 0; nj < 8; ++nj)
#pragma unroll
            for (int r = 0; r < 4; ++r) sacc[nj][r] = 0.f;

#pragma unroll
        for (int kk = 0; kk < 8; ++kk) {
            int k = kk * 16;
#pragma unroll
            for (int g = 0; g < 4; ++g) {
                uint32_t bf[4];
                int row = g * 16 + q23 * 8 + l8;
                int col = k + q01 * 8;
                ldsm_x4(bf, kst + (uint32_t)(row * AT_KS + col) * 2);
                mma_f16(sacc[g * 2 + 0], qf[kk], bf[0], bf[1]);
                mma_f16(sacc[g * 2 + 1], qf[kk], bf[2], bf[3]);
            }
        }

        // causal mask (last two key tiles only)
        if (kt >= q0) {
            int row0 = q0 + r0, row1 = row0 + 8;
#pragma unroll
            for (int nj = 0; nj < 8; ++nj) {
                int c = kt + nj * 8 + 2 * tig;
                if (c     > row0) sacc[nj][0] = -INFINITY;
                if (c + 1 > row0) sacc[nj][1] = -INFINITY;
                if (c     > row1) sacc[nj][2] = -INFINITY;
                if (c + 1 > row1) sacc[nj][3] = -INFINITY;
            }
        }

        // online softmax1 (fast ex2)
        float mx0 = -INFINITY, mx1 = -INFINITY;
#pragma unroll
        for (int nj = 0; nj < 8; ++nj) {
            mx0 = fmaxf(mx0, fmaxf(sacc[nj][0], sacc[nj][1]));
            mx1 = fmaxf(mx1, fmaxf(sacc[nj][2], sacc[nj][3]));
        }
        mx0 = fmaxf(mx0, __shfl_xor_sync(0xffffffffu, mx0, 1));
        mx0 = fmaxf(mx0, __shfl_xor_sync(0xffffffffu, mx0, 2));
        mx1 = fmaxf(mx1, __shfl_xor_sync(0xffffffffu, mx1, 1));
        mx1 = fmaxf(mx1, __shfl_xor_sync(0xffffffffu, mx1, 2));

        float m0n = fmaxf(m0, mx0), m1n = fmaxf(m1, mx1);
        float c0 = fexpf(m0 - m0n),  c1 = fexpf(m1 - m1n);
        m0 = m0n; m1 = m1n;

        // P in registers: C-fragment(keys) == A-fragment(k) layout.
        uint32_t pf[4][4];
        float ls0 = 0.f, ls1 = 0.f;
#pragma unroll
        for (int nj = 0; nj < 8; ++nj) {
            float p0 = fexpf(sacc[nj][0] - m0n);
            float p1 = fexpf(sacc[nj][1] - m0n);
            float p2 = fexpf(sacc[nj][2] - m1n);
            float p3 = fexpf(sacc[nj][3] - m1n);
            ls0 += p0 + p1; ls1 += p2 + p3;
            int kk = nj >> 1, hh = (nj & 1) * 2;
            __half2 lo = __floats2half2_rn(p0, p1);
            __half2 hi = __floats2half2_rn(p2, p3);
            pf[kk][hh + 0] = *(uint32_t*)&lo;
            pf[kk][hh + 1] = *(uint32_t*)&hi;
        }
        ls0 += __shfl_xor_sync(0xffffffffu, ls0, 1);
        ls0 += __shfl_xor_sync(0xffffffffu, ls0, 2);
        ls1 += __shfl_xor_sync(0xffffffffu, ls1, 1);
        ls1 += __shfl_xor_sync(0xffffffffu, ls1, 2);
        l0 = l0 * c0 + ls0;
        l1 = l1 * c1 + ls1;

#pragma unroll
        for (int nj = 0; nj < 8; ++nj) {
            o[nj][0] *= c0; o[nj][1] *= c0;
            o[nj][2] *= c1; o[nj][3] *= c1;
        }

        // O += P @ V (V row-major [key][dim]; B fragments via ldmatrix.trans)
#pragma unroll
        for (int kk = 0; kk < 4; ++kk) {
            int k = kk * 16;
#pragma unroll
            for (int g = 0; g < 4; ++g) {
                uint32_t bf[4];
                int row = k + q01 * 8 + l8;          // key index
                int col = g * 16 + q23 * 8;          // dim index
                ldsm_x4_t(bf, vst + (uint32_t)(row * AT_VS + col) * 2);
                mma_f16(o[g * 2 + 0], pf[kk], bf[0], bf[1]);
                mma_f16(o[g * 2 + 1], pf[kk], bf[2], bf[3]);
            }
        }
    }

    // epilogue: softmax1 denominator; write fp16 (B,S,D)
    float inv0 = 1.f / (1.f + l0);
    float inv1 = 1.f / (1.f + l1);
    int row0 = q0 + r0;
#pragma unroll
    for (int nj = 0; nj < 8; ++nj) {
        int c = h * HEADDIM + nj * 8 + 2 * tig;
        *(__half2*)&out[((size_t)b * SEQ + row0)     * DMODEL + c] =
            __floats2half2_rn(o[nj][0] * inv0, o[nj][1] * inv0);
        *(__half2*)&out[((size_t)b * SEQ + row0 + 8) * DMODEL + c] =
            __floats2half2_rn(o[nj][2] * inv1, o[nj][3] * inv1);
    }
}

// ---------------------------------------------------------------------------
// Fused residual add + LayerNorm; optional fp16 copy of the output.
// ---------------------------------------------------------------------------
template<int WRITEH>
__global__ __launch_bounds__(256)
void add_ln_kernel(const float* __restrict__ x, const float* __restrict__ y,
                   const float* __restrict__ g, const float* __restrict__ beta,
                   float* __restrict__ out, __half* __restrict__ outh)
{
    __shared__ float red_s[8];
    __shared__ float red_ss[8];
    __shared__ float s_mu, s_rstd;

    const int row = blockIdx.x;
    const int tid = threadIdx.x;
    const size_t base = (size_t)row * DMODEL;

    float4 xv = ((const float4*)(x + base))[tid];
    float4 yv = ((const float4*)(y + base))[tid];
    float v0 = xv.x + yv.x, v1 = xv.y + yv.y, v2 = xv.z + yv.z, v3 = xv.w + yv.w;

    float sum = v0 + v1 + v2 + v3;
    float ssq = v0 * v0 + v1 * v1 + v2 * v2 + v3 * v3;
#pragma unroll
    for (int off = 16; off >= 1; off >>= 1) {
        sum += __shfl_down_sync(0xffffffffu, sum, off);
        ssq += __shfl_down_sync(0xffffffffu, ssq, off);
    }
    const int warp = tid >> 5;
    if ((tid & 31) == 0) { red_s[warp] = sum; red_ss[warp] = ssq; }
    __syncthreads();
    if (tid == 0) {
        float ts = 0.f, tss = 0.f;
#pragma unroll
        for (int w = 0; w < 8; ++w) { ts += red_s[w]; tss += red_ss[w]; }
        float mu  = ts / (float)DMODEL;
        float var = tss / (float)DMODEL - mu * mu;
        s_mu = mu;
        s_rstd = rsqrtf(var + LN_EPS);
    }
    __syncthreads();
    const float mu = s_mu, rstd = s_rstd;

    float4 gv = ((const float4*)g)[tid];
    float4 bv = ((const float4*)beta)[tid];
    float4 o;
    o.x = (v0 - mu) * rstd * gv.x + bv.x;
    o.y = (v1 - mu) * rstd * gv.y + bv.y;
    o.z = (v2 - mu) * rstd * gv.z + bv.z;
    o.w = (v3 - mu) * rstd * gv.w + bv.w;
    ((float4*)(out + base))[tid] = o;
    if (WRITEH) {
        __half2 h0 = __floats2half2_rn(o.x, o.y);
        __half2 h1 = __floats2half2_rn(o.z, o.w);
        ((__half2*)(outh + base))[2 * tid]     = h0;
        ((__half2*)(outh + base))[2 * tid + 1] = h1;
    }
}

// ---------------------------------------------------------------------------
// Launcher
// ---------------------------------------------------------------------------
extern "C" void kernel_launch(void* const* d_in, const int* in_sizes, int n_in,
                              void* d_out, int out_size)
{
    (void)in_sizes; (void)n_in; (void)out_size;
    const float* x          = (const float*)d_in[0];
    const int*   positions  = (const int*)  d_in[1];
    const float* Wq         = (const float*)d_in[2];
    const float* bq         = (const float*)d_in[3];
    const float* Wk         = (const float*)d_in[4];
    const float* bk         = (const float*)d_in[5];
    const float* Wv         = (const float*)d_in[6];
    const float* bv         = (const float*)d_in[7];
    const float* Wo         = (const float*)d_in[8];
    const float* bo         = (const float*)d_in[9];
    const float* phase_bias = (const float*)d_in[10];
    const float* freqs      = (const float*)d_in[11];
    const float* W1         = (const float*)d_in[12];
    const float* b1         = (const float*)d_in[13];
    const float* W2         = (const float*)d_in[14];
    const float* b2         = (const float*)d_in[15];
    const float* g1         = (const float*)d_in[16];
    const float* beta1      = (const float*)d_in[17];
    const float* g2         = (const float*)d_in[18];
    const float* beta2      = (const float*)d_in[19];
    float* outp             = (float*)d_out;

    float  *bufA, *bufB, *bufX1, *bqkv;
    __half *xh, *Vh, *QPh, *KPh, *AttnH, *X1h, *FFh;
    __half *Wcat, *Woh, *W1h, *W2h;
    cudaGetSymbolAddress((void**)&bufA,  g_bufA);
    cudaGetSymbolAddress((void**)&bufB,  g_bufB);
    cudaGetSymbolAddress((void**)&bufX1, g_bufX1);
    cudaGetSymbolAddress((void**)&bqkv,  g_bqkv);
    cudaGetSymbolAddress((void**)&xh,    g_xh);
    cudaGetSymbolAddress((void**)&Vh,    g_Vh);
    cudaGetSymbolAddress((void**)&QPh,   g_QPh);
    cudaGetSymbolAddress((void**)&KPh,   g_KPh);
    cudaGetSymbolAddress((void**)&AttnH, g_AttnH);
    cudaGetSymbolAddress((void**)&X1h,   g_X1h);
    cudaGetSymbolAddress((void**)&FFh,   g_FFh);
    cudaGetSymbolAddress((void**)&Wcat,  g_Wcat);
    cudaGetSymbolAddress((void**)&Woh,   g_Woh);
    cudaGetSymbolAddress((void**)&W1h,   g_W1h);
    cudaGetSymbolAddress((void**)&W2h,   g_W2h);

    cudaFuncSetAttribute(attn_h_kernel, cudaFuncAttributeMaxDynamicSharedMemorySize,
                         AT_SMEM_BYTES);
    cudaFuncSetAttribute(hgemm_kernel<0,0,0>, cudaFuncAttributeMaxDynamicSharedMemorySize,
                         HG_SMEM_BYTES);
    cudaFuncSetAttribute(hgemm_kernel<0,1,0>, cudaFuncAttributeMaxDynamicSharedMemorySize,
                         HG_SMEM_BYTES);
    cudaFuncSetAttribute(hgemm_kernel<1,1,0>, cudaFuncAttributeMaxDynamicSharedMemorySize,
                         HG_SMEM_BYTES);
    cudaFuncSetAttribute(hgemm_kernel<0,1,1>, cudaFuncAttributeMaxDynamicSharedMemorySize,
                         HG_SMEM_BYTES);

    // 0: ALL conversions (weights + bias + x) in one launch
    {
        dim3 grid(DFF * DMODEL / 8 / 256, 8);    // 2048 x 8
        f2h_weights_kernel<<<grid, 256>>>(Wq, Wk, Wv, Wo, W1, W2, bq, bk, bv, x,
                                          Wcat, Woh, W1h, W2h, bqkv, xh);
    }

    // 1: fused QKV projection + PoPE epilogue (q->QPh, k->KPh, v->Vh)
    {
        dim3 grid(QKVN / 128, BS / 128);
        hgemm_kernel<0,1,1><<<grid, 256, HG_SMEM_BYTES>>>(
            xh, Wcat, bqkv, Vh, BS, QKVN, DMODEL,
            positions, freqs, phase_bias, QPh, KPh);
    }

    // 2: attention -> fp16
    {
        dim3 grid(SEQ / 128, NHEADS, BATCH);
        attn_h_kernel<<<grid, 256, AT_SMEM_BYTES>>>(QPh, KPh, Vh, AttnH);
    }

    // 3: output projection -> fp32
    {
        dim3 grid(DMODEL / 128, BS / 128);
        hgemm_kernel<0,0,0><<<grid, 256, HG_SMEM_BYTES>>>(
            AttnH, Woh, bo, bufA, BS, DMODEL, DMODEL,
            nullptr, nullptr, nullptr, nullptr, nullptr);
    }

    // 4: residual + LN1 -> fp32 + fp16
    add_ln_kernel<1><<<BS, 256>>>(x, bufA, g1, beta1, bufX1, X1h);

    // 5: FFN up + ReLU -> fp16
    {
        dim3 grid(DFF / 128, BS / 128);
        hgemm_kernel<1,1,0><<<grid, 256, HG_SMEM_BYTES>>>(
            X1h, W1h, b1, FFh, BS, DFF, DMODEL,
            nullptr, nullptr, nullptr, nullptr, nullptr);
    }

    // 6: FFN down -> fp32
    {
        dim3 grid(DMODEL / 128, BS / 128);
        hgemm_kernel<0,0,0><<<grid, 256, HG_SMEM_BYTES>>>(
            FFh, W2h, b2, bufB, BS, DMODEL, DFF,
            nullptr, nullptr, nullptr, nullptr, nullptr);
    }

    // 7: residual + LN2 -> output
    add_ln_kernel<0><<<BS, 256>>>(bufX1, bufB, g2, beta2, outp, nullptr);
}

// round 17
// speedup vs baseline: 1.2276x; 1.0528x over previous
#include <cuda_runtime.h>
#include <cuda_fp16.h>
#include <math.h>
#include <stdint.h>

// ---------------------------------------------------------------------------
// Problem constants
// ---------------------------------------------------------------------------
#define BATCH   2
#define SEQ     2048
#define DMODEL  1024
#define NHEADS  16
#define HEADDIM 64
#define DFF     4096
#define BS      (BATCH * SEQ)          // 4096 rows
#define LN_EPS  1e-5f
#define ATTN_SCALE 0.08838834764831845f   // 1/sqrt(128)
#define QKVN    (3 * DMODEL)           // fused QKV width

// ---------------------------------------------------------------------------
// Scratch buffers
// ---------------------------------------------------------------------------
__device__ float  g_bufA   [BS * DMODEL];            // Wo out (fp32)
__device__ float  g_bufB   [BS * DMODEL];            // FFN2 out (fp32)
__device__ float  g_bufX1  [BS * DMODEL];            // LN1 out fp32
__device__ __half g_xh     [BS * DMODEL];            // x in fp16
__device__ __half g_Vh     [BS * DMODEL];            // V fp16 (compact)
__device__ __half g_QPh    [BATCH * NHEADS * SEQ * 2 * HEADDIM];
__device__ __half g_KPh    [BATCH * NHEADS * SEQ * 2 * HEADDIM];
__device__ __half g_AttnH  [BS * DMODEL];            // attention out fp16
__device__ __half g_X1h    [BS * DMODEL];            // LN1 out fp16
__device__ __half g_FFh    [BS * DFF];               // FFN hidden fp16

// fp16 weights in NATIVE [K][N] layout (no transpose needed: ldmatrix.trans)
__device__ __half g_Wcat[DMODEL * QKVN];             // cols: Wq | Wk | Wv
__device__ float  g_bqkv[QKVN];
__device__ __half g_Woh[DMODEL * DMODEL];
__device__ __half g_W1h[DMODEL * DFF];
__device__ __half g_W2h[DFF * DMODEL];

// ---------------------------------------------------------------------------
// Helpers
// ---------------------------------------------------------------------------
__device__ __forceinline__ uint32_t smem_u32(const void* p) {
    uint32_t a;
    asm("{ .reg .u64 t; cvta.to.shared.u64 t, %1; cvt.u32.u64 %0, t; }"
        : "=r"(a) : "l"(p));
    return a;
}

__device__ __forceinline__ void cp_async16(uint32_t saddr, const void* gptr) {
    asm volatile("cp.async.cg.shared.global [%0], [%1], 16;"
                 :: "r"(saddr), "l"(gptr) : "memory");
}

// fp16 mma m16n8k16, fp32 accumulate
__device__ __forceinline__ void mma_f16(float (&d)[4],
                                        const uint32_t (&a)[4],
                                        uint32_t b0, uint32_t b1)
{
    asm volatile(
        "mma.sync.aligned.m16n8k16.row.col.f32.f16.f16.f32 "
        "{%0,%1,%2,%3}, {%4,%5,%6,%7}, {%8,%9}, {%0,%1,%2,%3};"
        : "+f"(d[0]), "+f"(d[1]), "+f"(d[2]), "+f"(d[3])
        : "r"(a[0]), "r"(a[1]), "r"(a[2]), "r"(a[3]), "r"(b0), "r"(b1));
}

__device__ __forceinline__ void ldsm_x4(uint32_t (&r)[4], uint32_t saddr) {
    asm volatile("ldmatrix.sync.aligned.m8n8.x4.shared.b16 {%0,%1,%2,%3}, [%4];"
                 : "=r"(r[0]), "=r"(r[1]), "=r"(r[2]), "=r"(r[3]) : "r"(saddr));
}

__device__ __forceinline__ void ldsm_x4_t(uint32_t (&r)[4], uint32_t saddr) {
    asm volatile("ldmatrix.sync.aligned.m8n8.x4.trans.shared.b16 {%0,%1,%2,%3}, [%4];"
                 : "=r"(r[0]), "=r"(r[1]), "=r"(r[2]), "=r"(r[3]) : "r"(saddr));
}

// Fast exp via MUFU.EX2 (args are <= 0 here; ex2.approx(-inf) = 0)
__device__ __forceinline__ float fexpf(float x) {
    float y = x * 1.4426950408889634f;
    float r;
    asm("ex2.approx.f32 %0, %1;" : "=f"(r) : "f"(y));
    return r;
}

__device__ __forceinline__ float fex2(float x) {
    float r; asm("ex2.approx.f32 %0, %1;" : "=f"(r) : "f"(x)); return r;
}
__device__ __forceinline__ float flg2(float x) {
    float r; asm("lg2.approx.f32 %0, %1;" : "=f"(r) : "f"(x)); return r;
}
__device__ __forceinline__ float fsin(float x) {
    float r; asm("sin.approx.f32 %0, %1;" : "=f"(r) : "f"(x)); return r;
}
__device__ __forceinline__ float fcos(float x) {
    float r; asm("cos.approx.f32 %0, %1;" : "=f"(r) : "f"(x)); return r;
}

// Fast softplus: max(x,0) + ln2 * lg2(1 + 2^(-|x|*log2e))
__device__ __forceinline__ float fsoftplus(float x) {
    float t = fex2(-fabsf(x) * 1.4426950408889634f);
    return fmaxf(x, 0.f) + 0.6931471805599453f * flg2(1.f + t);
}

// Fast sincos with Cody-Waite range reduction (|ph| < ~2100, n <= ~340).
__device__ __forceinline__ void fsincos(float ph, float* s, float* c) {
    float n = rintf(ph * 0.15915494309189535f);       // ph / 2pi
    float r = fmaf(n, -6.28125f, ph);                 // 2pi hi (exact products)
    r = fmaf(n, -1.9353071795864769e-3f, r);          // 2pi lo
    *s = fsin(r);
    *c = fcos(r);
}

// ---------------------------------------------------------------------------
// ALL conversions in ONE launch. grid.y selects item:
//   0..2: Wq/Wk/Wv -> Wcat (column-concat) 3: Wo, 4: W1, 5: W2, 6: bias, 7: x
// ---------------------------------------------------------------------------
__global__ __launch_bounds__(256)
void f2h_weights_kernel(const float* __restrict__ Wq, const float* __restrict__ Wk,
                        const float* __restrict__ Wv, const float* __restrict__ Wo,
                        const float* __restrict__ W1, const float* __restrict__ W2,
                        const float* __restrict__ bq, const float* __restrict__ bk,
                        const float* __restrict__ bv, const float* __restrict__ x,
                        __half* __restrict__ Wcat, __half* __restrict__ Woh,
                        __half* __restrict__ W1h, __half* __restrict__ W2h,
                        float* __restrict__ bqkv, __half* __restrict__ xh)
{
    const int id  = blockIdx.y;
    const int idx = blockIdx.x * 256 + threadIdx.x;   // chunk of 8 elems

    if (id == 6) {
        if (idx >= QKVN) return;
        float v = (idx < DMODEL) ? bq[idx]
                : (idx < 2 * DMODEL) ? bk[idx - DMODEL] : bv[idx - 2 * DMODEL];
        bqkv[idx] = v;
        return;
    }

    const float* src;
    __half* dst;
    int nchunks;
    if (id < 3)      { src = (id == 0) ? Wq : (id == 1) ? Wk : Wv;
                       dst = Wcat; nchunks = DMODEL * DMODEL / 8; }
    else if (id == 3){ src = Wo; dst = Woh; nchunks = DMODEL * DMODEL / 8; }
    else if (id == 4){ src = W1; dst = W1h; nchunks = DMODEL * DFF / 8; }
    else if (id == 5){ src = W2; dst = W2h; nchunks = DFF * DMODEL / 8; }
    else             { src = x;  dst = xh;  nchunks = BS * DMODEL / 8; }
    if (idx >= nchunks) return;

    float4 a = *(const float4*)(src + idx * 8);
    float4 b = *(const float4*)(src + idx * 8 + 4);
    __half2 h[4];
    h[0] = __floats2half2_rn(a.x, a.y);
    h[1] = __floats2half2_rn(a.z, a.w);
    h[2] = __floats2half2_rn(b.x, b.y);
    h[3] = __floats2half2_rn(b.z, b.w);

    if (id < 3) {
        int r = idx >> 7;            // 128 chunks per 1024-wide row
        int c = idx & 127;
        *(uint4*)(dst + (size_t)r * QKVN + id * DMODEL + c * 8) = *(uint4*)h;
    } else {
        *(uint4*)(dst + (size_t)idx * 8) = *(uint4*)h;
    }
}

// ---------------------------------------------------------------------------
// fp16 mma GEMM: C(MxN) = A(MxK) @ W(KxN) + bias. W in NATIVE [K][N] layout;
// B fragments via ldmatrix.trans. 128x128x64 tiles (64-K iterations halve the
// barrier count vs 32-K), 8 warps, 3-stage cp.async pipeline, 2 CTAs/SM.
// POPE=1: fused PoPE epilogue (q->qp, k->kp, v->Cv compact).
// ---------------------------------------------------------------------------
#define HG_AS     72          // A tile stride (halves), 128 rows x 64 k
#define HG_BS     136         // B tile stride (halves), 64 k-rows x 128 cols
#define HG_STAGES 3
#define HG_A_HALVES (128 * HG_AS)                         // 9216
#define HG_B_HALVES (64 * HG_BS)                          // 8704
#define HG_STAGE_HALVES (HG_A_HALVES + HG_B_HALVES)       // 17920
#define HG_SMEM_BYTES (HG_STAGES * HG_STAGE_HALVES * 2)   // 107520 B

template<int RELU, int HALFOUT, int POPE>
__global__ __launch_bounds__(256, 2)
void hgemm_kernel(const __half* __restrict__ A, const __half* __restrict__ W,
                  const float* __restrict__ bias, void* __restrict__ Cv,
                  int M, int N, int K,
                  const int* __restrict__ positions,
                  const float* __restrict__ freqs,
                  const float* __restrict__ phase_bias,
                  __half* __restrict__ qp, __half* __restrict__ kp)
{
    extern __shared__ __half hsm[];

    const int tid  = threadIdx.x;
    const int lane = tid & 31, wid = tid >> 5;
    const int wm = wid >> 1, wn = wid & 1;
    const int grp = lane >> 2, tig = lane & 3;
    const int m0 = blockIdx.y * 128, n0 = blockIdx.x * 128;

    const uint32_t smbase = smem_u32(hsm);

    const int l8  = lane & 7;
    const int q01 = (lane >> 3) & 1;
    const int q23 = lane >> 4;

    float acc[2][8][4];
#pragma unroll
    for (int mi = 0; mi < 2; ++mi)
#pragma unroll
        for (int nj = 0; nj < 8; ++nj)
#pragma unroll
            for (int r = 0; r < 4; ++r) acc[mi][nj][r] = 0.f;

    auto load_tiles = [&](int stage, int k0) {
        uint32_t ab = smbase + stage * HG_STAGE_HALVES * 2;
        uint32_t bb = ab + HG_A_HALVES * 2;
        // A: 128 rows x 64 halves = 1024 chunks (4/thread)
#pragma unroll
        for (int i = 0; i < 4; ++i) {
            int idx = tid + i * 256;
            int r = idx >> 3, c = idx & 7;
            cp_async16(ab + (uint32_t)(r * HG_AS + c * 8) * 2,
                       A + (size_t)(m0 + r) * K + k0 + c * 8);
        }
        // B: 64 k-rows x 128 cols = 1024 chunks (4/thread), native [K][N]
#pragma unroll
        for (int i = 0; i < 4; ++i) {
            int idx = tid + i * 256;
            int r = idx >> 4, c = idx & 15;
            cp_async16(bb + (uint32_t)(r * HG_BS + c * 8) * 2,
                       W + (size_t)(k0 + r) * N + n0 + c * 8);
        }
    };

    const int nIt = K / 64;
    load_tiles(0, 0);
    asm volatile("cp.async.commit_group;" ::: "memory");
    load_tiles(1, 64);
    asm volatile("cp.async.commit_group;" ::: "memory");

    int st = 0, lst = 2;
    for (int it = 0; it < nIt; ++it) {
        asm volatile("cp.async.wait_group 1;" ::: "memory");
        __syncthreads();
        if (it + 2 < nIt) {
            load_tiles(lst, (it + 2) * 64);
            asm volatile("cp.async.commit_group;" ::: "memory");
            lst = (lst == 2) ? 0 : lst + 1;
        }

        const uint32_t abase = smbase + st * HG_STAGE_HALVES * 2;
        const uint32_t bbase = abase + HG_A_HALVES * 2;
        st = (st == 2) ? 0 : st + 1;

#pragma unroll
        for (int kk = 0; kk < 4; ++kk) {
            const int k = kk * 16;
            uint32_t af[2][4];
#pragma unroll
            for (int mi = 0; mi < 2; ++mi) {
                int row = wm * 32 + mi * 16 + q01 * 8 + l8;
                int col = k + q23 * 8;
                ldsm_x4(af[mi], abase + (uint32_t)(row * HG_AS + col) * 2);
            }
#pragma unroll
            for (int g = 0; g < 4; ++g) {
                uint32_t bf[4];
                int row = k + q01 * 8 + l8;                 // k index
                int col = wn * 64 + g * 16 + q23 * 8;       // n index
                ldsm_x4_t(bf, bbase + (uint32_t)(row * HG_BS + col) * 2);
#pragma unroll
                for (int h2 = 0; h2 < 2; ++h2)
#pragma unroll
                    for (int mi = 0; mi < 2; ++mi)
                        mma_f16(acc[mi][g * 2 + h2], af[mi], bf[h2 * 2], bf[h2 * 2 + 1]);
            }
        }
    }

#pragma unroll
    for (int mi = 0; mi < 2; ++mi) {
        int r = m0 + wm * 32 + mi * 16 + grp;
#pragma unroll
        for (int nj = 0; nj < 8; ++nj) {
            int c = n0 + wn * 64 + nj * 8 + tig * 2;
            float bb0 = bias[c], bb1 = bias[c + 1];
            float v0 = acc[mi][nj][0] + bb0;
            float v1 = acc[mi][nj][1] + bb1;
            float v2 = acc[mi][nj][2] + bb0;
            float v3 = acc[mi][nj][3] + bb1;
            if (POPE) {
                if (c < 2 * DMODEL) {
                    // q or k column: PoPE transform (branch is warp-uniform)
                    int which = c >> 10;                 // 0=q, 1=k
                    int d  = c & 63;
                    int hh = (c >> 6) & 15;
                    float fr0 = freqs[d], fr1 = freqs[d + 1];
                    float pb0 = phase_bias[hh * HEADDIM + d];
                    float pb1 = phase_bias[hh * HEADDIM + d + 1];
                    float scale = which ? 1.f : ATTN_SCALE;
                    __half* dst = which ? kp : qp;
#pragma unroll
                    for (int rr = 0; rr < 2; ++rr) {
                        int row = r + rr * 8;
                        float va = rr ? v2 : v0;
                        float vb = rr ? v3 : v1;
                        int bidx = row >> 11, s = row & (SEQ - 1);
                        float pos = (float)positions[s];
                        float sn0, cs0, sn1, cs1;
                        fsincos(fmaf(pos, fr0, pb0), &sn0, &cs0);
                        fsincos(fmaf(pos, fr1, pb1), &sn1, &cs1);
                        float ma = fsoftplus(va) * scale;
                        float mb = fsoftplus(vb) * scale;
                        size_t base = (((size_t)(bidx * NHEADS + hh) * SEQ) + s) * 128 + d;
                        *(__half2*)&dst[base]      = __floats2half2_rn(ma * cs0, mb * cs1);
                        *(__half2*)&dst[base + 64] = __floats2half2_rn(ma * sn0, mb * sn1);
                    }
                } else {
                    __half* V = (__half*)Cv;
                    int cc = c - 2 * DMODEL;
                    *(__half2*)&V[(size_t)r * DMODEL + cc]       = __floats2half2_rn(v0, v1);
                    *(__half2*)&V[(size_t)(r + 8) * DMODEL + cc] = __floats2half2_rn(v2, v3);
                }
            } else {
                if (RELU) {
                    v0 = fmaxf(v0, 0.f); v1 = fmaxf(v1, 0.f);
                    v2 = fmaxf(v2, 0.f); v3 = fmaxf(v3, 0.f);
                }
                if (HALFOUT) {
                    __half* C = (__half*)Cv;
                    *(__half2*)&C[(size_t)r * N + c]       = __floats2half2_rn(v0, v1);
                    *(__half2*)&C[(size_t)(r + 8) * N + c] = __floats2half2_rn(v2, v3);
                } else {
                    float* C = (float*)Cv;
                    float2 lo; lo.x = v0; lo.y = v1;
                    float2 hi; hi.x = v2; hi.y = v3;
                    *(float2*)&C[(size_t)r * N + c]       = lo;
                    *(float2*)&C[(size_t)(r + 8) * N + c] = hi;
                }
            }
        }
    }
}

// ---------------------------------------------------------------------------
// Flash attention with softmax1, fp16 mma + ldmatrix. 2 CTAs/SM.
// P kept entirely in registers (QK C-fragment == PV A-fragment layout).
// ---------------------------------------------------------------------------
#define AT_QS 136
#define AT_KS 136
#define AT_VS 72
#define AT_Q_HALVES (128 * AT_QS)
#define AT_K_STAGE  (64 * AT_KS)
#define AT_V_STAGE  (64 * AT_VS)
#define AT_SMEM_HALVES (AT_Q_HALVES + 2 * AT_K_STAGE + 2 * AT_V_STAGE)
#define AT_SMEM_BYTES  (AT_SMEM_HALVES * 2)   // 88064 B

__global__ __launch_bounds__(256, 2)
void attn_h_kernel(const __half* __restrict__ qp, const __half* __restrict__ kp,
                   const __half* __restrict__ v, __half* __restrict__ out)
{
    extern __shared__ __half hsm[];
    __half* Qs = hsm;                           // 128 x 136 (staging)

    const int b = blockIdx.z;
    const int h = blockIdx.y;
    const int qtile = gridDim.x - 1 - blockIdx.x;   // heavy tiles first
    const int q0 = qtile * 128;

    const int tid  = threadIdx.x;
    const int lane = tid & 31, wid = tid >> 5;
    const int grp = lane >> 2, tig = lane & 3;
    const int r0 = wid * 16 + grp;

    const int l8  = lane & 7;
    const int q01 = (lane >> 3) & 1;
    const int q23 = lane >> 4;

    const uint32_t smbase = smem_u32(hsm);
    const uint32_t kssm0 = smbase + AT_Q_HALVES * 2;             // K stage 0
    const uint32_t vssm0 = kssm0 + 2 * AT_K_STAGE * 2;           // V stage 0

    const __half* qbase = qp + (((size_t)(b * NHEADS + h)) * SEQ) * 128;
    const __half* kbase = kp + (((size_t)(b * NHEADS + h)) * SEQ) * 128;
    const __half* vbase = v + h * HEADDIM;                       // compact V

    auto load_kv = [&](int stage, int kt) {
        uint32_t kb = kssm0 + stage * AT_K_STAGE * 2;
#pragma unroll
        for (int i = 0; i < 4; ++i) {
            int idx = tid + i * 256;
            int r = idx >> 4, c = idx & 15;
            cp_async16(kb + (uint32_t)(r * AT_KS + c * 8) * 2,
                       kbase + (size_t)(kt + r) * 128 + c * 8);
        }
        uint32_t vb = vssm0 + stage * AT_V_STAGE * 2;
#pragma unroll
        for (int i = 0; i < 2; ++i) {
            int idx = tid + i * 256;
            int r = idx >> 3, c = idx & 7;
            cp_async16(vb + (uint32_t)(r * AT_VS + c * 8) * 2,
                       vbase + ((size_t)b * SEQ + kt + r) * DMODEL + c * 8);
        }
    };

    // Prologue: start K/V tile 0 fetch, then stage Q.
    load_kv(0, 0);
    asm volatile("cp.async.commit_group;" ::: "memory");

    for (int i = tid; i < 2048; i += 256) {
        int r = i >> 4, c = i & 15;
        *(uint4*)&Qs[r * AT_QS + c * 8] =
            *(const uint4*)&qbase[(size_t)(q0 + r) * 128 + c * 8];
    }
    __syncthreads();

    // Preload Q fragments via ldmatrix: 8 k16 chunks
    uint32_t qf[8][4];
    {
        int row = wid * 16 + q01 * 8 + l8;
#pragma unroll
        for (int kk = 0; kk < 8; ++kk) {
            int col = kk * 16 + q23 * 8;
            ldsm_x4(qf[kk], smbase + (uint32_t)(row * AT_QS + col) * 2);
        }
    }

    float m0 = -INFINITY, m1 = -INFINITY, l0 = 0.f, l1 = 0.f;
    float o[8][4];
#pragma unroll
    for (int nj = 0; nj < 8; ++nj)
#pragma unroll
        for (int r = 0; r < 4; ++r) o[nj][r] = 0.f;

    const int nT = q0 / 64 + 2;
    for (int t = 0; t < nT; ++t) {
        const int kt = t * 64;
        asm volatile("cp.async.wait_group 0;" ::: "memory");
        __syncthreads();
        if (t + 1 < nT) {
            load_kv((t + 1) & 1, (t + 1) * 64);
            asm volatile("cp.async.commit_group;" ::: "memory");
        }
        const uint32_t kst = kssm0 + (t & 1) * AT_K_STAGE * 2;
        const uint32_t vst = vssm0 + (t & 1) * AT_V_STAGE * 2;

        // scores = Q @ K^T
        float sacc[8][4];
#pragma unroll
        for (int nj = 0; nj < 8; ++nj)
#pragma unroll
            for (int r = 0; r < 4; ++r) sacc[nj][r] = 0.f;

#pragma unroll
        for (int kk = 0; kk < 8; ++kk) {
            int k = kk * 16;
#pragma unroll
            for (int g = 0; g < 4; ++g) {
                uint32_t bf[4];
                int row = g * 16 + q23 * 8 + l8;
                int col = k + q01 * 8;
                ldsm_x4(bf, kst + (uint32_t)(row * AT_KS + col) * 2);
                mma_f16(sacc[g * 2 + 0], qf[kk], bf[0], bf[1]);
                mma_f16(sacc[g * 2 + 1], qf[kk], bf[2], bf[3]);
            }
        }

        // causal mask (last two key tiles only)
        if (kt >= q0) {
            int row0 = q0 + r0, row1 = row0 + 8;
#pragma unroll
            for (int nj = 0; nj < 8; ++nj) {
                int c = kt + nj * 8 + 2 * tig;
                if (c     > row0) sacc[nj][0] = -INFINITY;
                if (c + 1 > row0) sacc[nj][1] = -INFINITY;
                if (c     > row1) sacc[nj][2] = -INFINITY;
                if (c + 1 > row1) sacc[nj][3] = -INFINITY;
            }
        }

        // online softmax1 (fast ex2)
        float mx0 = -INFINITY, mx1 = -INFINITY;
#pragma unroll
        for (int nj = 0; nj < 8; ++nj) {
            mx0 = fmaxf(mx0, fmaxf(sacc[nj][0], sacc[nj][1]));
            mx1 = fmaxf(mx1, fmaxf(sacc[nj][2], sacc[nj][3]));
        }
        mx0 = fmaxf(mx0, __shfl_xor_sync(0xffffffffu, mx0, 1));
        mx0 = fmaxf(mx0, __shfl_xor_sync(0xffffffffu, mx0, 2));
        mx1 = fmaxf(mx1, __shfl_xor_sync(0xffffffffu, mx1, 1));
        mx1 = fmaxf(mx1, __shfl_xor_sync(0xffffffffu, mx1, 2));

        float m0n = fmaxf(m0, mx0), m1n = fmaxf(m1, mx1);
        float c0 = fexpf(m0 - m0n),  c1 = fexpf(m1 - m1n);
        m0 = m0n; m1 = m1n;

        // P in registers: C-fragment(keys) == A-fragment(k) layout.
        uint32_t pf[4][4];
        float ls0 = 0.f, ls1 = 0.f;
#pragma unroll
        for (int nj = 0; nj < 8; ++nj) {
            float p0 = fexpf(sacc[nj][0] - m0n);
            float p1 = fexpf(sacc[nj][1] - m0n);
            float p2 = fexpf(sacc[nj][2] - m1n);
            float p3 = fexpf(sacc[nj][3] - m1n);
            ls0 += p0 + p1; ls1 += p2 + p3;
            int kk = nj >> 1, hh = (nj & 1) * 2;
            __half2 lo = __floats2half2_rn(p0, p1);
            __half2 hi = __floats2half2_rn(p2, p3);
            pf[kk][hh + 0] = *(uint32_t*)&lo;
            pf[kk][hh + 1] = *(uint32_t*)&hi;
        }
        ls0 += __shfl_xor_sync(0xffffffffu, ls0, 1);
        ls0 += __shfl_xor_sync(0xffffffffu, ls0, 2);
        ls1 += __shfl_xor_sync(0xffffffffu, ls1, 1);
        ls1 += __shfl_xor_sync(0xffffffffu, ls1, 2);
        l0 = l0 * c0 + ls0;
        l1 = l1 * c1 + ls1;

#pragma unroll
        for (int nj = 0; nj < 8; ++nj) {
            o[nj][0] *= c0; o[nj][1] *= c0;
            o[nj][2] *= c1; o[nj][3] *= c1;
        }

        // O += P @ V (V row-major [key][dim]; B fragments via ldmatrix.trans)
#pragma unroll
        for (int kk = 0; kk < 4; ++kk) {
            int k = kk * 16;
#pragma unroll
            for (int g = 0; g < 4; ++g) {
                uint32_t bf[4];
                int row = k + q01 * 8 + l8;          // key index
                int col = g * 16 + q23 * 8;          // dim index
                ldsm_x4_t(bf, vst + (uint32_t)(row * AT_VS + col) * 2);
                mma_f16(o[g * 2 + 0], pf[kk], bf[0], bf[1]);
                mma_f16(o[g * 2 + 1], pf[kk], bf[2], bf[3]);
            }
        }
    }

    // epilogue: softmax1 denominator; write fp16 (B,S,D)
    float inv0 = 1.f / (1.f + l0);
    float inv1 = 1.f / (1.f + l1);
    int row0 = q0 + r0;
#pragma unroll
    for (int nj = 0; nj < 8; ++nj) {
        int c = h * HEADDIM + nj * 8 + 2 * tig;
        *(__half2*)&out[((size_t)b * SEQ + row0)     * DMODEL + c] =
            __floats2half2_rn(o[nj][0] * inv0, o[nj][1] * inv0);
        *(__half2*)&out[((size_t)b * SEQ + row0 + 8) * DMODEL + c] =
            __floats2half2_rn(o[nj][2] * inv1, o[nj][3] * inv1);
    }
}

// ---------------------------------------------------------------------------
// Fused residual add + LayerNorm; optional fp16 copy of the output.
// ---------------------------------------------------------------------------
template<int WRITEH>
__global__ __launch_bounds__(256)
void add_ln_kernel(const float* __restrict__ x, const float* __restrict__ y,
                   const float* __restrict__ g, const float* __restrict__ beta,
                   float* __restrict__ out, __half* __restrict__ outh)
{
    __shared__ float red_s[8];
    __shared__ float red_ss[8];
    __shared__ float s_mu, s_rstd;

    const int row = blockIdx.x;
    const int tid = threadIdx.x;
    const size_t base = (size_t)row * DMODEL;

    float4 xv = ((const float4*)(x + base))[tid];
    float4 yv = ((const float4*)(y + base))[tid];
    float v0 = xv.x + yv.x, v1 = xv.y + yv.y, v2 = xv.z + yv.z, v3 = xv.w + yv.w;

    float sum = v0 + v1 + v2 + v3;
    float ssq = v0 * v0 + v1 * v1 + v2 * v2 + v3 * v3;
#pragma unroll
    for (int off = 16; off >= 1; off >>= 1) {
        sum += __shfl_down_sync(0xffffffffu, sum, off);
        ssq += __shfl_down_sync(0xffffffffu, ssq, off);
    }
    const int warp = tid >> 5;
    if ((tid & 31) == 0) { red_s[warp] = sum; red_ss[warp] = ssq; }
    __syncthreads();
    if (tid == 0) {
        float ts = 0.f, tss = 0.f;
#pragma unroll
        for (int w = 0; w < 8; ++w) { ts += red_s[w]; tss += red_ss[w]; }
        float mu  = ts / (float)DMODEL;
        float var = tss / (float)DMODEL - mu * mu;
        s_mu = mu;
        s_rstd = rsqrtf(var + LN_EPS);
    }
    __syncthreads();
    const float mu = s_mu, rstd = s_rstd;

    float4 gv = ((const float4*)g)[tid];
    float4 bv = ((const float4*)beta)[tid];
    float4 o;
    o.x = (v0 - mu) * rstd * gv.x + bv.x;
    o.y = (v1 - mu) * rstd * gv.y + bv.y;
    o.z = (v2 - mu) * rstd * gv.z + bv.z;
    o.w = (v3 - mu) * rstd * gv.w + bv.w;
    ((float4*)(out + base))[tid] = o;
    if (WRITEH) {
        __half2 h0 = __floats2half2_rn(o.x, o.y);
        __half2 h1 = __floats2half2_rn(o.z, o.w);
        ((__half2*)(outh + base))[2 * tid]     = h0;
        ((__half2*)(outh + base))[2 * tid + 1] = h1;
    }
}

// ---------------------------------------------------------------------------
// Launcher
// ---------------------------------------------------------------------------
extern "C" void kernel_launch(void* const* d_in, const int* in_sizes, int n_in,
                              void* d_out, int out_size)
{
    (void)in_sizes; (void)n_in; (void)out_size;
    const float* x          = (const float*)d_in[0];
    const int*   positions  = (const int*)  d_in[1];
    const float* Wq         = (const float*)d_in[2];
    const float* bq         = (const float*)d_in[3];
    const float* Wk         = (const float*)d_in[4];
    const float* bk         = (const float*)d_in[5];
    const float* Wv         = (const float*)d_in[6];
    const float* bv         = (const float*)d_in[7];
    const float* Wo         = (const float*)d_in[8];
    const float* bo         = (const float*)d_in[9];
    const float* phase_bias = (const float*)d_in[10];
    const float* freqs      = (const float*)d_in[11];
    const float* W1         = (const float*)d_in[12];
    const float* b1         = (const float*)d_in[13];
    const float* W2         = (const float*)d_in[14];
    const float* b2         = (const float*)d_in[15];
    const float* g1         = (const float*)d_in[16];
    const float* beta1      = (const float*)d_in[17];
    const float* g2         = (const float*)d_in[18];
    const float* beta2      = (const float*)d_in[19];
    float* outp             = (float*)d_out;

    float  *bufA, *bufB, *bufX1, *bqkv;
    __half *xh, *Vh, *QPh, *KPh, *AttnH, *X1h, *FFh;
    __half *Wcat, *Woh, *W1h, *W2h;
    cudaGetSymbolAddress((void**)&bufA,  g_bufA);
    cudaGetSymbolAddress((void**)&bufB,  g_bufB);
    cudaGetSymbolAddress((void**)&bufX1, g_bufX1);
    cudaGetSymbolAddress((void**)&bqkv,  g_bqkv);
    cudaGetSymbolAddress((void**)&xh,    g_xh);
    cudaGetSymbolAddress((void**)&Vh,    g_Vh);
    cudaGetSymbolAddress((void**)&QPh,   g_QPh);
    cudaGetSymbolAddress((void**)&KPh,   g_KPh);
    cudaGetSymbolAddress((void**)&AttnH, g_AttnH);
    cudaGetSymbolAddress((void**)&X1h,   g_X1h);
    cudaGetSymbolAddress((void**)&FFh,   g_FFh);
    cudaGetSymbolAddress((void**)&Wcat,  g_Wcat);
    cudaGetSymbolAddress((void**)&Woh,   g_Woh);
    cudaGetSymbolAddress((void**)&W1h,   g_W1h);
    cudaGetSymbolAddress((void**)&W2h,   g_W2h);

    cudaFuncSetAttribute(attn_h_kernel, cudaFuncAttributeMaxDynamicSharedMemorySize,
                         AT_SMEM_BYTES);
    cudaFuncSetAttribute(hgemm_kernel<0,0,0>, cudaFuncAttributeMaxDynamicSharedMemorySize,
                         HG_SMEM_BYTES);
    cudaFuncSetAttribute(hgemm_kernel<0,1,0>, cudaFuncAttributeMaxDynamicSharedMemorySize,
                         HG_SMEM_BYTES);
    cudaFuncSetAttribute(hgemm_kernel<1,1,0>, cudaFuncAttributeMaxDynamicSharedMemorySize,
                         HG_SMEM_BYTES);
    cudaFuncSetAttribute(hgemm_kernel<0,1,1>, cudaFuncAttributeMaxDynamicSharedMemorySize,
                         HG_SMEM_BYTES);

    // 0: ALL conversions (weights + bias + x) in one launch
    {
        dim3 grid(DFF * DMODEL / 8 / 256, 8);    // 2048 x 8
        f2h_weights_kernel<<<grid, 256>>>(Wq, Wk, Wv, Wo, W1, W2, bq, bk, bv, x,
                                          Wcat, Woh, W1h, W2h, bqkv, xh);
    }

    // 1: fused QKV projection + PoPE epilogue (q->QPh, k->KPh, v->Vh)
    {
        dim3 grid(QKVN / 128, BS / 128);
        hgemm_kernel<0,1,1><<<grid, 256, HG_SMEM_BYTES>>>(
            xh, Wcat, bqkv, Vh, BS, QKVN, DMODEL,
            positions, freqs, phase_bias, QPh, KPh);
    }

    // 2: attention -> fp16
    {
        dim3 grid(SEQ / 128, NHEADS, BATCH);
        attn_h_kernel<<<grid, 256, AT_SMEM_BYTES>>>(QPh, KPh, Vh, AttnH);
    }

    // 3: output projection -> fp32
    {
        dim3 grid(DMODEL / 128, BS / 128);
        hgemm_kernel<0,0,0><<<grid, 256, HG_SMEM_BYTES>>>(
            AttnH, Woh, bo, bufA, BS, DMODEL, DMODEL,
            nullptr, nullptr, nullptr, nullptr, nullptr);
    }

    // 4: residual + LN1 -> fp32 + fp16
    add_ln_kernel<1><<<BS, 256>>>(x, bufA, g1, beta1, bufX1, X1h);

    // 5: FFN up + ReLU -> fp16
    {
        dim3 grid(DFF / 128, BS / 128);
        hgemm_kernel<1,1,0><<<grid, 256, HG_SMEM_BYTES>>>(
            X1h, W1h, b1, FFh, BS, DFF, DMODEL,
            nullptr, nullptr, nullptr, nullptr, nullptr);
    }

    // 6: FFN down -> fp32
    {
        dim3 grid(DMODEL / 128, BS / 128);
        hgemm_kernel<0,0,0><<<grid, 256, HG_SMEM_BYTES>>>(
            FFh, W2h, b2, bufB, BS, DMODEL, DFF,
            nullptr, nullptr, nullptr, nullptr, nullptr);
    }

    // 7: residual + LN2 -> output
    add_ln_kernel<0><<<BS, 256>>>(bufX1, bufB, g2, beta2, outp, nullptr);
}